// round 10
// baseline (speedup 1.0000x reference)
#include <cuda_runtime.h>
#include <cuda_bf16.h>
#include <cuda_fp16.h>
#include <math.h>
#include <stdint.h>

#define NN 2048          // nodes
#define NH 8             // heads
#define ALPHA 0.2f
#define NNZ_CAP (2048*128)
#define HID_MAX 512
#define DEG_CAP 1024

// ---------------- scratch (static device allocations) ----------------
__device__ int   g_deg[NN];
__device__ int   g_rowptr[NN + 1];
__device__ int   g_colidx[NNZ_CAP];
__device__ __half g_h[NH * NN * HID_MAX];       // per-head projected features (fp16)
__device__ float g_s1[NH * NN];
__device__ float g_s2[NH * NN];
__device__ __half g_hoh[NN * HID_MAX];          // output-head features (fp16, gather operand)
__device__ float g_o1[NN];
__device__ float g_o2[NN];
__device__ float g_part[8 * NN * 384];          // split-K partials for Wo gemm
// bf16 hi/lo operand buffers (A: activations; B: ALL weights, pre-split once)
__device__ __nv_bfloat16 g_a1[NN * 4096];
__device__ __nv_bfloat16 g_a2[NN * 4096];
__device__ __nv_bfloat16 g_b1[1 << 23];
__device__ __nv_bfloat16 g_b2[1 << 23];

// ---------------- bf16 hi/lo elementwise split ----------------
__device__ __forceinline__ void split4(float4 v, ushort4& uh, ushort4& ul) {
    __nv_bfloat16 h0 = __float2bfloat16_rn(v.x), h1 = __float2bfloat16_rn(v.y);
    __nv_bfloat16 h2 = __float2bfloat16_rn(v.z), h3 = __float2bfloat16_rn(v.w);
    __nv_bfloat16 l0 = __float2bfloat16_rn(v.x - __bfloat162float(h0));
    __nv_bfloat16 l1 = __float2bfloat16_rn(v.y - __bfloat162float(h1));
    __nv_bfloat16 l2 = __float2bfloat16_rn(v.z - __bfloat162float(h2));
    __nv_bfloat16 l3 = __float2bfloat16_rn(v.w - __bfloat162float(h3));
    uh.x = *(unsigned short*)&h0; uh.y = *(unsigned short*)&h1;
    uh.z = *(unsigned short*)&h2; uh.w = *(unsigned short*)&h3;
    ul.x = *(unsigned short*)&l0; ul.y = *(unsigned short*)&l1;
    ul.z = *(unsigned short*)&l2; ul.w = *(unsigned short*)&l3;
}

__global__ void split_bf(const float* __restrict__ in, __nv_bfloat16* __restrict__ o1,
                         __nv_bfloat16* __restrict__ o2, long n4) {
    long i = (long)blockIdx.x * blockDim.x + threadIdx.x;
    if (i >= n4) return;
    ushort4 uh, ul;
    split4(((const float4*)in)[i], uh, ul);
    ((ushort4*)o1)[i] = uh;
    ((ushort4*)o2)[i] = ul;
}

// ---------------- batched weight split ----------------
struct WEnt { const float* src; long off4; long n4; };
struct WTab { WEnt e[12]; };

__global__ void split_bf_batch(WTab tab, __nv_bfloat16* __restrict__ o1,
                               __nv_bfloat16* __restrict__ o2) {
    WEnt en = tab.e[blockIdx.y];
    long i = (long)blockIdx.x * blockDim.x + threadIdx.x;
    if (i >= en.n4) return;
    ushort4 uh, ul;
    split4(((const float4*)en.src)[i], uh, ul);
    ((ushort4*)o1)[en.off4 + i] = uh;
    ((ushort4*)o2)[en.off4 + i] = ul;
}

// ---------------- HMMA bf16x2 GEMM (cp.async double-buffered) ----------------
#define A_ST 40
#define B_ST 136
#define A_BYTES (128 * A_ST * 2)
#define B_BYTES (32 * B_ST * 2)
#define BUF_BYTES (2 * A_BYTES + 2 * B_BYTES)
#define GSMEM_BYTES (2 * BUF_BYTES)

__device__ __forceinline__ uint32_t smem_u32(const void* p) {
    uint32_t a;
    asm("{ .reg .u64 t; cvta.to.shared.u64 t, %1; cvt.u32.u64 %0, t; }" : "=r"(a) : "l"(p));
    return a;
}

__device__ __forceinline__ void cpa16(uint32_t d, const void* s) {
    asm volatile("cp.async.cg.shared.global [%0], [%1], 16;" :: "r"(d), "l"(s));
}
#define CPA_COMMIT() asm volatile("cp.async.commit_group;" ::: "memory")

#define LDMX4(r0, r1, r2, r3, addr) \
    asm volatile("ldmatrix.sync.aligned.m8n8.x4.shared.b16 {%0,%1,%2,%3}, [%4];" \
                 : "=r"(r0), "=r"(r1), "=r"(r2), "=r"(r3) : "r"(addr))
#define LDMX2T(r0, r1, addr) \
    asm volatile("ldmatrix.sync.aligned.m8n8.x2.trans.shared.b16 {%0,%1}, [%2];" \
                 : "=r"(r0), "=r"(r1) : "r"(addr))
#define MMA16816(acc, a, b) \
    asm volatile("mma.sync.aligned.m16n8k16.row.col.f32.bf16.bf16.f32 " \
                 "{%0,%1,%2,%3}, {%4,%5,%6,%7}, {%8,%9}, {%0,%1,%2,%3};" \
                 : "+f"((acc)[0]), "+f"((acc)[1]), "+f"((acc)[2]), "+f"((acc)[3]) \
                 : "r"((a)[0]), "r"((a)[1]), "r"((a)[2]), "r"((a)[3]), \
                   "r"((b)[0]), "r"((b)[1]))

__device__ __forceinline__ void store2(float* p, float x, float y) {
    *(float2*)p = make_float2(x, y);
}
__device__ __forceinline__ void store2(__half* p, float x, float y) {
    *(__half2*)p = __floats2half2_rn(x, y);
}

template <typename OT>
__global__ void __launch_bounds__(256, 2) gemm_mma(
    const __nv_bfloat16* __restrict__ A1, const __nv_bfloat16* __restrict__ A2,
    long lda, long sAz,
    const __nv_bfloat16* __restrict__ B1, const __nv_bfloat16* __restrict__ B2,
    long ldb, long sBz,
    OT* __restrict__ C, long ldc, long sCz, int Kc)
{
    extern __shared__ char sm[];
    int tid = threadIdx.x;
    int wid = tid >> 5, lane = tid & 31;
    int mBase = blockIdx.y * 128;
    int nBase = blockIdx.x * 128;
    int z = blockIdx.z;

    const __nv_bfloat16* a1 = A1 + (long)z * sAz + (size_t)mBase * lda;
    const __nv_bfloat16* a2 = A2 + (long)z * sAz + (size_t)mBase * lda;
    const __nv_bfloat16* b1 = B1 + (long)z * sBz + nBase;
    const __nv_bfloat16* b2 = B2 + (long)z * sBz + nBase;
    OT* c = C + (long)z * sCz;

    float acc[4][4][4];
#pragma unroll
    for (int i = 0; i < 4; i++)
#pragma unroll
        for (int j = 0; j < 4; j++)
#pragma unroll
            for (int r = 0; r < 4; r++) acc[i][j][r] = 0.f;

    int mW = (wid >> 2) * 64;
    int nW = (wid & 3) * 32;
    uint32_t sb = smem_u32(sm);

    // per-thread loader indices (2 chunks of 16B each for A1/A2/B1/B2)
    int cA0 = tid, cA1 = 256 + tid;
    int rA0 = cA0 >> 2, hA0 = (cA0 & 3) << 4;
    int rA1 = cA1 >> 2, hA1 = (cA1 & 3) << 4;
    int rB0 = cA0 >> 4, hB0 = (cA0 & 15) << 4;
    int rB1 = cA1 >> 4, hB1 = (cA1 & 15) << 4;

    int nT = Kc >> 5;

    // issue tile t into buffer at smem offset bufS
    auto issue = [&](int t, uint32_t bufS) {
        long aoff = (long)t * 64;           // bytes along K (32 bf16)
        long boff = (long)t * 32;           // B rows
        cpa16(bufS + rA0 * (A_ST * 2) + hA0,
              (const char*)a1 + (size_t)rA0 * lda * 2 + aoff + hA0);
        cpa16(bufS + rA1 * (A_ST * 2) + hA1,
              (const char*)a1 + (size_t)rA1 * lda * 2 + aoff + hA1);
        cpa16(bufS + A_BYTES + rA0 * (A_ST * 2) + hA0,
              (const char*)a2 + (size_t)rA0 * lda * 2 + aoff + hA0);
        cpa16(bufS + A_BYTES + rA1 * (A_ST * 2) + hA1,
              (const char*)a2 + (size_t)rA1 * lda * 2 + aoff + hA1);
        cpa16(bufS + 2 * A_BYTES + rB0 * (B_ST * 2) + hB0,
              (const char*)b1 + (size_t)(boff + rB0) * ldb * 2 + hB0);
        cpa16(bufS + 2 * A_BYTES + rB1 * (B_ST * 2) + hB1,
              (const char*)b1 + (size_t)(boff + rB1) * ldb * 2 + hB1);
        cpa16(bufS + 2 * A_BYTES + B_BYTES + rB0 * (B_ST * 2) + hB0,
              (const char*)b2 + (size_t)(boff + rB0) * ldb * 2 + hB0);
        cpa16(bufS + 2 * A_BYTES + B_BYTES + rB1 * (B_ST * 2) + hB1,
              (const char*)b2 + (size_t)(boff + rB1) * ldb * 2 + hB1);
        CPA_COMMIT();
    };

    issue(0, sb);

    for (int t = 0; t < nT; t++) {
        // prefetch next tile into the other buffer (free since end-of-prev-iter sync)
        if (t + 1 < nT) issue(t + 1, sb + (uint32_t)((t + 1) & 1) * BUF_BYTES);
        // tile t's group is the older one
        if (t + 1 < nT) asm volatile("cp.async.wait_group 1;" ::: "memory");
        else            asm volatile("cp.async.wait_group 0;" ::: "memory");
        __syncthreads();

        uint32_t bufb = sb + (uint32_t)(t & 1) * BUF_BYTES;
        uint32_t sA1 = bufb;
        uint32_t sA2 = bufb + A_BYTES;
        uint32_t sB1 = bufb + 2 * A_BYTES;
        uint32_t sB2 = bufb + 2 * A_BYTES + B_BYTES;

#pragma unroll
        for (int kk = 0; kk < 32; kk += 16) {
            uint32_t af[2][4][4];
            uint32_t bfr[2][4][2];
#pragma unroll
            for (int mt = 0; mt < 4; mt++) {
                uint32_t off = (uint32_t)((mW + mt * 16 + (lane & 15)) * (A_ST * 2)
                                          + (kk + ((lane >> 4) << 3)) * 2);
                LDMX4(af[0][mt][0], af[0][mt][1], af[0][mt][2], af[0][mt][3], sA1 + off);
                LDMX4(af[1][mt][0], af[1][mt][1], af[1][mt][2], af[1][mt][3], sA2 + off);
            }
#pragma unroll
            for (int nt = 0; nt < 4; nt++) {
                uint32_t off = (uint32_t)((kk + (lane & 15)) * (B_ST * 2) + (nW + nt * 8) * 2);
                LDMX2T(bfr[0][nt][0], bfr[0][nt][1], sB1 + off);
                LDMX2T(bfr[1][nt][0], bfr[1][nt][1], sB2 + off);
            }
#pragma unroll
            for (int mt = 0; mt < 4; mt++)
#pragma unroll
                for (int nt = 0; nt < 4; nt++) {
                    MMA16816(acc[mt][nt], af[0][mt], bfr[0][nt]);
                    MMA16816(acc[mt][nt], af[0][mt], bfr[1][nt]);
                    MMA16816(acc[mt][nt], af[1][mt], bfr[0][nt]);
                }
        }
        __syncthreads();   // all reads of buf t done before iter t+1 issues into it
    }

#pragma unroll
    for (int mt = 0; mt < 4; mt++) {
        int row0 = mBase + mW + mt * 16 + (lane >> 2);
#pragma unroll
        for (int nt = 0; nt < 4; nt++) {
            int col = nBase + nW + nt * 8 + (lane & 3) * 2;
            OT* cr = c + (size_t)row0 * ldc + col;
            store2(cr, acc[mt][nt][0], acc[mt][nt][1]);
            store2(cr + 8 * ldc, acc[mt][nt][2], acc[mt][nt][3]);
        }
    }
}

// ---------------- CSR build ----------------
__global__ void csr_count(const float* __restrict__ adj, int* __restrict__ deg) {
    int row = blockIdx.x * (blockDim.x >> 5) + (threadIdx.x >> 5);
    if (row >= NN) return;
    int lane = threadIdx.x & 31;
    const float* r = adj + (size_t)row * NN;
    int cnt = 0;
    for (int c0 = 0; c0 < NN; c0 += 32) {
        float v = r[c0 + lane];
        unsigned m = __ballot_sync(0xffffffffu, v > 0.f);
        cnt += __popc(m);
    }
    if (lane == 0) deg[row] = cnt;
}

__global__ void csr_scan(const int* __restrict__ deg, int* __restrict__ rowptr) {
    __shared__ int s[1024];
    int t = threadIdx.x;
    int d0 = deg[2 * t], d1 = deg[2 * t + 1];
    s[t] = d0 + d1;
    __syncthreads();
    for (int off = 1; off < 1024; off <<= 1) {
        int v = s[t];
        int add = (t >= off) ? s[t - off] : 0;
        __syncthreads();
        s[t] = v + add;
        __syncthreads();
    }
    int excl = (t > 0) ? s[t - 1] : 0;
    rowptr[2 * t]     = excl;
    rowptr[2 * t + 1] = excl + d0;
    if (t == 1023) rowptr[NN] = s[1023];
}

__global__ void csr_fill(const float* __restrict__ adj, const int* __restrict__ rowptr,
                         int* __restrict__ colidx) {
    int row = blockIdx.x * (blockDim.x >> 5) + (threadIdx.x >> 5);
    if (row >= NN) return;
    int lane = threadIdx.x & 31;
    const float* r = adj + (size_t)row * NN;
    int pos = rowptr[row];
    for (int c0 = 0; c0 < NN; c0 += 32) {
        float v = r[c0 + lane];
        unsigned m = __ballot_sync(0xffffffffu, v > 0.f);
        if (v > 0.f) {
            int off = __popc(m & ((1u << lane) - 1u));
            colidx[pos + off] = c0 + lane;
        }
        pos += __popc(m);
    }
}

// ---------------- s1/s2 dot products (half h) ----------------
__global__ void dot_s_h(const __half* __restrict__ h, const float* __restrict__ a,
                        float* __restrict__ s1, float* __restrict__ s2, int hid, int total) {
    int w = (blockIdx.x * blockDim.x + threadIdx.x) >> 5;
    if (w >= total) return;
    int lane = threadIdx.x & 31;
    int head = w / NN;
    const __half2* hp = (const __half2*)(h + (size_t)w * hid);
    const float* a1 = a + (size_t)head * 2 * hid;
    const float* a2 = a1 + hid;
    int hw = hid >> 1;
    float v1 = 0.f, v2 = 0.f;
    for (int d = lane; d < hw; d += 32) {
        float2 x = __half22float2(hp[d]);
        float2 w1 = *(const float2*)&a1[2 * d];
        float2 w2 = *(const float2*)&a2[2 * d];
        v1 += x.x * w1.x + x.y * w1.y;
        v2 += x.x * w2.x + x.y * w2.y;
    }
#pragma unroll
    for (int o = 16; o; o >>= 1) {
        v1 += __shfl_xor_sync(0xffffffffu, v1, o);
        v2 += __shfl_xor_sync(0xffffffffu, v2, o);
    }
    if (lane == 0) { s1[w] = v1; s2[w] = v2; }
}

// ---------------- fused split-K reduce + o1/o2 dot (block per node) ----------------
__global__ void reduce_dot(const float* __restrict__ part, const float* __restrict__ ao,
                           __half* __restrict__ hoh, float* __restrict__ o1,
                           float* __restrict__ o2, int fout, int ks) {
    __shared__ float rbuf[8];
    int i = blockIdx.x;
    int tid = threadIdx.x;                  // 128
    int wid = tid >> 5, lane = tid & 31;
    size_t MN = (size_t)NN * fout;
    float v1 = 0.f, v2 = 0.f;
    for (int c = tid; c < fout; c += 128) {
        size_t idx = (size_t)i * fout + c;
        float s = 0.f;
        for (int p = 0; p < ks; p++) s += part[(size_t)p * MN + idx];
        hoh[idx] = __float2half_rn(s);
        v1 += s * ao[c];
        v2 += s * ao[fout + c];
    }
#pragma unroll
    for (int o = 16; o; o >>= 1) {
        v1 += __shfl_xor_sync(0xffffffffu, v1, o);
        v2 += __shfl_xor_sync(0xffffffffu, v2, o);
    }
    if (lane == 0) { rbuf[wid] = v1; rbuf[4 + wid] = v2; }
    __syncthreads();
    if (tid == 0) {
        o1[i] = rbuf[0] + rbuf[1] + rbuf[2] + rbuf[3];
        o2[i] = rbuf[4] + rbuf[5] + rbuf[6] + rbuf[7];
    }
}

// ---------------- helpers ----------------
__device__ __forceinline__ float elu1(float x) { return x > 0.f ? x : expm1f(x); }

__device__ __forceinline__ ushort4 bf_hi4(float a, float b, float c, float d,
                                          float& ra, float& rb, float& rc, float& rd) {
    __nv_bfloat16 ha = __float2bfloat16_rn(a), hb = __float2bfloat16_rn(b);
    __nv_bfloat16 hc = __float2bfloat16_rn(c), hd = __float2bfloat16_rn(d);
    ra = a - __bfloat162float(ha); rb = b - __bfloat162float(hb);
    rc = c - __bfloat162float(hc); rd = d - __bfloat162float(hd);
    ushort4 u;
    u.x = *(unsigned short*)&ha; u.y = *(unsigned short*)&hb;
    u.z = *(unsigned short*)&hc; u.w = *(unsigned short*)&hd;
    return u;
}
__device__ __forceinline__ ushort4 bf_lo4(float a, float b, float c, float d) {
    __nv_bfloat16 la = __float2bfloat16_rn(a), lb = __float2bfloat16_rn(b);
    __nv_bfloat16 lc = __float2bfloat16_rn(c), ld = __float2bfloat16_rn(d);
    ushort4 u;
    u.x = *(unsigned short*)&la; u.y = *(unsigned short*)&lb;
    u.z = *(unsigned short*)&lc; u.w = *(unsigned short*)&ld;
    return u;
}
__device__ __forceinline__ void write_bf_quad(__nv_bfloat16* o1, __nv_bfloat16* o2,
                                              size_t idx, float a, float b, float c, float d) {
    float ra, rb, rc, rd;
    *(ushort4*)(o1 + idx) = bf_hi4(a, b, c, d, ra, rb, rc, rd);
    *(ushort4*)(o2 + idx) = bf_lo4(ra, rb, rc, rd);
}

// block softmax over neighbor list. 128 threads.
__device__ __forceinline__ int block_softmax(const int* __restrict__ rowptr,
                                             const int* __restrict__ colidx,
                                             float si, const float* __restrict__ s2,
                                             int i, float* ex, int* cj, float& inv) {
    __shared__ float rbuf[8];
    int tid = threadIdx.x;
    int wid = tid >> 5, lane = tid & 31;
    int b = rowptr[i];
    int d = rowptr[i + 1] - b;
    if (d > DEG_CAP) d = DEG_CAP;
    float lm = -1e30f;
    for (int k = tid; k < d; k += 128) {
        int j = colidx[b + k];
        cj[k] = j;
        float v = si + s2[j];
        v = v > 0.f ? v : ALPHA * v;
        ex[k] = v;
        lm = fmaxf(lm, v);
    }
#pragma unroll
    for (int o = 16; o; o >>= 1) lm = fmaxf(lm, __shfl_xor_sync(0xffffffffu, lm, o));
    if (lane == 0) rbuf[wid] = lm;
    __syncthreads();
    float m = fmaxf(fmaxf(rbuf[0], rbuf[1]), fmaxf(rbuf[2], rbuf[3]));
    float ls = 0.f;
    for (int k = tid; k < d; k += 128) {
        float t = expf(ex[k] - m);
        ex[k] = t;
        ls += t;
    }
#pragma unroll
    for (int o = 16; o; o >>= 1) ls += __shfl_xor_sync(0xffffffffu, ls, o);
    if (lane == 0) rbuf[4 + wid] = ls;
    __syncthreads();
    inv = 1.f / (rbuf[4] + rbuf[5] + rbuf[6] + rbuf[7]);
    return d;
}

__device__ __forceinline__ void unpack_h4(uint2 v, float& a, float& b, float& c, float& d) {
    float2 p0 = __half22float2(*(__half2*)&v.x);
    float2 p1 = __half22float2(*(__half2*)&v.y);
    a = p0.x; b = p0.y; c = p1.x; d = p1.y;
}

// ---------------- fused head softmax + SpMM: hcat = elu(softmax @ h) ----------------
__global__ void spmm_h_fused(const int* __restrict__ rowptr, const int* __restrict__ colidx,
                             const float* __restrict__ s1, const float* __restrict__ s2,
                             const __half* __restrict__ h,
                             __nv_bfloat16* __restrict__ o1, __nv_bfloat16* __restrict__ o2,
                             int hid, int out_stride) {
    __shared__ float ex[DEG_CAP];
    __shared__ int cj[DEG_CAP];
    int i = blockIdx.x, head = blockIdx.y;
    int tid = threadIdx.x;                    // 128
    float inv;
    int d = block_softmax(rowptr, colidx, s1[(size_t)head * NN + i],
                          s2 + (size_t)head * NN, i, ex, cj, inv);
    int pos = hid >> 2;                       // uint2 chunks per row (32..128)
    if (tid >= pos) return;
    const uint2* hb = (const uint2*)(h + (size_t)head * NN * hid);
    float x0 = 0.f, x1 = 0.f, x2 = 0.f, x3 = 0.f;
#pragma unroll 4
    for (int k = 0; k < d; k++) {
        float a = ex[k];
        float v0, v1, v2, v3;
        unpack_h4(hb[(size_t)cj[k] * pos + tid], v0, v1, v2, v3);
        x0 += a * v0; x1 += a * v1; x2 += a * v2; x3 += a * v3;
    }
    size_t base = (size_t)i * out_stride + (size_t)head * hid + 4 * tid;
    write_bf_quad(o1, o2, base, elu1(x0 * inv), elu1(x1 * inv), elu1(x2 * inv), elu1(x3 * inv));
}

// ---------------- fused output softmax + SpMM: x' = elu(softmax @ ho_fp16) ----------------
__global__ void spmm_out_fused(const int* __restrict__ rowptr, const int* __restrict__ colidx,
                               const float* __restrict__ s1, const float* __restrict__ s2,
                               const __half* __restrict__ hoh,
                               __nv_bfloat16* __restrict__ o1, __nv_bfloat16* __restrict__ o2,
                               float* __restrict__ ofp, int hid) {
    __shared__ float ex[DEG_CAP];
    __shared__ int cj[DEG_CAP];
    int i = blockIdx.x;
    int tid = threadIdx.x;                    // 128
    float inv;
    int d = block_softmax(rowptr, colidx, s1[i], s2, i, ex, cj, inv);
    int pos = hid >> 2;                       // 32..96
    if (tid >= pos) return;
    const uint2* hb = (const uint2*)hoh;
    float x0 = 0.f, x1 = 0.f, x2 = 0.f, x3 = 0.f;
#pragma unroll 4
    for (int k = 0; k < d; k++) {
        float a = ex[k];
        float v0, v1, v2, v3;
        unpack_h4(hb[(size_t)cj[k] * pos + tid], v0, v1, v2, v3);
        x0 += a * v0; x1 += a * v1; x2 += a * v2; x3 += a * v3;
    }
    float e0 = elu1(x0 * inv), e1 = elu1(x1 * inv), e2 = elu1(x2 * inv), e3 = elu1(x3 * inv);
    size_t base = (size_t)i * hid + 4 * tid;
    if (ofp) *(float4*)(ofp + base) = make_float4(e0, e1, e2, e3);
    else     write_bf_quad(o1, o2, base, e0, e1, e2, e3);
}

// ---------------- host side ----------------
struct LayerDims { int fin, hid, fout; };
static const LayerDims g_dims[6] = {
    {256, 128, 128}, {128, 256, 256}, {256, 512, 384},
    {384, 512, 256}, {256, 256, 128}, {128, 128, 256}
};

extern "C" void kernel_launch(void* const* d_in, const int* in_sizes, int n_in,
                              void* d_out, int out_size) {
    const float* x   = (const float*)d_in[0];
    const float* adj = (const float*)d_in[1];

    float *p_s1, *p_s2, *p_o1v, *p_o2v, *p_part;
    int *p_deg, *p_rowptr, *p_colidx;
    __half *p_h, *p_hoh;
    __nv_bfloat16 *p_a1, *p_a2, *p_b1, *p_b2;
    cudaGetSymbolAddress((void**)&p_deg, g_deg);
    cudaGetSymbolAddress((void**)&p_rowptr, g_rowptr);
    cudaGetSymbolAddress((void**)&p_colidx, g_colidx);
    cudaGetSymbolAddress((void**)&p_h, g_h);
    cudaGetSymbolAddress((void**)&p_s1, g_s1);
    cudaGetSymbolAddress((void**)&p_s2, g_s2);
    cudaGetSymbolAddress((void**)&p_hoh, g_hoh);
    cudaGetSymbolAddress((void**)&p_o1v, g_o1);
    cudaGetSymbolAddress((void**)&p_o2v, g_o2);
    cudaGetSymbolAddress((void**)&p_part, g_part);
    cudaGetSymbolAddress((void**)&p_a1, g_a1);
    cudaGetSymbolAddress((void**)&p_a2, g_a2);
    cudaGetSymbolAddress((void**)&p_b1, g_b1);
    cudaGetSymbolAddress((void**)&p_b2, g_b2);

    static int smem_set = 0;
    if (!smem_set) {
        cudaFuncSetAttribute(gemm_mma<float>, cudaFuncAttributeMaxDynamicSharedMemorySize, GSMEM_BYTES);
        cudaFuncSetAttribute(gemm_mma<__half>, cudaFuncAttributeMaxDynamicSharedMemorySize, GSMEM_BYTES);
        smem_set = 1;
    }

    // weight table: offsets into g_b1/g_b2 (elements), hi/lo split once upfront
    long whoff[6], wooff[6];
    WTab tab;
    long cur = 0, maxN4 = 0;
    for (int l = 0; l < 6; l++) {
        int fin = g_dims[l].fin, hid = g_dims[l].hid, fout = g_dims[l].fout;
        long nWh = (long)NH * fin * hid;
        long nWo = (long)NH * hid * fout;
        whoff[l] = cur;
        tab.e[2 * l] = { (const float*)d_in[2 + 4 * l], cur / 4, nWh / 4 };
        cur += nWh;
        wooff[l] = cur;
        tab.e[2 * l + 1] = { (const float*)d_in[4 + 4 * l], cur / 4, nWo / 4 };
        cur += nWo;
        if (nWh / 4 > maxN4) maxN4 = nWh / 4;
        if (nWo / 4 > maxN4) maxN4 = nWo / 4;
    }

    // Build CSR of adjacency
    csr_count<<<NN / 8, 256>>>(adj, p_deg);
    csr_scan<<<1, 1024>>>(p_deg, p_rowptr);
    csr_fill<<<NN / 8, 256>>>(adj, p_rowptr, p_colidx);

    // all weights split in one launch; layer-0 x split
    split_bf_batch<<<dim3((unsigned)((maxN4 + 255) / 256), 12), 256>>>(tab, p_b1, p_b2);
    split_bf<<<(NN * 256 / 4 + 255) / 256, 256>>>(x, p_a1, p_a2, NN * 256 / 4);

    for (int l = 0; l < 6; l++) {
        int fin = g_dims[l].fin, hid = g_dims[l].hid, fout = g_dims[l].fout;
        const float* ah = (const float*)d_in[3 + 4 * l];
        const float* ao = (const float*)d_in[5 + 4 * l];

        // ---- head GEMM: h[head] = x @ Wh[head], fp16 output ----
        gemm_mma<__half><<<dim3(hid / 128, NN / 128, NH), 256, GSMEM_BYTES>>>(
            p_a1, p_a2, fin, 0L,
            p_b1 + whoff[l], p_b2 + whoff[l], hid, (long)fin * hid,
            p_h, hid, (long)NN * hid, fin);

        // s1/s2, fused softmax+SpMM (writes hcat bf16 hi/lo -> Wo A operands)
        int totalHN = NH * NN;
        dot_s_h<<<(totalHN * 32 + 255) / 256, 256>>>(p_h, ah, p_s1, p_s2, hid, totalHN);
        spmm_h_fused<<<dim3(NN, NH), 128>>>(p_rowptr, p_colidx, p_s1, p_s2, p_h,
                                            p_a1, p_a2, hid, NH * hid);

        // ---- output GEMM: ho = hcat @ Wo, adaptive split-K, fused reduce+dot ----
        int Ktot = NH * hid;
        int ks = (fout >= 256) ? 4 : 8;
        int Kc = Ktot / ks;
        gemm_mma<float><<<dim3(fout / 128, NN / 128, ks), 256, GSMEM_BYTES>>>(
            p_a1, p_a2, Ktot, (long)Kc,
            p_b1 + wooff[l], p_b2 + wooff[l], fout, (long)Kc * fout,
            p_part, fout, (long)NN * fout, Kc);
        reduce_dot<<<NN, 128>>>(p_part, ao, p_hoh, p_o1v, p_o2v, fout, ks);

        // fused output softmax + SpMM; fp32 d_out at layer 5, else bf16 hi/lo A
        float* ofp = (l == 5) ? (float*)d_out : nullptr;
        spmm_out_fused<<<NN, 128>>>(p_rowptr, p_colidx, p_o1v, p_o2v, p_hoh,
                                    p_a1, p_a2, ofp, fout);
    }
    (void)in_sizes; (void)n_in; (void)out_size;
}

// round 11
// speedup vs baseline: 1.0092x; 1.0092x over previous
#include <cuda_runtime.h>
#include <cuda_bf16.h>
#include <cuda_fp16.h>
#include <math.h>
#include <stdint.h>

#define NN 2048          // nodes
#define NH 8             // heads
#define ALPHA 0.2f
#define NNZ_CAP (2048*128)
#define HID_MAX 512
#define DEG_CAP 1024

// ---------------- scratch (static device allocations) ----------------
__device__ int   g_deg[NN];
__device__ int   g_rowptr[NN + 1];
__device__ int   g_colidx[NNZ_CAP];
__device__ __half g_h[NH * NN * HID_MAX];       // per-head projected features (fp16)
__device__ float g_s1[NH * NN];
__device__ float g_s2[NH * NN];
__device__ __half g_hoh[NN * HID_MAX];          // output-head features (fp16, gather operand)
__device__ float g_o1[NN];
__device__ float g_o2[NN];
__device__ float g_part[8 * NN * 384];          // split-K partials for Wo gemm
// bf16 hi/lo operand buffers (A: activations; B: ALL weights, pre-split once)
__device__ __nv_bfloat16 g_a1[NN * 4096];
__device__ __nv_bfloat16 g_a2[NN * 4096];
__device__ __nv_bfloat16 g_b1[1 << 23];
__device__ __nv_bfloat16 g_b2[1 << 23];

// ---------------- bf16 hi/lo elementwise split ----------------
__device__ __forceinline__ void split4(float4 v, ushort4& uh, ushort4& ul) {
    __nv_bfloat16 h0 = __float2bfloat16_rn(v.x), h1 = __float2bfloat16_rn(v.y);
    __nv_bfloat16 h2 = __float2bfloat16_rn(v.z), h3 = __float2bfloat16_rn(v.w);
    __nv_bfloat16 l0 = __float2bfloat16_rn(v.x - __bfloat162float(h0));
    __nv_bfloat16 l1 = __float2bfloat16_rn(v.y - __bfloat162float(h1));
    __nv_bfloat16 l2 = __float2bfloat16_rn(v.z - __bfloat162float(h2));
    __nv_bfloat16 l3 = __float2bfloat16_rn(v.w - __bfloat162float(h3));
    uh.x = *(unsigned short*)&h0; uh.y = *(unsigned short*)&h1;
    uh.z = *(unsigned short*)&h2; uh.w = *(unsigned short*)&h3;
    ul.x = *(unsigned short*)&l0; ul.y = *(unsigned short*)&l1;
    ul.z = *(unsigned short*)&l2; ul.w = *(unsigned short*)&l3;
}

__global__ void split_bf(const float* __restrict__ in, __nv_bfloat16* __restrict__ o1,
                         __nv_bfloat16* __restrict__ o2, long n4) {
    long i = (long)blockIdx.x * blockDim.x + threadIdx.x;
    if (i >= n4) return;
    ushort4 uh, ul;
    split4(((const float4*)in)[i], uh, ul);
    ((ushort4*)o1)[i] = uh;
    ((ushort4*)o2)[i] = ul;
}

// ---------------- batched weight split ----------------
struct WEnt { const float* src; long off4; long n4; };
struct WTab { WEnt e[12]; };

__global__ void split_bf_batch(WTab tab, __nv_bfloat16* __restrict__ o1,
                               __nv_bfloat16* __restrict__ o2) {
    WEnt en = tab.e[blockIdx.y];
    long i = (long)blockIdx.x * blockDim.x + threadIdx.x;
    if (i >= en.n4) return;
    ushort4 uh, ul;
    split4(((const float4*)en.src)[i], uh, ul);
    ((ushort4*)o1)[en.off4 + i] = uh;
    ((ushort4*)o2)[en.off4 + i] = ul;
}

// ---------------- HMMA bf16x2 GEMM (register-staged, proven R9 version) ----------------
#define A_ST 40
#define B_ST 136
#define A_BYTES (128 * A_ST * 2)
#define B_BYTES (32 * B_ST * 2)
#define BUF_BYTES (2 * A_BYTES + 2 * B_BYTES)
#define GSMEM_BYTES (2 * BUF_BYTES)

__device__ __forceinline__ uint32_t smem_u32(const void* p) {
    uint32_t a;
    asm("{ .reg .u64 t; cvta.to.shared.u64 t, %1; cvt.u32.u64 %0, t; }" : "=r"(a) : "l"(p));
    return a;
}

#define LDMX4(r0, r1, r2, r3, addr) \
    asm volatile("ldmatrix.sync.aligned.m8n8.x4.shared.b16 {%0,%1,%2,%3}, [%4];" \
                 : "=r"(r0), "=r"(r1), "=r"(r2), "=r"(r3) : "r"(addr))
#define LDMX2T(r0, r1, addr) \
    asm volatile("ldmatrix.sync.aligned.m8n8.x2.trans.shared.b16 {%0,%1}, [%2];" \
                 : "=r"(r0), "=r"(r1) : "r"(addr))
#define MMA16816(acc, a, b) \
    asm volatile("mma.sync.aligned.m16n8k16.row.col.f32.bf16.bf16.f32 " \
                 "{%0,%1,%2,%3}, {%4,%5,%6,%7}, {%8,%9}, {%0,%1,%2,%3};" \
                 : "+f"((acc)[0]), "+f"((acc)[1]), "+f"((acc)[2]), "+f"((acc)[3]) \
                 : "r"((a)[0]), "r"((a)[1]), "r"((a)[2]), "r"((a)[3]), \
                   "r"((b)[0]), "r"((b)[1]))

__device__ __forceinline__ void store2(float* p, float x, float y) {
    *(float2*)p = make_float2(x, y);
}
__device__ __forceinline__ void store2(__half* p, float x, float y) {
    *(__half2*)p = __floats2half2_rn(x, y);
}

template <typename OT>
__global__ void __launch_bounds__(256, 1) gemm_mma(
    const __nv_bfloat16* __restrict__ A1, const __nv_bfloat16* __restrict__ A2,
    long lda, long sAz,
    const __nv_bfloat16* __restrict__ B1, const __nv_bfloat16* __restrict__ B2,
    long ldb, long sBz,
    OT* __restrict__ C, long ldc, long sCz, int Kc)
{
    extern __shared__ char sm[];
    int tid = threadIdx.x;
    int wid = tid >> 5, lane = tid & 31;
    int mBase = blockIdx.y * 128;
    int nBase = blockIdx.x * 128;
    int z = blockIdx.z;

    const __nv_bfloat16* a1 = A1 + (long)z * sAz + (size_t)mBase * lda;
    const __nv_bfloat16* a2 = A2 + (long)z * sAz + (size_t)mBase * lda;
    const __nv_bfloat16* b1 = B1 + (long)z * sBz + nBase;
    const __nv_bfloat16* b2 = B2 + (long)z * sBz + nBase;
    OT* c = C + (long)z * sCz;

    float acc[4][4][4];
#pragma unroll
    for (int i = 0; i < 4; i++)
#pragma unroll
        for (int j = 0; j < 4; j++)
#pragma unroll
            for (int r = 0; r < 4; r++) acc[i][j][r] = 0.f;

    int mW = (wid >> 2) * 64;
    int nW = (wid & 3) * 32;
    uint32_t sb = smem_u32(sm);
    uint4 ra1[2], ra2[2], rb1[2], rb2[2];

#pragma unroll
    for (int i = 0; i < 2; i++) {
        int cch = i * 256 + tid;
        int r = cch >> 2, ch = cch & 3;
        ra1[i] = *(const uint4*)((const char*)a1 + (size_t)r * lda * 2 + ch * 16);
        ra2[i] = *(const uint4*)((const char*)a2 + (size_t)r * lda * 2 + ch * 16);
        int rB = cch >> 4, chB = cch & 15;
        rb1[i] = *(const uint4*)((const char*)b1 + (size_t)rB * ldb * 2 + chB * 16);
        rb2[i] = *(const uint4*)((const char*)b2 + (size_t)rB * ldb * 2 + chB * 16);
    }
#pragma unroll
    for (int i = 0; i < 2; i++) {
        int cch = i * 256 + tid;
        int r = cch >> 2, ch = cch & 3;
        *(uint4*)(sm + r * (A_ST * 2) + ch * 16) = ra1[i];
        *(uint4*)(sm + A_BYTES + r * (A_ST * 2) + ch * 16) = ra2[i];
        int rB = cch >> 4, chB = cch & 15;
        *(uint4*)(sm + 2 * A_BYTES + rB * (B_ST * 2) + chB * 16) = rb1[i];
        *(uint4*)(sm + 2 * A_BYTES + B_BYTES + rB * (B_ST * 2) + chB * 16) = rb2[i];
    }
    __syncthreads();

    int nT = Kc >> 5;
    for (int t = 0; t < nT; t++) {
        if (t + 1 < nT) {
#pragma unroll
            for (int i = 0; i < 2; i++) {
                int cch = i * 256 + tid;
                int r = cch >> 2, ch = cch & 3;
                ra1[i] = *(const uint4*)((const char*)a1 + (size_t)r * lda * 2 + (t + 1) * 64 + ch * 16);
                ra2[i] = *(const uint4*)((const char*)a2 + (size_t)r * lda * 2 + (t + 1) * 64 + ch * 16);
                int rB = cch >> 4, chB = cch & 15;
                rb1[i] = *(const uint4*)((const char*)b1 + (size_t)((t + 1) * 32 + rB) * ldb * 2 + chB * 16);
                rb2[i] = *(const uint4*)((const char*)b2 + (size_t)((t + 1) * 32 + rB) * ldb * 2 + chB * 16);
            }
        }
        uint32_t bufb = sb + (uint32_t)(t & 1) * BUF_BYTES;
        uint32_t sA1 = bufb;
        uint32_t sA2 = bufb + A_BYTES;
        uint32_t sB1 = bufb + 2 * A_BYTES;
        uint32_t sB2 = bufb + 2 * A_BYTES + B_BYTES;

#pragma unroll
        for (int kk = 0; kk < 32; kk += 16) {
            uint32_t af[2][4][4];
            uint32_t bfr[2][4][2];
#pragma unroll
            for (int mt = 0; mt < 4; mt++) {
                uint32_t off = (uint32_t)((mW + mt * 16 + (lane & 15)) * (A_ST * 2)
                                          + (kk + ((lane >> 4) << 3)) * 2);
                LDMX4(af[0][mt][0], af[0][mt][1], af[0][mt][2], af[0][mt][3], sA1 + off);
                LDMX4(af[1][mt][0], af[1][mt][1], af[1][mt][2], af[1][mt][3], sA2 + off);
            }
#pragma unroll
            for (int nt = 0; nt < 4; nt++) {
                uint32_t off = (uint32_t)((kk + (lane & 15)) * (B_ST * 2) + (nW + nt * 8) * 2);
                LDMX2T(bfr[0][nt][0], bfr[0][nt][1], sB1 + off);
                LDMX2T(bfr[1][nt][0], bfr[1][nt][1], sB2 + off);
            }
#pragma unroll
            for (int mt = 0; mt < 4; mt++)
#pragma unroll
                for (int nt = 0; nt < 4; nt++) {
                    MMA16816(acc[mt][nt], af[0][mt], bfr[0][nt]);
                    MMA16816(acc[mt][nt], af[0][mt], bfr[1][nt]);
                    MMA16816(acc[mt][nt], af[1][mt], bfr[0][nt]);
                }
        }
        if (t + 1 < nT) {
            char* nb = sm + ((t + 1) & 1) * BUF_BYTES;
#pragma unroll
            for (int i = 0; i < 2; i++) {
                int cch = i * 256 + tid;
                int r = cch >> 2, ch = cch & 3;
                *(uint4*)(nb + r * (A_ST * 2) + ch * 16) = ra1[i];
                *(uint4*)(nb + A_BYTES + r * (A_ST * 2) + ch * 16) = ra2[i];
                int rB = cch >> 4, chB = cch & 15;
                *(uint4*)(nb + 2 * A_BYTES + rB * (B_ST * 2) + chB * 16) = rb1[i];
                *(uint4*)(nb + 2 * A_BYTES + B_BYTES + rB * (B_ST * 2) + chB * 16) = rb2[i];
            }
            __syncthreads();
        }
    }

#pragma unroll
    for (int mt = 0; mt < 4; mt++) {
        int row0 = mBase + mW + mt * 16 + (lane >> 2);
#pragma unroll
        for (int nt = 0; nt < 4; nt++) {
            int col = nBase + nW + nt * 8 + (lane & 3) * 2;
            OT* cr = c + (size_t)row0 * ldc + col;
            store2(cr, acc[mt][nt][0], acc[mt][nt][1]);
            store2(cr + 8 * ldc, acc[mt][nt][2], acc[mt][nt][3]);
        }
    }
}

// ---------------- CSR build ----------------
__global__ void csr_count(const float* __restrict__ adj, int* __restrict__ deg) {
    int row = blockIdx.x * (blockDim.x >> 5) + (threadIdx.x >> 5);
    if (row >= NN) return;
    int lane = threadIdx.x & 31;
    const float* r = adj + (size_t)row * NN;
    int cnt = 0;
    for (int c0 = 0; c0 < NN; c0 += 32) {
        float v = r[c0 + lane];
        unsigned m = __ballot_sync(0xffffffffu, v > 0.f);
        cnt += __popc(m);
    }
    if (lane == 0) deg[row] = cnt;
}

__global__ void csr_scan(const int* __restrict__ deg, int* __restrict__ rowptr) {
    __shared__ int s[1024];
    int t = threadIdx.x;
    int d0 = deg[2 * t], d1 = deg[2 * t + 1];
    s[t] = d0 + d1;
    __syncthreads();
    for (int off = 1; off < 1024; off <<= 1) {
        int v = s[t];
        int add = (t >= off) ? s[t - off] : 0;
        __syncthreads();
        s[t] = v + add;
        __syncthreads();
    }
    int excl = (t > 0) ? s[t - 1] : 0;
    rowptr[2 * t]     = excl;
    rowptr[2 * t + 1] = excl + d0;
    if (t == 1023) rowptr[NN] = s[1023];
}

__global__ void csr_fill(const float* __restrict__ adj, const int* __restrict__ rowptr,
                         int* __restrict__ colidx) {
    int row = blockIdx.x * (blockDim.x >> 5) + (threadIdx.x >> 5);
    if (row >= NN) return;
    int lane = threadIdx.x & 31;
    const float* r = adj + (size_t)row * NN;
    int pos = rowptr[row];
    for (int c0 = 0; c0 < NN; c0 += 32) {
        float v = r[c0 + lane];
        unsigned m = __ballot_sync(0xffffffffu, v > 0.f);
        if (v > 0.f) {
            int off = __popc(m & ((1u << lane) - 1u));
            colidx[pos + off] = c0 + lane;
        }
        pos += __popc(m);
    }
}

// ---------------- s1/s2 dot products (half h) ----------------
__global__ void dot_s_h(const __half* __restrict__ h, const float* __restrict__ a,
                        float* __restrict__ s1, float* __restrict__ s2, int hid, int total) {
    int w = (blockIdx.x * blockDim.x + threadIdx.x) >> 5;
    if (w >= total) return;
    int lane = threadIdx.x & 31;
    int head = w / NN;
    const __half2* hp = (const __half2*)(h + (size_t)w * hid);
    const float* a1 = a + (size_t)head * 2 * hid;
    const float* a2 = a1 + hid;
    int hw = hid >> 1;
    float v1 = 0.f, v2 = 0.f;
    for (int d = lane; d < hw; d += 32) {
        float2 x = __half22float2(hp[d]);
        float2 w1 = *(const float2*)&a1[2 * d];
        float2 w2 = *(const float2*)&a2[2 * d];
        v1 += x.x * w1.x + x.y * w1.y;
        v2 += x.x * w2.x + x.y * w2.y;
    }
#pragma unroll
    for (int o = 16; o; o >>= 1) {
        v1 += __shfl_xor_sync(0xffffffffu, v1, o);
        v2 += __shfl_xor_sync(0xffffffffu, v2, o);
    }
    if (lane == 0) { s1[w] = v1; s2[w] = v2; }
}

// ---------------- fused split-K reduce + o1/o2 dot (block per node) ----------------
__global__ void reduce_dot(const float* __restrict__ part, const float* __restrict__ ao,
                           __half* __restrict__ hoh, float* __restrict__ o1,
                           float* __restrict__ o2, int fout, int ks) {
    __shared__ float rbuf[8];
    int i = blockIdx.x;
    int tid = threadIdx.x;                  // 128
    int wid = tid >> 5, lane = tid & 31;
    size_t MN = (size_t)NN * fout;
    float v1 = 0.f, v2 = 0.f;
    for (int c = tid; c < fout; c += 128) {
        size_t idx = (size_t)i * fout + c;
        float s = 0.f;
        for (int p = 0; p < ks; p++) s += part[(size_t)p * MN + idx];
        hoh[idx] = __float2half_rn(s);
        v1 += s * ao[c];
        v2 += s * ao[fout + c];
    }
#pragma unroll
    for (int o = 16; o; o >>= 1) {
        v1 += __shfl_xor_sync(0xffffffffu, v1, o);
        v2 += __shfl_xor_sync(0xffffffffu, v2, o);
    }
    if (lane == 0) { rbuf[wid] = v1; rbuf[4 + wid] = v2; }
    __syncthreads();
    if (tid == 0) {
        o1[i] = rbuf[0] + rbuf[1] + rbuf[2] + rbuf[3];
        o2[i] = rbuf[4] + rbuf[5] + rbuf[6] + rbuf[7];
    }
}

// ---------------- helpers ----------------
__device__ __forceinline__ float elu1(float x) { return x > 0.f ? x : expm1f(x); }

__device__ __forceinline__ ushort4 bf_hi4(float a, float b, float c, float d,
                                          float& ra, float& rb, float& rc, float& rd) {
    __nv_bfloat16 ha = __float2bfloat16_rn(a), hb = __float2bfloat16_rn(b);
    __nv_bfloat16 hc = __float2bfloat16_rn(c), hd = __float2bfloat16_rn(d);
    ra = a - __bfloat162float(ha); rb = b - __bfloat162float(hb);
    rc = c - __bfloat162float(hc); rd = d - __bfloat162float(hd);
    ushort4 u;
    u.x = *(unsigned short*)&ha; u.y = *(unsigned short*)&hb;
    u.z = *(unsigned short*)&hc; u.w = *(unsigned short*)&hd;
    return u;
}
__device__ __forceinline__ ushort4 bf_lo4(float a, float b, float c, float d) {
    __nv_bfloat16 la = __float2bfloat16_rn(a), lb = __float2bfloat16_rn(b);
    __nv_bfloat16 lc = __float2bfloat16_rn(c), ld = __float2bfloat16_rn(d);
    ushort4 u;
    u.x = *(unsigned short*)&la; u.y = *(unsigned short*)&lb;
    u.z = *(unsigned short*)&lc; u.w = *(unsigned short*)&ld;
    return u;
}
__device__ __forceinline__ void write_bf_quad(__nv_bfloat16* o1, __nv_bfloat16* o2,
                                              size_t idx, float a, float b, float c, float d) {
    float ra, rb, rc, rd;
    *(ushort4*)(o1 + idx) = bf_hi4(a, b, c, d, ra, rb, rc, rd);
    *(ushort4*)(o2 + idx) = bf_lo4(ra, rb, rc, rd);
}

// block softmax over neighbor list. 128 threads. All threads stay alive.
__device__ __forceinline__ int block_softmax(const int* __restrict__ rowptr,
                                             const int* __restrict__ colidx,
                                             float si, const float* __restrict__ s2,
                                             int i, float* ex, int* cj, float& inv) {
    __shared__ float rbuf[8];
    int tid = threadIdx.x;
    int wid = tid >> 5, lane = tid & 31;
    int b = rowptr[i];
    int d = rowptr[i + 1] - b;
    if (d > DEG_CAP) d = DEG_CAP;
    float lm = -1e30f;
    for (int k = tid; k < d; k += 128) {
        int j = colidx[b + k];
        cj[k] = j;
        float v = si + s2[j];
        v = v > 0.f ? v : ALPHA * v;
        ex[k] = v;
        lm = fmaxf(lm, v);
    }
#pragma unroll
    for (int o = 16; o; o >>= 1) lm = fmaxf(lm, __shfl_xor_sync(0xffffffffu, lm, o));
    if (lane == 0) rbuf[wid] = lm;
    __syncthreads();
    float m = fmaxf(fmaxf(rbuf[0], rbuf[1]), fmaxf(rbuf[2], rbuf[3]));
    float ls = 0.f;
    for (int k = tid; k < d; k += 128) {
        float t = expf(ex[k] - m);
        ex[k] = t;
        ls += t;
    }
#pragma unroll
    for (int o = 16; o; o >>= 1) ls += __shfl_xor_sync(0xffffffffu, ls, o);
    if (lane == 0) rbuf[4 + wid] = ls;
    __syncthreads();
    inv = 1.f / (rbuf[4] + rbuf[5] + rbuf[6] + rbuf[7]);
    return d;
}

__device__ __forceinline__ void unpack_h4(uint2 v, float& a, float& b, float& c, float& d) {
    float2 p0 = __half22float2(*(__half2*)&v.x);
    float2 p1 = __half22float2(*(__half2*)&v.y);
    a = p0.x; b = p0.y; c = p1.x; d = p1.y;
}

// ---------------- fused head softmax + SpMM with neighbor-group parallelism ----------------
// pos = hid/4 chunks; g = 128/pos groups; group s handles neighbors k = s, s+g, ...
__global__ void spmm_h_fused(const int* __restrict__ rowptr, const int* __restrict__ colidx,
                             const float* __restrict__ s1, const float* __restrict__ s2,
                             const __half* __restrict__ h,
                             __nv_bfloat16* __restrict__ o1, __nv_bfloat16* __restrict__ o2,
                             int hid, int out_stride) {
    __shared__ float ex[DEG_CAP];
    __shared__ int cj[DEG_CAP];
    __shared__ float4 pbuf[128];
    int i = blockIdx.x, head = blockIdx.y;
    int tid = threadIdx.x;                    // 128
    float inv;
    int d = block_softmax(rowptr, colidx, s1[(size_t)head * NN + i],
                          s2 + (size_t)head * NN, i, ex, cj, inv);
    int pos = hid >> 2;                       // 32..128
    int g = 128 / pos;                        // 1,2,4
    int c = tid % pos;
    int s = tid / pos;
    bool active = tid < pos * g;
    const uint2* hb = (const uint2*)(h + (size_t)head * NN * hid);
    float x0 = 0.f, x1 = 0.f, x2 = 0.f, x3 = 0.f;
    if (active) {
#pragma unroll 4
        for (int k = s; k < d; k += g) {
            float a = ex[k];
            float v0, v1, v2, v3;
            unpack_h4(hb[(size_t)cj[k] * pos + c], v0, v1, v2, v3);
            x0 += a * v0; x1 += a * v1; x2 += a * v2; x3 += a * v3;
        }
    }
    if (g > 1) {
        pbuf[tid] = make_float4(x0, x1, x2, x3);
        __syncthreads();
        if (s == 0) {
            for (int q = 1; q < g; q++) {
                float4 p = pbuf[c + q * pos];
                x0 += p.x; x1 += p.y; x2 += p.z; x3 += p.w;
            }
        }
    }
    if (s == 0 && active) {
        size_t base = (size_t)i * out_stride + (size_t)head * hid + 4 * c;
        write_bf_quad(o1, o2, base, elu1(x0 * inv), elu1(x1 * inv),
                      elu1(x2 * inv), elu1(x3 * inv));
    }
}

// ---------------- fused output softmax + SpMM (fp16 ho), neighbor groups ----------------
__global__ void spmm_out_fused(const int* __restrict__ rowptr, const int* __restrict__ colidx,
                               const float* __restrict__ s1, const float* __restrict__ s2,
                               const __half* __restrict__ hoh,
                               __nv_bfloat16* __restrict__ o1, __nv_bfloat16* __restrict__ o2,
                               float* __restrict__ ofp, int hid) {
    __shared__ float ex[DEG_CAP];
    __shared__ int cj[DEG_CAP];
    __shared__ float4 pbuf[128];
    int i = blockIdx.x;
    int tid = threadIdx.x;                    // 128
    float inv;
    int d = block_softmax(rowptr, colidx, s1[i], s2, i, ex, cj, inv);
    int pos = hid >> 2;                       // 32..96
    int g = 128 / pos;                        // 1,2,4
    int c = tid % pos;
    int s = tid / pos;
    bool active = tid < pos * g;
    const uint2* hb = (const uint2*)hoh;
    float x0 = 0.f, x1 = 0.f, x2 = 0.f, x3 = 0.f;
    if (active) {
#pragma unroll 4
        for (int k = s; k < d; k += g) {
            float a = ex[k];
            float v0, v1, v2, v3;
            unpack_h4(hb[(size_t)cj[k] * pos + c], v0, v1, v2, v3);
            x0 += a * v0; x1 += a * v1; x2 += a * v2; x3 += a * v3;
        }
    }
    if (g > 1) {
        pbuf[tid] = make_float4(x0, x1, x2, x3);
        __syncthreads();
        if (s == 0) {
            for (int q = 1; q < g; q++) {
                float4 p = pbuf[c + q * pos];
                x0 += p.x; x1 += p.y; x2 += p.z; x3 += p.w;
            }
        }
    }
    if (s == 0 && active) {
        float e0 = elu1(x0 * inv), e1 = elu1(x1 * inv), e2 = elu1(x2 * inv), e3 = elu1(x3 * inv);
        size_t base = (size_t)i * hid + 4 * c;
        if (ofp) *(float4*)(ofp + base) = make_float4(e0, e1, e2, e3);
        else     write_bf_quad(o1, o2, base, e0, e1, e2, e3);
    }
}

// ---------------- host side ----------------
struct LayerDims { int fin, hid, fout; };
static const LayerDims g_dims[6] = {
    {256, 128, 128}, {128, 256, 256}, {256, 512, 384},
    {384, 512, 256}, {256, 256, 128}, {128, 128, 256}
};

extern "C" void kernel_launch(void* const* d_in, const int* in_sizes, int n_in,
                              void* d_out, int out_size) {
    const float* x   = (const float*)d_in[0];
    const float* adj = (const float*)d_in[1];

    float *p_s1, *p_s2, *p_o1v, *p_o2v, *p_part;
    int *p_deg, *p_rowptr, *p_colidx;
    __half *p_h, *p_hoh;
    __nv_bfloat16 *p_a1, *p_a2, *p_b1, *p_b2;
    cudaGetSymbolAddress((void**)&p_deg, g_deg);
    cudaGetSymbolAddress((void**)&p_rowptr, g_rowptr);
    cudaGetSymbolAddress((void**)&p_colidx, g_colidx);
    cudaGetSymbolAddress((void**)&p_h, g_h);
    cudaGetSymbolAddress((void**)&p_s1, g_s1);
    cudaGetSymbolAddress((void**)&p_s2, g_s2);
    cudaGetSymbolAddress((void**)&p_hoh, g_hoh);
    cudaGetSymbolAddress((void**)&p_o1v, g_o1);
    cudaGetSymbolAddress((void**)&p_o2v, g_o2);
    cudaGetSymbolAddress((void**)&p_part, g_part);
    cudaGetSymbolAddress((void**)&p_a1, g_a1);
    cudaGetSymbolAddress((void**)&p_a2, g_a2);
    cudaGetSymbolAddress((void**)&p_b1, g_b1);
    cudaGetSymbolAddress((void**)&p_b2, g_b2);

    static int smem_set = 0;
    if (!smem_set) {
        cudaFuncSetAttribute(gemm_mma<float>, cudaFuncAttributeMaxDynamicSharedMemorySize, GSMEM_BYTES);
        cudaFuncSetAttribute(gemm_mma<__half>, cudaFuncAttributeMaxDynamicSharedMemorySize, GSMEM_BYTES);
        smem_set = 1;
    }

    // weight table: offsets into g_b1/g_b2 (elements), hi/lo split once upfront
    long whoff[6], wooff[6];
    WTab tab;
    long cur = 0, maxN4 = 0;
    for (int l = 0; l < 6; l++) {
        int fin = g_dims[l].fin, hid = g_dims[l].hid, fout = g_dims[l].fout;
        long nWh = (long)NH * fin * hid;
        long nWo = (long)NH * hid * fout;
        whoff[l] = cur;
        tab.e[2 * l] = { (const float*)d_in[2 + 4 * l], cur / 4, nWh / 4 };
        cur += nWh;
        wooff[l] = cur;
        tab.e[2 * l + 1] = { (const float*)d_in[4 + 4 * l], cur / 4, nWo / 4 };
        cur += nWo;
        if (nWh / 4 > maxN4) maxN4 = nWh / 4;
        if (nWo / 4 > maxN4) maxN4 = nWo / 4;
    }

    // Build CSR of adjacency
    csr_count<<<NN / 8, 256>>>(adj, p_deg);
    csr_scan<<<1, 1024>>>(p_deg, p_rowptr);
    csr_fill<<<NN / 8, 256>>>(adj, p_rowptr, p_colidx);

    // all weights split in one launch; layer-0 x split
    split_bf_batch<<<dim3((unsigned)((maxN4 + 255) / 256), 12), 256>>>(tab, p_b1, p_b2);
    split_bf<<<(NN * 256 / 4 + 255) / 256, 256>>>(x, p_a1, p_a2, NN * 256 / 4);

    for (int l = 0; l < 6; l++) {
        int fin = g_dims[l].fin, hid = g_dims[l].hid, fout = g_dims[l].fout;
        const float* ah = (const float*)d_in[3 + 4 * l];
        const float* ao = (const float*)d_in[5 + 4 * l];

        // ---- head GEMM: h[head] = x @ Wh[head], fp16 output ----
        gemm_mma<__half><<<dim3(hid / 128, NN / 128, NH), 256, GSMEM_BYTES>>>(
            p_a1, p_a2, fin, 0L,
            p_b1 + whoff[l], p_b2 + whoff[l], hid, (long)fin * hid,
            p_h, hid, (long)NN * hid, fin);

        // s1/s2, fused softmax+SpMM (writes hcat bf16 hi/lo -> Wo A operands)
        int totalHN = NH * NN;
        dot_s_h<<<(totalHN * 32 + 255) / 256, 256>>>(p_h, ah, p_s1, p_s2, hid, totalHN);
        spmm_h_fused<<<dim3(NN, NH), 128>>>(p_rowptr, p_colidx, p_s1, p_s2, p_h,
                                            p_a1, p_a2, hid, NH * hid);

        // ---- output GEMM: ho = hcat @ Wo, adaptive split-K, fused reduce+dot ----
        int Ktot = NH * hid;
        int ks = (fout >= 256) ? 4 : 8;
        int Kc = Ktot / ks;
        gemm_mma<float><<<dim3(fout / 128, NN / 128, ks), 256, GSMEM_BYTES>>>(
            p_a1, p_a2, Ktot, (long)Kc,
            p_b1 + wooff[l], p_b2 + wooff[l], fout, (long)Kc * fout,
            p_part, fout, (long)NN * fout, Kc);
        reduce_dot<<<NN, 128>>>(p_part, ao, p_hoh, p_o1v, p_o2v, fout, ks);

        // fused output softmax + SpMM; fp32 d_out at layer 5, else bf16 hi/lo A
        float* ofp = (l == 5) ? (float*)d_out : nullptr;
        spmm_out_fused<<<NN, 128>>>(p_rowptr, p_colidx, p_o1v, p_o2v, p_hoh,
                                    p_a1, p_a2, ofp, fout);
    }
    (void)in_sizes; (void)n_in; (void)out_size;
}

// round 12
// speedup vs baseline: 1.0259x; 1.0166x over previous
#include <cuda_runtime.h>
#include <cuda_bf16.h>
#include <cuda_fp16.h>
#include <math.h>
#include <stdint.h>

#define NN 2048          // nodes
#define NH 8             // heads
#define ALPHA 0.2f
#define NNZ_CAP (2048*128)
#define HID_MAX 512
#define DEG_CAP 1024

// ---------------- scratch (static device allocations) ----------------
__device__ int   g_deg[NN];
__device__ int   g_rowptr[NN + 1];
__device__ int   g_colidx[NNZ_CAP];
__device__ __half g_h[NH * NN * HID_MAX];       // per-head projected features (fp16)
__device__ float g_s1[NH * NN];
__device__ float g_s2[NH * NN];
__device__ __half g_hoh[NN * HID_MAX];          // output-head features (fp16, gather operand)
__device__ float g_o1[NN];
__device__ float g_o2[NN];
__device__ float g_part[8 * NN * 384];          // split-K partials for Wo gemm
// bf16 hi/lo operand buffers (A: activations; B: ALL weights, pre-split once)
__device__ __nv_bfloat16 g_a1[NN * 4096];
__device__ __nv_bfloat16 g_a2[NN * 4096];
__device__ __nv_bfloat16 g_b1[1 << 23];
__device__ __nv_bfloat16 g_b2[1 << 23];

// ---------------- bf16 hi/lo elementwise split ----------------
__device__ __forceinline__ void split4(float4 v, ushort4& uh, ushort4& ul) {
    __nv_bfloat16 h0 = __float2bfloat16_rn(v.x), h1 = __float2bfloat16_rn(v.y);
    __nv_bfloat16 h2 = __float2bfloat16_rn(v.z), h3 = __float2bfloat16_rn(v.w);
    __nv_bfloat16 l0 = __float2bfloat16_rn(v.x - __bfloat162float(h0));
    __nv_bfloat16 l1 = __float2bfloat16_rn(v.y - __bfloat162float(h1));
    __nv_bfloat16 l2 = __float2bfloat16_rn(v.z - __bfloat162float(h2));
    __nv_bfloat16 l3 = __float2bfloat16_rn(v.w - __bfloat162float(h3));
    uh.x = *(unsigned short*)&h0; uh.y = *(unsigned short*)&h1;
    uh.z = *(unsigned short*)&h2; uh.w = *(unsigned short*)&h3;
    ul.x = *(unsigned short*)&l0; ul.y = *(unsigned short*)&l1;
    ul.z = *(unsigned short*)&l2; ul.w = *(unsigned short*)&l3;
}

__global__ void split_bf(const float* __restrict__ in, __nv_bfloat16* __restrict__ o1,
                         __nv_bfloat16* __restrict__ o2, long n4) {
    long i = (long)blockIdx.x * blockDim.x + threadIdx.x;
    if (i >= n4) return;
    ushort4 uh, ul;
    split4(((const float4*)in)[i], uh, ul);
    ((ushort4*)o1)[i] = uh;
    ((ushort4*)o2)[i] = ul;
}

// ---------------- batched weight split ----------------
struct WEnt { const float* src; long off4; long n4; };
struct WTab { WEnt e[12]; };

__global__ void split_bf_batch(WTab tab, __nv_bfloat16* __restrict__ o1,
                               __nv_bfloat16* __restrict__ o2) {
    WEnt en = tab.e[blockIdx.y];
    long i = (long)blockIdx.x * blockDim.x + threadIdx.x;
    if (i >= en.n4) return;
    ushort4 uh, ul;
    split4(((const float4*)en.src)[i], uh, ul);
    ((ushort4*)o1)[en.off4 + i] = uh;
    ((ushort4*)o2)[en.off4 + i] = ul;
}

// ---------------- HMMA bf16x2 GEMM (register-staged, proven R9 version) ----------------
#define A_ST 40
#define B_ST 136
#define A_BYTES (128 * A_ST * 2)
#define B_BYTES (32 * B_ST * 2)
#define BUF_BYTES (2 * A_BYTES + 2 * B_BYTES)
#define GSMEM_BYTES (2 * BUF_BYTES)

__device__ __forceinline__ uint32_t smem_u32(const void* p) {
    uint32_t a;
    asm("{ .reg .u64 t; cvta.to.shared.u64 t, %1; cvt.u32.u64 %0, t; }" : "=r"(a) : "l"(p));
    return a;
}

#define LDMX4(r0, r1, r2, r3, addr) \
    asm volatile("ldmatrix.sync.aligned.m8n8.x4.shared.b16 {%0,%1,%2,%3}, [%4];" \
                 : "=r"(r0), "=r"(r1), "=r"(r2), "=r"(r3) : "r"(addr))
#define LDMX2T(r0, r1, addr) \
    asm volatile("ldmatrix.sync.aligned.m8n8.x2.trans.shared.b16 {%0,%1}, [%2];" \
                 : "=r"(r0), "=r"(r1) : "r"(addr))
#define MMA16816(acc, a, b) \
    asm volatile("mma.sync.aligned.m16n8k16.row.col.f32.bf16.bf16.f32 " \
                 "{%0,%1,%2,%3}, {%4,%5,%6,%7}, {%8,%9}, {%0,%1,%2,%3};" \
                 : "+f"((acc)[0]), "+f"((acc)[1]), "+f"((acc)[2]), "+f"((acc)[3]) \
                 : "r"((a)[0]), "r"((a)[1]), "r"((a)[2]), "r"((a)[3]), \
                   "r"((b)[0]), "r"((b)[1]))

__device__ __forceinline__ void store2(float* p, float x, float y) {
    *(float2*)p = make_float2(x, y);
}
__device__ __forceinline__ void store2(__half* p, float x, float y) {
    *(__half2*)p = __floats2half2_rn(x, y);
}

template <typename OT>
__global__ void __launch_bounds__(256, 1) gemm_mma(
    const __nv_bfloat16* __restrict__ A1, const __nv_bfloat16* __restrict__ A2,
    long lda, long sAz,
    const __nv_bfloat16* __restrict__ B1, const __nv_bfloat16* __restrict__ B2,
    long ldb, long sBz,
    OT* __restrict__ C, long ldc, long sCz, int Kc)
{
    extern __shared__ char sm[];
    int tid = threadIdx.x;
    int wid = tid >> 5, lane = tid & 31;
    int mBase = blockIdx.y * 128;
    int nBase = blockIdx.x * 128;
    int z = blockIdx.z;

    const __nv_bfloat16* a1 = A1 + (long)z * sAz + (size_t)mBase * lda;
    const __nv_bfloat16* a2 = A2 + (long)z * sAz + (size_t)mBase * lda;
    const __nv_bfloat16* b1 = B1 + (long)z * sBz + nBase;
    const __nv_bfloat16* b2 = B2 + (long)z * sBz + nBase;
    OT* c = C + (long)z * sCz;

    float acc[4][4][4];
#pragma unroll
    for (int i = 0; i < 4; i++)
#pragma unroll
        for (int j = 0; j < 4; j++)
#pragma unroll
            for (int r = 0; r < 4; r++) acc[i][j][r] = 0.f;

    int mW = (wid >> 2) * 64;
    int nW = (wid & 3) * 32;
    uint32_t sb = smem_u32(sm);
    uint4 ra1[2], ra2[2], rb1[2], rb2[2];

#pragma unroll
    for (int i = 0; i < 2; i++) {
        int cch = i * 256 + tid;
        int r = cch >> 2, ch = cch & 3;
        ra1[i] = *(const uint4*)((const char*)a1 + (size_t)r * lda * 2 + ch * 16);
        ra2[i] = *(const uint4*)((const char*)a2 + (size_t)r * lda * 2 + ch * 16);
        int rB = cch >> 4, chB = cch & 15;
        rb1[i] = *(const uint4*)((const char*)b1 + (size_t)rB * ldb * 2 + chB * 16);
        rb2[i] = *(const uint4*)((const char*)b2 + (size_t)rB * ldb * 2 + chB * 16);
    }
#pragma unroll
    for (int i = 0; i < 2; i++) {
        int cch = i * 256 + tid;
        int r = cch >> 2, ch = cch & 3;
        *(uint4*)(sm + r * (A_ST * 2) + ch * 16) = ra1[i];
        *(uint4*)(sm + A_BYTES + r * (A_ST * 2) + ch * 16) = ra2[i];
        int rB = cch >> 4, chB = cch & 15;
        *(uint4*)(sm + 2 * A_BYTES + rB * (B_ST * 2) + chB * 16) = rb1[i];
        *(uint4*)(sm + 2 * A_BYTES + B_BYTES + rB * (B_ST * 2) + chB * 16) = rb2[i];
    }
    __syncthreads();

    int nT = Kc >> 5;
    for (int t = 0; t < nT; t++) {
        if (t + 1 < nT) {
#pragma unroll
            for (int i = 0; i < 2; i++) {
                int cch = i * 256 + tid;
                int r = cch >> 2, ch = cch & 3;
                ra1[i] = *(const uint4*)((const char*)a1 + (size_t)r * lda * 2 + (t + 1) * 64 + ch * 16);
                ra2[i] = *(const uint4*)((const char*)a2 + (size_t)r * lda * 2 + (t + 1) * 64 + ch * 16);
                int rB = cch >> 4, chB = cch & 15;
                rb1[i] = *(const uint4*)((const char*)b1 + (size_t)((t + 1) * 32 + rB) * ldb * 2 + chB * 16);
                rb2[i] = *(const uint4*)((const char*)b2 + (size_t)((t + 1) * 32 + rB) * ldb * 2 + chB * 16);
            }
        }
        uint32_t bufb = sb + (uint32_t)(t & 1) * BUF_BYTES;
        uint32_t sA1 = bufb;
        uint32_t sA2 = bufb + A_BYTES;
        uint32_t sB1 = bufb + 2 * A_BYTES;
        uint32_t sB2 = bufb + 2 * A_BYTES + B_BYTES;

#pragma unroll
        for (int kk = 0; kk < 32; kk += 16) {
            uint32_t af[2][4][4];
            uint32_t bfr[2][4][2];
#pragma unroll
            for (int mt = 0; mt < 4; mt++) {
                uint32_t off = (uint32_t)((mW + mt * 16 + (lane & 15)) * (A_ST * 2)
                                          + (kk + ((lane >> 4) << 3)) * 2);
                LDMX4(af[0][mt][0], af[0][mt][1], af[0][mt][2], af[0][mt][3], sA1 + off);
                LDMX4(af[1][mt][0], af[1][mt][1], af[1][mt][2], af[1][mt][3], sA2 + off);
            }
#pragma unroll
            for (int nt = 0; nt < 4; nt++) {
                uint32_t off = (uint32_t)((kk + (lane & 15)) * (B_ST * 2) + (nW + nt * 8) * 2);
                LDMX2T(bfr[0][nt][0], bfr[0][nt][1], sB1 + off);
                LDMX2T(bfr[1][nt][0], bfr[1][nt][1], sB2 + off);
            }
#pragma unroll
            for (int mt = 0; mt < 4; mt++)
#pragma unroll
                for (int nt = 0; nt < 4; nt++) {
                    MMA16816(acc[mt][nt], af[0][mt], bfr[0][nt]);
                    MMA16816(acc[mt][nt], af[0][mt], bfr[1][nt]);
                    MMA16816(acc[mt][nt], af[1][mt], bfr[0][nt]);
                }
        }
        if (t + 1 < nT) {
            char* nb = sm + ((t + 1) & 1) * BUF_BYTES;
#pragma unroll
            for (int i = 0; i < 2; i++) {
                int cch = i * 256 + tid;
                int r = cch >> 2, ch = cch & 3;
                *(uint4*)(nb + r * (A_ST * 2) + ch * 16) = ra1[i];
                *(uint4*)(nb + A_BYTES + r * (A_ST * 2) + ch * 16) = ra2[i];
                int rB = cch >> 4, chB = cch & 15;
                *(uint4*)(nb + 2 * A_BYTES + rB * (B_ST * 2) + chB * 16) = rb1[i];
                *(uint4*)(nb + 2 * A_BYTES + B_BYTES + rB * (B_ST * 2) + chB * 16) = rb2[i];
            }
            __syncthreads();
        }
    }

#pragma unroll
    for (int mt = 0; mt < 4; mt++) {
        int row0 = mBase + mW + mt * 16 + (lane >> 2);
#pragma unroll
        for (int nt = 0; nt < 4; nt++) {
            int col = nBase + nW + nt * 8 + (lane & 3) * 2;
            OT* cr = c + (size_t)row0 * ldc + col;
            store2(cr, acc[mt][nt][0], acc[mt][nt][1]);
            store2(cr + 8 * ldc, acc[mt][nt][2], acc[mt][nt][3]);
        }
    }
}

// ---------------- CSR build ----------------
__global__ void csr_count(const float* __restrict__ adj, int* __restrict__ deg) {
    int row = blockIdx.x * (blockDim.x >> 5) + (threadIdx.x >> 5);
    if (row >= NN) return;
    int lane = threadIdx.x & 31;
    const float* r = adj + (size_t)row * NN;
    int cnt = 0;
    for (int c0 = 0; c0 < NN; c0 += 32) {
        float v = r[c0 + lane];
        unsigned m = __ballot_sync(0xffffffffu, v > 0.f);
        cnt += __popc(m);
    }
    if (lane == 0) deg[row] = cnt;
}

__global__ void csr_scan(const int* __restrict__ deg, int* __restrict__ rowptr) {
    __shared__ int s[1024];
    int t = threadIdx.x;
    int d0 = deg[2 * t], d1 = deg[2 * t + 1];
    s[t] = d0 + d1;
    __syncthreads();
    for (int off = 1; off < 1024; off <<= 1) {
        int v = s[t];
        int add = (t >= off) ? s[t - off] : 0;
        __syncthreads();
        s[t] = v + add;
        __syncthreads();
    }
    int excl = (t > 0) ? s[t - 1] : 0;
    rowptr[2 * t]     = excl;
    rowptr[2 * t + 1] = excl + d0;
    if (t == 1023) rowptr[NN] = s[1023];
}

__global__ void csr_fill(const float* __restrict__ adj, const int* __restrict__ rowptr,
                         int* __restrict__ colidx) {
    int row = blockIdx.x * (blockDim.x >> 5) + (threadIdx.x >> 5);
    if (row >= NN) return;
    int lane = threadIdx.x & 31;
    const float* r = adj + (size_t)row * NN;
    int pos = rowptr[row];
    for (int c0 = 0; c0 < NN; c0 += 32) {
        float v = r[c0 + lane];
        unsigned m = __ballot_sync(0xffffffffu, v > 0.f);
        if (v > 0.f) {
            int off = __popc(m & ((1u << lane) - 1u));
            colidx[pos + off] = c0 + lane;
        }
        pos += __popc(m);
    }
}

// ---------------- s1/s2 dot products (half h) ----------------
__global__ void dot_s_h(const __half* __restrict__ h, const float* __restrict__ a,
                        float* __restrict__ s1, float* __restrict__ s2, int hid, int total) {
    int w = (blockIdx.x * blockDim.x + threadIdx.x) >> 5;
    if (w >= total) return;
    int lane = threadIdx.x & 31;
    int head = w / NN;
    const __half2* hp = (const __half2*)(h + (size_t)w * hid);
    const float* a1 = a + (size_t)head * 2 * hid;
    const float* a2 = a1 + hid;
    int hw = hid >> 1;
    float v1 = 0.f, v2 = 0.f;
    for (int d = lane; d < hw; d += 32) {
        float2 x = __half22float2(hp[d]);
        float2 w1 = *(const float2*)&a1[2 * d];
        float2 w2 = *(const float2*)&a2[2 * d];
        v1 += x.x * w1.x + x.y * w1.y;
        v2 += x.x * w2.x + x.y * w2.y;
    }
#pragma unroll
    for (int o = 16; o; o >>= 1) {
        v1 += __shfl_xor_sync(0xffffffffu, v1, o);
        v2 += __shfl_xor_sync(0xffffffffu, v2, o);
    }
    if (lane == 0) { s1[w] = v1; s2[w] = v2; }
}

// ---------------- fused split-K reduce + o1/o2 dot (block per node, float4) ----------------
__global__ void reduce_dot(const float* __restrict__ part, const float* __restrict__ ao,
                           __half* __restrict__ hoh, float* __restrict__ o1,
                           float* __restrict__ o2, int fout, int ks) {
    __shared__ float rbuf[8];
    int i = blockIdx.x;
    int tid = threadIdx.x;                  // 128
    int wid = tid >> 5, lane = tid & 31;
    int f4 = fout >> 2;                     // 32..96
    size_t MN4 = (size_t)NN * f4;
    float v1 = 0.f, v2 = 0.f;
    if (tid < f4) {
        size_t idx4 = (size_t)i * f4 + tid;
        float4 s = make_float4(0.f, 0.f, 0.f, 0.f);
        const float4* p4 = (const float4*)part;
        for (int p = 0; p < ks; p++) {
            float4 v = p4[(size_t)p * MN4 + idx4];
            s.x += v.x; s.y += v.y; s.z += v.z; s.w += v.w;
        }
        __half2 h0 = __floats2half2_rn(s.x, s.y);
        __half2 h1 = __floats2half2_rn(s.z, s.w);
        uint2 hv;
        hv.x = *(uint32_t*)&h0; hv.y = *(uint32_t*)&h1;
        *(uint2*)(hoh + (size_t)i * fout + 4 * tid) = hv;
        float4 w1 = *(const float4*)&ao[4 * tid];
        float4 w2 = *(const float4*)&ao[fout + 4 * tid];
        v1 = s.x * w1.x + s.y * w1.y + s.z * w1.z + s.w * w1.w;
        v2 = s.x * w2.x + s.y * w2.y + s.z * w2.z + s.w * w2.w;
    }
#pragma unroll
    for (int o = 16; o; o >>= 1) {
        v1 += __shfl_xor_sync(0xffffffffu, v1, o);
        v2 += __shfl_xor_sync(0xffffffffu, v2, o);
    }
    if (lane == 0) { rbuf[wid] = v1; rbuf[4 + wid] = v2; }
    __syncthreads();
    if (tid == 0) {
        o1[i] = rbuf[0] + rbuf[1] + rbuf[2] + rbuf[3];
        o2[i] = rbuf[4] + rbuf[5] + rbuf[6] + rbuf[7];
    }
}

// ---------------- helpers ----------------
__device__ __forceinline__ float elu1(float x) { return x > 0.f ? x : expm1f(x); }

__device__ __forceinline__ ushort4 bf_hi4(float a, float b, float c, float d,
                                          float& ra, float& rb, float& rc, float& rd) {
    __nv_bfloat16 ha = __float2bfloat16_rn(a), hb = __float2bfloat16_rn(b);
    __nv_bfloat16 hc = __float2bfloat16_rn(c), hd = __float2bfloat16_rn(d);
    ra = a - __bfloat162float(ha); rb = b - __bfloat162float(hb);
    rc = c - __bfloat162float(hc); rd = d - __bfloat162float(hd);
    ushort4 u;
    u.x = *(unsigned short*)&ha; u.y = *(unsigned short*)&hb;
    u.z = *(unsigned short*)&hc; u.w = *(unsigned short*)&hd;
    return u;
}
__device__ __forceinline__ ushort4 bf_lo4(float a, float b, float c, float d) {
    __nv_bfloat16 la = __float2bfloat16_rn(a), lb = __float2bfloat16_rn(b);
    __nv_bfloat16 lc = __float2bfloat16_rn(c), ld = __float2bfloat16_rn(d);
    ushort4 u;
    u.x = *(unsigned short*)&la; u.y = *(unsigned short*)&lb;
    u.z = *(unsigned short*)&lc; u.w = *(unsigned short*)&ld;
    return u;
}
__device__ __forceinline__ void write_bf_quad(__nv_bfloat16* o1, __nv_bfloat16* o2,
                                              size_t idx, float a, float b, float c, float d) {
    float ra, rb, rc, rd;
    *(ushort4*)(o1 + idx) = bf_hi4(a, b, c, d, ra, rb, rc, rd);
    *(ushort4*)(o2 + idx) = bf_lo4(ra, rb, rc, rd);
}

// block softmax over neighbor list. 128 threads.
__device__ __forceinline__ int block_softmax(const int* __restrict__ rowptr,
                                             const int* __restrict__ colidx,
                                             float si, const float* __restrict__ s2,
                                             int i, float* ex, int* cj, float& inv) {
    __shared__ float rbuf[8];
    int tid = threadIdx.x;
    int wid = tid >> 5, lane = tid & 31;
    int b = rowptr[i];
    int d = rowptr[i + 1] - b;
    if (d > DEG_CAP) d = DEG_CAP;
    float lm = -1e30f;
    for (int k = tid; k < d; k += 128) {
        int j = colidx[b + k];
        cj[k] = j;
        float v = si + s2[j];
        v = v > 0.f ? v : ALPHA * v;
        ex[k] = v;
        lm = fmaxf(lm, v);
    }
#pragma unroll
    for (int o = 16; o; o >>= 1) lm = fmaxf(lm, __shfl_xor_sync(0xffffffffu, lm, o));
    if (lane == 0) rbuf[wid] = lm;
    __syncthreads();
    float m = fmaxf(fmaxf(rbuf[0], rbuf[1]), fmaxf(rbuf[2], rbuf[3]));
    float ls = 0.f;
    for (int k = tid; k < d; k += 128) {
        float t = expf(ex[k] - m);
        ex[k] = t;
        ls += t;
    }
#pragma unroll
    for (int o = 16; o; o >>= 1) ls += __shfl_xor_sync(0xffffffffu, ls, o);
    if (lane == 0) rbuf[4 + wid] = ls;
    __syncthreads();
    inv = 1.f / (rbuf[4] + rbuf[5] + rbuf[6] + rbuf[7]);
    return d;
}

__device__ __forceinline__ void unpack_h4(uint2 v, float& a, float& b, float& c, float& d) {
    float2 p0 = __half22float2(*(__half2*)&v.x);
    float2 p1 = __half22float2(*(__half2*)&v.y);
    a = p0.x; b = p0.y; c = p1.x; d = p1.y;
}

// ---------------- fused head softmax + SpMM: hcat = elu(softmax @ h) ----------------
// 8B-vectorized gather: thread covers 4 half values; hid/4 <= 128. (proven R9 form)
__global__ void spmm_h_fused(const int* __restrict__ rowptr, const int* __restrict__ colidx,
                             const float* __restrict__ s1, const float* __restrict__ s2,
                             const __half* __restrict__ h,
                             __nv_bfloat16* __restrict__ o1, __nv_bfloat16* __restrict__ o2,
                             int hid, int out_stride) {
    __shared__ float ex[DEG_CAP];
    __shared__ int cj[DEG_CAP];
    int i = blockIdx.x, head = blockIdx.y;
    int tid = threadIdx.x;                    // 128
    float inv;
    int d = block_softmax(rowptr, colidx, s1[(size_t)head * NN + i],
                          s2 + (size_t)head * NN, i, ex, cj, inv);
    int pos = hid >> 2;                       // uint2 chunks per row (32..128)
    if (tid >= pos) return;
    const uint2* hb = (const uint2*)(h + (size_t)head * NN * hid);
    float x0 = 0.f, x1 = 0.f, x2 = 0.f, x3 = 0.f;
#pragma unroll 8
    for (int k = 0; k < d; k++) {
        float a = ex[k];
        float v0, v1, v2, v3;
        unpack_h4(hb[(size_t)cj[k] * pos + tid], v0, v1, v2, v3);
        x0 += a * v0; x1 += a * v1; x2 += a * v2; x3 += a * v3;
    }
    size_t base = (size_t)i * out_stride + (size_t)head * hid + 4 * tid;
    write_bf_quad(o1, o2, base, elu1(x0 * inv), elu1(x1 * inv), elu1(x2 * inv), elu1(x3 * inv));
}

// ---------------- fused output softmax + SpMM: x' = elu(softmax @ ho_fp16) ----------------
__global__ void spmm_out_fused(const int* __restrict__ rowptr, const int* __restrict__ colidx,
                               const float* __restrict__ s1, const float* __restrict__ s2,
                               const __half* __restrict__ hoh,
                               __nv_bfloat16* __restrict__ o1, __nv_bfloat16* __restrict__ o2,
                               float* __restrict__ ofp, int hid) {
    __shared__ float ex[DEG_CAP];
    __shared__ int cj[DEG_CAP];
    int i = blockIdx.x;
    int tid = threadIdx.x;                    // 128
    float inv;
    int d = block_softmax(rowptr, colidx, s1[i], s2, i, ex, cj, inv);
    int pos = hid >> 2;                       // 32..96
    if (tid >= pos) return;
    const uint2* hb = (const uint2*)hoh;
    float x0 = 0.f, x1 = 0.f, x2 = 0.f, x3 = 0.f;
#pragma unroll 8
    for (int k = 0; k < d; k++) {
        float a = ex[k];
        float v0, v1, v2, v3;
        unpack_h4(hb[(size_t)cj[k] * pos + tid], v0, v1, v2, v3);
        x0 += a * v0; x1 += a * v1; x2 += a * v2; x3 += a * v3;
    }
    float e0 = elu1(x0 * inv), e1 = elu1(x1 * inv), e2 = elu1(x2 * inv), e3 = elu1(x3 * inv);
    size_t base = (size_t)i * hid + 4 * tid;
    if (ofp) *(float4*)(ofp + base) = make_float4(e0, e1, e2, e3);
    else     write_bf_quad(o1, o2, base, e0, e1, e2, e3);
}

// ---------------- host side ----------------
struct LayerDims { int fin, hid, fout; };
static const LayerDims g_dims[6] = {
    {256, 128, 128}, {128, 256, 256}, {256, 512, 384},
    {384, 512, 256}, {256, 256, 128}, {128, 128, 256}
};

extern "C" void kernel_launch(void* const* d_in, const int* in_sizes, int n_in,
                              void* d_out, int out_size) {
    const float* x   = (const float*)d_in[0];
    const float* adj = (const float*)d_in[1];

    float *p_s1, *p_s2, *p_o1v, *p_o2v, *p_part;
    int *p_deg, *p_rowptr, *p_colidx;
    __half *p_h, *p_hoh;
    __nv_bfloat16 *p_a1, *p_a2, *p_b1, *p_b2;
    cudaGetSymbolAddress((void**)&p_deg, g_deg);
    cudaGetSymbolAddress((void**)&p_rowptr, g_rowptr);
    cudaGetSymbolAddress((void**)&p_colidx, g_colidx);
    cudaGetSymbolAddress((void**)&p_h, g_h);
    cudaGetSymbolAddress((void**)&p_s1, g_s1);
    cudaGetSymbolAddress((void**)&p_s2, g_s2);
    cudaGetSymbolAddress((void**)&p_hoh, g_hoh);
    cudaGetSymbolAddress((void**)&p_o1v, g_o1);
    cudaGetSymbolAddress((void**)&p_o2v, g_o2);
    cudaGetSymbolAddress((void**)&p_part, g_part);
    cudaGetSymbolAddress((void**)&p_a1, g_a1);
    cudaGetSymbolAddress((void**)&p_a2, g_a2);
    cudaGetSymbolAddress((void**)&p_b1, g_b1);
    cudaGetSymbolAddress((void**)&p_b2, g_b2);

    static int smem_set = 0;
    if (!smem_set) {
        cudaFuncSetAttribute(gemm_mma<float>, cudaFuncAttributeMaxDynamicSharedMemorySize, GSMEM_BYTES);
        cudaFuncSetAttribute(gemm_mma<__half>, cudaFuncAttributeMaxDynamicSharedMemorySize, GSMEM_BYTES);
        smem_set = 1;
    }

    // weight table: offsets into g_b1/g_b2 (elements), hi/lo split once upfront
    long whoff[6], wooff[6];
    WTab tab;
    long cur = 0, maxN4 = 0;
    for (int l = 0; l < 6; l++) {
        int fin = g_dims[l].fin, hid = g_dims[l].hid, fout = g_dims[l].fout;
        long nWh = (long)NH * fin * hid;
        long nWo = (long)NH * hid * fout;
        whoff[l] = cur;
        tab.e[2 * l] = { (const float*)d_in[2 + 4 * l], cur / 4, nWh / 4 };
        cur += nWh;
        wooff[l] = cur;
        tab.e[2 * l + 1] = { (const float*)d_in[4 + 4 * l], cur / 4, nWo / 4 };
        cur += nWo;
        if (nWh / 4 > maxN4) maxN4 = nWh / 4;
        if (nWo / 4 > maxN4) maxN4 = nWo / 4;
    }

    // Build CSR of adjacency
    csr_count<<<NN / 8, 256>>>(adj, p_deg);
    csr_scan<<<1, 1024>>>(p_deg, p_rowptr);
    csr_fill<<<NN / 8, 256>>>(adj, p_rowptr, p_colidx);

    // all weights split in one launch; layer-0 x split
    split_bf_batch<<<dim3((unsigned)((maxN4 + 255) / 256), 12), 256>>>(tab, p_b1, p_b2);
    split_bf<<<(NN * 256 / 4 + 255) / 256, 256>>>(x, p_a1, p_a2, NN * 256 / 4);

    for (int l = 0; l < 6; l++) {
        int fin = g_dims[l].fin, hid = g_dims[l].hid, fout = g_dims[l].fout;
        const float* ah = (const float*)d_in[3 + 4 * l];
        const float* ao = (const float*)d_in[5 + 4 * l];

        // ---- head GEMM: h[head] = x @ Wh[head], fp16 output ----
        gemm_mma<__half><<<dim3(hid / 128, NN / 128, NH), 256, GSMEM_BYTES>>>(
            p_a1, p_a2, fin, 0L,
            p_b1 + whoff[l], p_b2 + whoff[l], hid, (long)fin * hid,
            p_h, hid, (long)NN * hid, fin);

        // s1/s2, fused softmax+SpMM (writes hcat bf16 hi/lo -> Wo A operands)
        int totalHN = NH * NN;
        dot_s_h<<<(totalHN * 32 + 255) / 256, 256>>>(p_h, ah, p_s1, p_s2, hid, totalHN);
        spmm_h_fused<<<dim3(NN, NH), 128>>>(p_rowptr, p_colidx, p_s1, p_s2, p_h,
                                            p_a1, p_a2, hid, NH * hid);

        // ---- output GEMM: ho = hcat @ Wo, adaptive split-K, fused reduce+dot ----
        int Ktot = NH * hid;
        int ks = (fout >= 256) ? 4 : 8;
        int Kc = Ktot / ks;
        gemm_mma<float><<<dim3(fout / 128, NN / 128, ks), 256, GSMEM_BYTES>>>(
            p_a1, p_a2, Ktot, (long)Kc,
            p_b1 + wooff[l], p_b2 + wooff[l], fout, (long)Kc * fout,
            p_part, fout, (long)NN * fout, Kc);
        reduce_dot<<<NN, 128>>>(p_part, ao, p_hoh, p_o1v, p_o2v, fout, ks);

        // fused output softmax + SpMM; fp32 d_out at layer 5, else bf16 hi/lo A
        float* ofp = (l == 5) ? (float*)d_out : nullptr;
        spmm_out_fused<<<NN, 128>>>(p_rowptr, p_colidx, p_o1v, p_o2v, p_hoh,
                                    p_a1, p_a2, ofp, fout);
    }
    (void)in_sizes; (void)n_in; (void)out_size;
}

// round 14
// speedup vs baseline: 1.0499x; 1.0233x over previous
#include <cuda_runtime.h>
#include <cuda_bf16.h>
#include <cuda_fp16.h>
#include <math.h>
#include <stdint.h>

#define NN 2048          // nodes
#define NH 8             // heads
#define ALPHA 0.2f
#define NNZ_CAP (2048*128)
#define HID_MAX 512
#define DEG_CAP 1024

// ---------------- scratch (static device allocations) ----------------
__device__ int   g_deg[NN];
__device__ int   g_rowptr[NN + 1];
__device__ int   g_colidx[NNZ_CAP];
__device__ __half g_h[NH * NN * HID_MAX];       // per-head projected features (fp16)
__device__ float g_s1[NH * NN];
__device__ float g_s2[NH * NN];
__device__ float g_sp1[NH * 4 * NN];            // per-x-block s1 partials from gemm epilogue
__device__ float g_sp2[NH * 4 * NN];
__device__ __half g_hoh[NN * HID_MAX];          // output-head features (fp16, gather operand)
__device__ float g_o1[NN];
__device__ float g_o2[NN];
__device__ float g_part[8 * NN * 384];          // split-K partials for Wo gemm
// bf16 hi/lo operand buffers (A: activations; B: ALL weights, pre-split once)
__device__ __nv_bfloat16 g_a1[NN * 4096];
__device__ __nv_bfloat16 g_a2[NN * 4096];
__device__ __nv_bfloat16 g_b1[1 << 23];
__device__ __nv_bfloat16 g_b2[1 << 23];

// ---------------- bf16 hi/lo elementwise split ----------------
__device__ __forceinline__ void split4(float4 v, ushort4& uh, ushort4& ul) {
    __nv_bfloat16 h0 = __float2bfloat16_rn(v.x), h1 = __float2bfloat16_rn(v.y);
    __nv_bfloat16 h2 = __float2bfloat16_rn(v.z), h3 = __float2bfloat16_rn(v.w);
    __nv_bfloat16 l0 = __float2bfloat16_rn(v.x - __bfloat162float(h0));
    __nv_bfloat16 l1 = __float2bfloat16_rn(v.y - __bfloat162float(h1));
    __nv_bfloat16 l2 = __float2bfloat16_rn(v.z - __bfloat162float(h2));
    __nv_bfloat16 l3 = __float2bfloat16_rn(v.w - __bfloat162float(h3));
    uh.x = *(unsigned short*)&h0; uh.y = *(unsigned short*)&h1;
    uh.z = *(unsigned short*)&h2; uh.w = *(unsigned short*)&h3;
    ul.x = *(unsigned short*)&l0; ul.y = *(unsigned short*)&l1;
    ul.z = *(unsigned short*)&l2; ul.w = *(unsigned short*)&l3;
}

__global__ void split_bf(const float* __restrict__ in, __nv_bfloat16* __restrict__ o1,
                         __nv_bfloat16* __restrict__ o2, long n4) {
    long i = (long)blockIdx.x * blockDim.x + threadIdx.x;
    if (i >= n4) return;
    ushort4 uh, ul;
    split4(((const float4*)in)[i], uh, ul);
    ((ushort4*)o1)[i] = uh;
    ((ushort4*)o2)[i] = ul;
}

// ---------------- batched weight split ----------------
struct WEnt { const float* src; long off4; long n4; };
struct WTab { WEnt e[12]; };

__global__ void split_bf_batch(WTab tab, __nv_bfloat16* __restrict__ o1,
                               __nv_bfloat16* __restrict__ o2) {
    WEnt en = tab.e[blockIdx.y];
    long i = (long)blockIdx.x * blockDim.x + threadIdx.x;
    if (i >= en.n4) return;
    ushort4 uh, ul;
    split4(((const float4*)en.src)[i], uh, ul);
    ((ushort4*)o1)[en.off4 + i] = uh;
    ((ushort4*)o2)[en.off4 + i] = ul;
}

// ---------------- HMMA bf16x2 GEMM (register-staged) + optional s-dot epilogue ----------------
#define A_ST 40
#define B_ST 136
#define A_BYTES (128 * A_ST * 2)
#define B_BYTES (32 * B_ST * 2)
#define BUF_BYTES (2 * A_BYTES + 2 * B_BYTES)
#define GSMEM_BYTES (2 * BUF_BYTES)

__device__ __forceinline__ uint32_t smem_u32(const void* p) {
    uint32_t a;
    asm("{ .reg .u64 t; cvta.to.shared.u64 t, %1; cvt.u32.u64 %0, t; }" : "=r"(a) : "l"(p));
    return a;
}

#define LDMX4(r0, r1, r2, r3, addr) \
    asm volatile("ldmatrix.sync.aligned.m8n8.x4.shared.b16 {%0,%1,%2,%3}, [%4];" \
                 : "=r"(r0), "=r"(r1), "=r"(r2), "=r"(r3) : "r"(addr))
#define LDMX2T(r0, r1, addr) \
    asm volatile("ldmatrix.sync.aligned.m8n8.x2.trans.shared.b16 {%0,%1}, [%2];" \
                 : "=r"(r0), "=r"(r1) : "r"(addr))
#define MMA16816(acc, a, b) \
    asm volatile("mma.sync.aligned.m16n8k16.row.col.f32.bf16.bf16.f32 " \
                 "{%0,%1,%2,%3}, {%4,%5,%6,%7}, {%8,%9}, {%0,%1,%2,%3};" \
                 : "+f"((acc)[0]), "+f"((acc)[1]), "+f"((acc)[2]), "+f"((acc)[3]) \
                 : "r"((a)[0]), "r"((a)[1]), "r"((a)[2]), "r"((a)[3]), \
                   "r"((b)[0]), "r"((b)[1]))

__device__ __forceinline__ void store2(float* p, float x, float y) {
    *(float2*)p = make_float2(x, y);
}
__device__ __forceinline__ void store2(__half* p, float x, float y) {
    *(__half2*)p = __floats2half2_rn(x, y);
}

template <typename OT>
__global__ void __launch_bounds__(256, 1) gemm_mma(
    const __nv_bfloat16* __restrict__ A1, const __nv_bfloat16* __restrict__ A2,
    long lda, long sAz,
    const __nv_bfloat16* __restrict__ B1, const __nv_bfloat16* __restrict__ B2,
    long ldb, long sBz,
    OT* __restrict__ C, long ldc, long sCz, int Kc,
    const float* __restrict__ AH, float* __restrict__ sp1, float* __restrict__ sp2)
{
    extern __shared__ char sm[];
    int tid = threadIdx.x;
    int wid = tid >> 5, lane = tid & 31;
    int mBase = blockIdx.y * 128;
    int nBase = blockIdx.x * 128;
    int z = blockIdx.z;

    const __nv_bfloat16* a1 = A1 + (long)z * sAz + (size_t)mBase * lda;
    const __nv_bfloat16* a2 = A2 + (long)z * sAz + (size_t)mBase * lda;
    const __nv_bfloat16* b1 = B1 + (long)z * sBz + nBase;
    const __nv_bfloat16* b2 = B2 + (long)z * sBz + nBase;
    OT* c = C + (long)z * sCz;

    float acc[4][4][4];
#pragma unroll
    for (int i = 0; i < 4; i++)
#pragma unroll
        for (int j = 0; j < 4; j++)
#pragma unroll
            for (int r = 0; r < 4; r++) acc[i][j][r] = 0.f;

    int mW = (wid >> 2) * 64;
    int nW = (wid & 3) * 32;
    uint32_t sb = smem_u32(sm);
    uint4 ra1[2], ra2[2], rb1[2], rb2[2];

#pragma unroll
    for (int i = 0; i < 2; i++) {
        int cch = i * 256 + tid;
        int r = cch >> 2, ch = cch & 3;
        ra1[i] = *(const uint4*)((const char*)a1 + (size_t)r * lda * 2 + ch * 16);
        ra2[i] = *(const uint4*)((const char*)a2 + (size_t)r * lda * 2 + ch * 16);
        int rB = cch >> 4, chB = cch & 15;
        rb1[i] = *(const uint4*)((const char*)b1 + (size_t)rB * ldb * 2 + chB * 16);
        rb2[i] = *(const uint4*)((const char*)b2 + (size_t)rB * ldb * 2 + chB * 16);
    }
#pragma unroll
    for (int i = 0; i < 2; i++) {
        int cch = i * 256 + tid;
        int r = cch >> 2, ch = cch & 3;
        *(uint4*)(sm + r * (A_ST * 2) + ch * 16) = ra1[i];
        *(uint4*)(sm + A_BYTES + r * (A_ST * 2) + ch * 16) = ra2[i];
        int rB = cch >> 4, chB = cch & 15;
        *(uint4*)(sm + 2 * A_BYTES + rB * (B_ST * 2) + chB * 16) = rb1[i];
        *(uint4*)(sm + 2 * A_BYTES + B_BYTES + rB * (B_ST * 2) + chB * 16) = rb2[i];
    }
    __syncthreads();

    int nT = Kc >> 5;
    for (int t = 0; t < nT; t++) {
        if (t + 1 < nT) {
#pragma unroll
            for (int i = 0; i < 2; i++) {
                int cch = i * 256 + tid;
                int r = cch >> 2, ch = cch & 3;
                ra1[i] = *(const uint4*)((const char*)a1 + (size_t)r * lda * 2 + (t + 1) * 64 + ch * 16);
                ra2[i] = *(const uint4*)((const char*)a2 + (size_t)r * lda * 2 + (t + 1) * 64 + ch * 16);
                int rB = cch >> 4, chB = cch & 15;
                rb1[i] = *(const uint4*)((const char*)b1 + (size_t)((t + 1) * 32 + rB) * ldb * 2 + chB * 16);
                rb2[i] = *(const uint4*)((const char*)b2 + (size_t)((t + 1) * 32 + rB) * ldb * 2 + chB * 16);
            }
        }
        uint32_t bufb = sb + (uint32_t)(t & 1) * BUF_BYTES;
        uint32_t sA1 = bufb;
        uint32_t sA2 = bufb + A_BYTES;
        uint32_t sB1 = bufb + 2 * A_BYTES;
        uint32_t sB2 = bufb + 2 * A_BYTES + B_BYTES;

#pragma unroll
        for (int kk = 0; kk < 32; kk += 16) {
            uint32_t af[2][4][4];
            uint32_t bfr[2][4][2];
#pragma unroll
            for (int mt = 0; mt < 4; mt++) {
                uint32_t off = (uint32_t)((mW + mt * 16 + (lane & 15)) * (A_ST * 2)
                                          + (kk + ((lane >> 4) << 3)) * 2);
                LDMX4(af[0][mt][0], af[0][mt][1], af[0][mt][2], af[0][mt][3], sA1 + off);
                LDMX4(af[1][mt][0], af[1][mt][1], af[1][mt][2], af[1][mt][3], sA2 + off);
            }
#pragma unroll
            for (int nt = 0; nt < 4; nt++) {
                uint32_t off = (uint32_t)((kk + (lane & 15)) * (B_ST * 2) + (nW + nt * 8) * 2);
                LDMX2T(bfr[0][nt][0], bfr[0][nt][1], sB1 + off);
                LDMX2T(bfr[1][nt][0], bfr[1][nt][1], sB2 + off);
            }
#pragma unroll
            for (int mt = 0; mt < 4; mt++)
#pragma unroll
                for (int nt = 0; nt < 4; nt++) {
                    MMA16816(acc[mt][nt], af[0][mt], bfr[0][nt]);
                    MMA16816(acc[mt][nt], af[0][mt], bfr[1][nt]);
                    MMA16816(acc[mt][nt], af[1][mt], bfr[0][nt]);
                }
        }
        if (t + 1 < nT) {
            char* nb = sm + ((t + 1) & 1) * BUF_BYTES;
#pragma unroll
            for (int i = 0; i < 2; i++) {
                int cch = i * 256 + tid;
                int r = cch >> 2, ch = cch & 3;
                *(uint4*)(nb + r * (A_ST * 2) + ch * 16) = ra1[i];
                *(uint4*)(nb + A_BYTES + r * (A_ST * 2) + ch * 16) = ra2[i];
                int rB = cch >> 4, chB = cch & 15;
                *(uint4*)(nb + 2 * A_BYTES + rB * (B_ST * 2) + chB * 16) = rb1[i];
                *(uint4*)(nb + 2 * A_BYTES + B_BYTES + rB * (B_ST * 2) + chB * 16) = rb2[i];
            }
            __syncthreads();
        }
    }

    // C writes
#pragma unroll
    for (int mt = 0; mt < 4; mt++) {
        int row0 = mBase + mW + mt * 16 + (lane >> 2);
#pragma unroll
        for (int nt = 0; nt < 4; nt++) {
            int col = nBase + nW + nt * 8 + (lane & 3) * 2;
            OT* cr = c + (size_t)row0 * ldc + col;
            store2(cr, acc[mt][nt][0], acc[mt][nt][1]);
            store2(cr + 8 * ldc, acc[mt][nt][2], acc[mt][nt][3]);
        }
    }

    // s1/s2 partial dots from fp32 accumulators (head gemm only)
    if (AH != nullptr) {
        const float* ah1 = AH + (size_t)z * 2 * ldc;   // ldc == hid for head gemm
        const float* ah2 = ah1 + ldc;
        float w1v[4][2], w2v[4][2];
#pragma unroll
        for (int nt = 0; nt < 4; nt++) {
            int col = nBase + nW + nt * 8 + (lane & 3) * 2;
            w1v[nt][0] = ah1[col]; w1v[nt][1] = ah1[col + 1];
            w2v[nt][0] = ah2[col]; w2v[nt][1] = ah2[col + 1];
        }
        float p1[4][2], p2[4][2];
#pragma unroll
        for (int mt = 0; mt < 4; mt++) {
            float a1lo = 0.f, a1hi = 0.f, a2lo = 0.f, a2hi = 0.f;
#pragma unroll
            for (int nt = 0; nt < 4; nt++) {
                a1lo += acc[mt][nt][0] * w1v[nt][0] + acc[mt][nt][1] * w1v[nt][1];
                a1hi += acc[mt][nt][2] * w1v[nt][0] + acc[mt][nt][3] * w1v[nt][1];
                a2lo += acc[mt][nt][0] * w2v[nt][0] + acc[mt][nt][1] * w2v[nt][1];
                a2hi += acc[mt][nt][2] * w2v[nt][0] + acc[mt][nt][3] * w2v[nt][1];
            }
            p1[mt][0] = a1lo; p1[mt][1] = a1hi;
            p2[mt][0] = a2lo; p2[mt][1] = a2hi;
        }
#pragma unroll
        for (int o = 1; o <= 2; o <<= 1) {
#pragma unroll
            for (int mt = 0; mt < 4; mt++) {
                p1[mt][0] += __shfl_xor_sync(0xffffffffu, p1[mt][0], o);
                p1[mt][1] += __shfl_xor_sync(0xffffffffu, p1[mt][1], o);
                p2[mt][0] += __shfl_xor_sync(0xffffffffu, p2[mt][0], o);
                p2[mt][1] += __shfl_xor_sync(0xffffffffu, p2[mt][1], o);
            }
        }
        float* sbuf = (float*)sm;   // [4 nwarp][128 row][2 (s1,s2)] = 4 KB
        __syncthreads();
        if ((lane & 3) == 0) {
            int nw = wid & 3;
#pragma unroll
            for (int mt = 0; mt < 4; mt++) {
                int r0 = mW + mt * 16 + (lane >> 2);
                sbuf[(nw * 128 + r0) * 2 + 0] = p1[mt][0];
                sbuf[(nw * 128 + r0) * 2 + 1] = p2[mt][0];
                sbuf[(nw * 128 + r0 + 8) * 2 + 0] = p1[mt][1];
                sbuf[(nw * 128 + r0 + 8) * 2 + 1] = p2[mt][1];
            }
        }
        __syncthreads();
        int row = tid >> 1, which = tid & 1;
        float s = sbuf[(0 * 128 + row) * 2 + which] + sbuf[(1 * 128 + row) * 2 + which]
                + sbuf[(2 * 128 + row) * 2 + which] + sbuf[(3 * 128 + row) * 2 + which];
        float* sp = which ? sp2 : sp1;
        sp[((size_t)z * 4 + blockIdx.x) * NN + mBase + row] = s;
    }
}

// combine per-x-block s partials -> s1/s2
__global__ void combine_s(const float* __restrict__ sp1, const float* __restrict__ sp2,
                          float* __restrict__ s1, float* __restrict__ s2, int nbx) {
    int idx = blockIdx.x * blockDim.x + threadIdx.x;
    if (idx >= NH * NN) return;
    int z = idx / NN, n = idx - z * NN;
    float a = 0.f, b = 0.f;
    for (int bx = 0; bx < nbx; bx++) {
        a += sp1[((size_t)z * 4 + bx) * NN + n];
        b += sp2[((size_t)z * 4 + bx) * NN + n];
    }
    s1[idx] = a;
    s2[idx] = b;
}

// ---------------- CSR build ----------------
__global__ void csr_count(const float* __restrict__ adj, int* __restrict__ deg) {
    int row = blockIdx.x * (blockDim.x >> 5) + (threadIdx.x >> 5);
    if (row >= NN) return;
    int lane = threadIdx.x & 31;
    const float* r = adj + (size_t)row * NN;
    int cnt = 0;
    for (int c0 = 0; c0 < NN; c0 += 32) {
        float v = r[c0 + lane];
        unsigned m = __ballot_sync(0xffffffffu, v > 0.f);
        cnt += __popc(m);
    }
    if (lane == 0) deg[row] = cnt;
}

__global__ void csr_scan(const int* __restrict__ deg, int* __restrict__ rowptr) {
    __shared__ int s[1024];
    int t = threadIdx.x;
    int d0 = deg[2 * t], d1 = deg[2 * t + 1];
    s[t] = d0 + d1;
    __syncthreads();
    for (int off = 1; off < 1024; off <<= 1) {
        int v = s[t];
        int add = (t >= off) ? s[t - off] : 0;
        __syncthreads();
        s[t] = v + add;
        __syncthreads();
    }
    int excl = (t > 0) ? s[t - 1] : 0;
    rowptr[2 * t]     = excl;
    rowptr[2 * t + 1] = excl + d0;
    if (t == 1023) rowptr[NN] = s[1023];
}

__global__ void csr_fill(const float* __restrict__ adj, const int* __restrict__ rowptr,
                         int* __restrict__ colidx) {
    int row = blockIdx.x * (blockDim.x >> 5) + (threadIdx.x >> 5);
    if (row >= NN) return;
    int lane = threadIdx.x & 31;
    const float* r = adj + (size_t)row * NN;
    int pos = rowptr[row];
    for (int c0 = 0; c0 < NN; c0 += 32) {
        float v = r[c0 + lane];
        unsigned m = __ballot_sync(0xffffffffu, v > 0.f);
        if (v > 0.f) {
            int off = __popc(m & ((1u << lane) - 1u));
            colidx[pos + off] = c0 + lane;
        }
        pos += __popc(m);
    }
}

// ---------------- fused split-K reduce + o1/o2 dot (block per node, float4) ----------------
__global__ void reduce_dot(const float* __restrict__ part, const float* __restrict__ ao,
                           __half* __restrict__ hoh, float* __restrict__ o1,
                           float* __restrict__ o2, int fout, int ks) {
    __shared__ float rbuf[8];
    int i = blockIdx.x;
    int tid = threadIdx.x;                  // 128
    int wid = tid >> 5, lane = tid & 31;
    int f4 = fout >> 2;                     // 32..96
    size_t MN4 = (size_t)NN * f4;
    float v1 = 0.f, v2 = 0.f;
    if (tid < f4) {
        size_t idx4 = (size_t)i * f4 + tid;
        float4 s = make_float4(0.f, 0.f, 0.f, 0.f);
        const float4* p4 = (const float4*)part;
        for (int p = 0; p < ks; p++) {
            float4 v = p4[(size_t)p * MN4 + idx4];
            s.x += v.x; s.y += v.y; s.z += v.z; s.w += v.w;
        }
        __half2 h0 = __floats2half2_rn(s.x, s.y);
        __half2 h1 = __floats2half2_rn(s.z, s.w);
        uint2 hv;
        hv.x = *(uint32_t*)&h0; hv.y = *(uint32_t*)&h1;
        *(uint2*)(hoh + (size_t)i * fout + 4 * tid) = hv;
        float4 w1 = *(const float4*)&ao[4 * tid];
        float4 w2 = *(const float4*)&ao[fout + 4 * tid];
        v1 = s.x * w1.x + s.y * w1.y + s.z * w1.z + s.w * w1.w;
        v2 = s.x * w2.x + s.y * w2.y + s.z * w2.z + s.w * w2.w;
    }
#pragma unroll
    for (int o = 16; o; o >>= 1) {
        v1 += __shfl_xor_sync(0xffffffffu, v1, o);
        v2 += __shfl_xor_sync(0xffffffffu, v2, o);
    }
    if (lane == 0) { rbuf[wid] = v1; rbuf[4 + wid] = v2; }
    __syncthreads();
    if (tid == 0) {
        o1[i] = rbuf[0] + rbuf[1] + rbuf[2] + rbuf[3];
        o2[i] = rbuf[4] + rbuf[5] + rbuf[6] + rbuf[7];
    }
}

// ---------------- helpers ----------------
__device__ __forceinline__ float elu1(float x) { return x > 0.f ? x : expm1f(x); }

__device__ __forceinline__ ushort4 bf_hi4(float a, float b, float c, float d,
                                          float& ra, float& rb, float& rc, float& rd) {
    __nv_bfloat16 ha = __float2bfloat16_rn(a), hb = __float2bfloat16_rn(b);
    __nv_bfloat16 hc = __float2bfloat16_rn(c), hd = __float2bfloat16_rn(d);
    ra = a - __bfloat162float(ha); rb = b - __bfloat162float(hb);
    rc = c - __bfloat162float(hc); rd = d - __bfloat162float(hd);
    ushort4 u;
    u.x = *(unsigned short*)&ha; u.y = *(unsigned short*)&hb;
    u.z = *(unsigned short*)&hc; u.w = *(unsigned short*)&hd;
    return u;
}
__device__ __forceinline__ ushort4 bf_lo4(float a, float b, float c, float d) {
    __nv_bfloat16 la = __float2bfloat16_rn(a), lb = __float2bfloat16_rn(b);
    __nv_bfloat16 lc = __float2bfloat16_rn(c), ld = __float2bfloat16_rn(d);
    ushort4 u;
    u.x = *(unsigned short*)&la; u.y = *(unsigned short*)&lb;
    u.z = *(unsigned short*)&lc; u.w = *(unsigned short*)&ld;
    return u;
}
__device__ __forceinline__ void write_bf_quad(__nv_bfloat16* o1, __nv_bfloat16* o2,
                                              size_t idx, float a, float b, float c, float d) {
    float ra, rb, rc, rd;
    *(ushort4*)(o1 + idx) = bf_hi4(a, b, c, d, ra, rb, rc, rd);
    *(ushort4*)(o2 + idx) = bf_lo4(ra, rb, rc, rd);
}

// block softmax over neighbor list. 128 threads.
__device__ __forceinline__ int block_softmax(const int* __restrict__ rowptr,
                                             const int* __restrict__ colidx,
                                             float si, const float* __restrict__ s2,
                                             int i, float* ex, int* cj, float& inv) {
    __shared__ float rbuf[8];
    int tid = threadIdx.x;
    int wid = tid >> 5, lane = tid & 31;
    int b = rowptr[i];
    int d = rowptr[i + 1] - b;
    if (d > DEG_CAP) d = DEG_CAP;
    float lm = -1e30f;
    for (int k = tid; k < d; k += 128) {
        int j = colidx[b + k];
        cj[k] = j;
        float v = si + s2[j];
        v = v > 0.f ? v : ALPHA * v;
        ex[k] = v;
        lm = fmaxf(lm, v);
    }
#pragma unroll
    for (int o = 16; o; o >>= 1) lm = fmaxf(lm, __shfl_xor_sync(0xffffffffu, lm, o));
    if (lane == 0) rbuf[wid] = lm;
    __syncthreads();
    float m = fmaxf(fmaxf(rbuf[0], rbuf[1]), fmaxf(rbuf[2], rbuf[3]));
    float ls = 0.f;
    for (int k = tid; k < d; k += 128) {
        float t = expf(ex[k] - m);
        ex[k] = t;
        ls += t;
    }
#pragma unroll
    for (int o = 16; o; o >>= 1) ls += __shfl_xor_sync(0xffffffffu, ls, o);
    if (lane == 0) rbuf[4 + wid] = ls;
    __syncthreads();
    inv = 1.f / (rbuf[4] + rbuf[5] + rbuf[6] + rbuf[7]);
    return d;
}

__device__ __forceinline__ void unpack_h4(uint2 v, float& a, float& b, float& c, float& d) {
    float2 p0 = __half22float2(*(__half2*)&v.x);
    float2 p1 = __half22float2(*(__half2*)&v.y);
    a = p0.x; b = p0.y; c = p1.x; d = p1.y;
}

// ---------------- fused head softmax + SpMM: hcat = elu(softmax @ h) ----------------
__global__ void spmm_h_fused(const int* __restrict__ rowptr, const int* __restrict__ colidx,
                             const float* __restrict__ s1, const float* __restrict__ s2,
                             const __half* __restrict__ h,
                             __nv_bfloat16* __restrict__ o1, __nv_bfloat16* __restrict__ o2,
                             int hid, int out_stride) {
    __shared__ float ex[DEG_CAP];
    __shared__ int cj[DEG_CAP];
    int i = blockIdx.x, head = blockIdx.y;
    int tid = threadIdx.x;                    // 128
    float inv;
    int d = block_softmax(rowptr, colidx, s1[(size_t)head * NN + i],
                          s2 + (size_t)head * NN, i, ex, cj, inv);
    int pos = hid >> 2;                       // uint2 chunks per row (32..128)
    if (tid >= pos) return;
    const uint2* hb = (const uint2*)(h + (size_t)head * NN * hid);
    float x0 = 0.f, x1 = 0.f, x2 = 0.f, x3 = 0.f;
#pragma unroll 8
    for (int k = 0; k < d; k++) {
        float a = ex[k];
        float v0, v1, v2, v3;
        unpack_h4(hb[(size_t)cj[k] * pos + tid], v0, v1, v2, v3);
        x0 += a * v0; x1 += a * v1; x2 += a * v2; x3 += a * v3;
    }
    size_t base = (size_t)i * out_stride + (size_t)head * hid + 4 * tid;
    write_bf_quad(o1, o2, base, elu1(x0 * inv), elu1(x1 * inv), elu1(x2 * inv), elu1(x3 * inv));
}

// ---------------- fused output softmax + SpMM: x' = elu(softmax @ ho_fp16) ----------------
__global__ void spmm_out_fused(const int* __restrict__ rowptr, const int* __restrict__ colidx,
                               const float* __restrict__ s1, const float* __restrict__ s2,
                               const __half* __restrict__ hoh,
                               __nv_bfloat16* __restrict__ o1, __nv_bfloat16* __restrict__ o2,
                               float* __restrict__ ofp, int hid) {
    __shared__ float ex[DEG_CAP];
    __shared__ int cj[DEG_CAP];
    int i = blockIdx.x;
    int tid = threadIdx.x;                    // 128
    float inv;
    int d = block_softmax(rowptr, colidx, s1[i], s2, i, ex, cj, inv);
    int pos = hid >> 2;                       // 32..96
    if (tid >= pos) return;
    const uint2* hb = (const uint2*)hoh;
    float x0 = 0.f, x1 = 0.f, x2 = 0.f, x3 = 0.f;
#pragma unroll 8
    for (int k = 0; k < d; k++) {
        float a = ex[k];
        float v0, v1, v2, v3;
        unpack_h4(hb[(size_t)cj[k] * pos + tid], v0, v1, v2, v3);
        x0 += a * v0; x1 += a * v1; x2 += a * v2; x3 += a * v3;
    }
    float e0 = elu1(x0 * inv), e1 = elu1(x1 * inv), e2 = elu1(x2 * inv), e3 = elu1(x3 * inv);
    size_t base = (size_t)i * hid + 4 * tid;
    if (ofp) *(float4*)(ofp + base) = make_float4(e0, e1, e2, e3);
    else     write_bf_quad(o1, o2, base, e0, e1, e2, e3);
}

// ---------------- host side ----------------
struct LayerDims { int fin, hid, fout; };
static const LayerDims g_dims[6] = {
    {256, 128, 128}, {128, 256, 256}, {256, 512, 384},
    {384, 512, 256}, {256, 256, 128}, {128, 128, 256}
};

extern "C" void kernel_launch(void* const* d_in, const int* in_sizes, int n_in,
                              void* d_out, int out_size) {
    const float* x   = (const float*)d_in[0];
    const float* adj = (const float*)d_in[1];

    float *p_s1, *p_s2, *p_sp1, *p_sp2, *p_o1v, *p_o2v, *p_part;
    int *p_deg, *p_rowptr, *p_colidx;
    __half *p_h, *p_hoh;
    __nv_bfloat16 *p_a1, *p_a2, *p_b1, *p_b2;
    cudaGetSymbolAddress((void**)&p_deg, g_deg);
    cudaGetSymbolAddress((void**)&p_rowptr, g_rowptr);
    cudaGetSymbolAddress((void**)&p_colidx, g_colidx);
    cudaGetSymbolAddress((void**)&p_h, g_h);
    cudaGetSymbolAddress((void**)&p_s1, g_s1);
    cudaGetSymbolAddress((void**)&p_s2, g_s2);
    cudaGetSymbolAddress((void**)&p_sp1, g_sp1);
    cudaGetSymbolAddress((void**)&p_sp2, g_sp2);
    cudaGetSymbolAddress((void**)&p_hoh, g_hoh);
    cudaGetSymbolAddress((void**)&p_o1v, g_o1);
    cudaGetSymbolAddress((void**)&p_o2v, g_o2);
    cudaGetSymbolAddress((void**)&p_part, g_part);
    cudaGetSymbolAddress((void**)&p_a1, g_a1);
    cudaGetSymbolAddress((void**)&p_a2, g_a2);
    cudaGetSymbolAddress((void**)&p_b1, g_b1);
    cudaGetSymbolAddress((void**)&p_b2, g_b2);

    static int smem_set = 0;
    if (!smem_set) {
        cudaFuncSetAttribute(gemm_mma<float>, cudaFuncAttributeMaxDynamicSharedMemorySize, GSMEM_BYTES);
        cudaFuncSetAttribute(gemm_mma<__half>, cudaFuncAttributeMaxDynamicSharedMemorySize, GSMEM_BYTES);
        smem_set = 1;
    }

    // weight table: offsets into g_b1/g_b2 (elements), hi/lo split once upfront
    long whoff[6], wooff[6];
    WTab tab;
    long cur = 0, maxN4 = 0;
    for (int l = 0; l < 6; l++) {
        int fin = g_dims[l].fin, hid = g_dims[l].hid, fout = g_dims[l].fout;
        long nWh = (long)NH * fin * hid;
        long nWo = (long)NH * hid * fout;
        whoff[l] = cur;
        tab.e[2 * l] = { (const float*)d_in[2 + 4 * l], cur / 4, nWh / 4 };
        cur += nWh;
        wooff[l] = cur;
        tab.e[2 * l + 1] = { (const float*)d_in[4 + 4 * l], cur / 4, nWo / 4 };
        cur += nWo;
        if (nWh / 4 > maxN4) maxN4 = nWh / 4;
        if (nWo / 4 > maxN4) maxN4 = nWo / 4;
    }

    // Build CSR of adjacency
    csr_count<<<NN / 8, 256>>>(adj, p_deg);
    csr_scan<<<1, 1024>>>(p_deg, p_rowptr);
    csr_fill<<<NN / 8, 256>>>(adj, p_rowptr, p_colidx);

    // all weights split in one launch; layer-0 x split
    split_bf_batch<<<dim3((unsigned)((maxN4 + 255) / 256), 12), 256>>>(tab, p_b1, p_b2);
    split_bf<<<(NN * 256 / 4 + 255) / 256, 256>>>(x, p_a1, p_a2, NN * 256 / 4);

    for (int l = 0; l < 6; l++) {
        int fin = g_dims[l].fin, hid = g_dims[l].hid, fout = g_dims[l].fout;
        const float* ah = (const float*)d_in[3 + 4 * l];
        const float* ao = (const float*)d_in[5 + 4 * l];

        // ---- head GEMM: h[head] = x @ Wh[head], fp16 out + fused s1/s2 partial dots ----
        gemm_mma<__half><<<dim3(hid / 128, NN / 128, NH), 256, GSMEM_BYTES>>>(
            p_a1, p_a2, fin, 0L,
            p_b1 + whoff[l], p_b2 + whoff[l], hid, (long)fin * hid,
            p_h, hid, (long)NN * hid, fin,
            ah, p_sp1, p_sp2);
        combine_s<<<(NH * NN + 255) / 256, 256>>>(p_sp1, p_sp2, p_s1, p_s2, hid / 128);

        // fused softmax+SpMM (writes hcat bf16 hi/lo -> Wo A operands)
        spmm_h_fused<<<dim3(NN, NH), 128>>>(p_rowptr, p_colidx, p_s1, p_s2, p_h,
                                            p_a1, p_a2, hid, NH * hid);

        // ---- output GEMM: ho = hcat @ Wo, adaptive split-K, fused reduce+dot ----
        int Ktot = NH * hid;
        int ks = (fout >= 256) ? 4 : 8;
        int Kc = Ktot / ks;
        gemm_mma<float><<<dim3(fout / 128, NN / 128, ks), 256, GSMEM_BYTES>>>(
            p_a1, p_a2, Ktot, (long)Kc,
            p_b1 + wooff[l], p_b2 + wooff[l], fout, (long)Kc * fout,
            p_part, fout, (long)NN * fout, Kc,
            nullptr, nullptr, nullptr);
        reduce_dot<<<NN, 128>>>(p_part, ao, p_hoh, p_o1v, p_o2v, fout, ks);

        // fused output softmax + SpMM; fp32 d_out at layer 5, else bf16 hi/lo A
        float* ofp = (l == 5) ? (float*)d_out : nullptr;
        spmm_out_fused<<<NN, 128>>>(p_rowptr, p_colidx, p_o1v, p_o2v, p_hoh,
                                    p_a1, p_a2, ofp, fout);
    }
    (void)in_sizes; (void)n_in; (void)out_size;
}

// round 15
// speedup vs baseline: 1.1714x; 1.1158x over previous
#include <cuda_runtime.h>
#include <cuda_bf16.h>
#include <cuda_fp16.h>
#include <math.h>
#include <stdint.h>

#define NN 2048          // nodes
#define NH 8             // heads
#define ALPHA 0.2f
#define NNZ_CAP (2048*128)
#define HID_MAX 512
#define DEG_CAP 1024

// ---------------- scratch (static device allocations) ----------------
__device__ int   g_deg[NN];
__device__ int   g_rowptr[NN + 1];
__device__ int   g_colidx[NNZ_CAP];
__device__ __half g_h[NH * NN * HID_MAX];       // per-head projected features (fp16)
__device__ float g_s1[NH * NN];
__device__ float g_s2[NH * NN];
__device__ float g_sp1[NH * 4 * NN];            // per-x-block s partials from gemm epilogue
__device__ float g_sp2[NH * 4 * NN];
__device__ __half g_hoh[NN * HID_MAX];          // output-head features (fp16, gather operand)
__device__ float g_o1[NN];
__device__ float g_o2[NN];
__device__ float g_part[8 * NN * 384];          // split-K partials for Wo gemm
// fp16 operand buffers (A: activations single fp16; B: ALL weights hi/lo, split once)
__device__ __half g_af[NN * 4096];
__device__ __half g_b1[1 << 23];
__device__ __half g_b2[1 << 23];

// ---------------- fp16 conversions / splits ----------------
__device__ __forceinline__ ushort4 h4bits(__half a, __half b, __half c, __half d) {
    ushort4 u;
    u.x = *(unsigned short*)&a; u.y = *(unsigned short*)&b;
    u.z = *(unsigned short*)&c; u.w = *(unsigned short*)&d;
    return u;
}

__global__ void conv_h(const float* __restrict__ in, __half* __restrict__ o, long n4) {
    long i = (long)blockIdx.x * blockDim.x + threadIdx.x;
    if (i >= n4) return;
    float4 v = ((const float4*)in)[i];
    ((ushort4*)o)[i] = h4bits(__float2half_rn(v.x), __float2half_rn(v.y),
                              __float2half_rn(v.z), __float2half_rn(v.w));
}

struct WEnt { const float* src; long off4; long n4; };
struct WTab { WEnt e[12]; };

__global__ void split_hf_batch(WTab tab, __half* __restrict__ o1, __half* __restrict__ o2) {
    WEnt en = tab.e[blockIdx.y];
    long i = (long)blockIdx.x * blockDim.x + threadIdx.x;
    if (i >= en.n4) return;
    float4 v = ((const float4*)en.src)[i];
    __half h0 = __float2half_rn(v.x), h1 = __float2half_rn(v.y);
    __half h2 = __float2half_rn(v.z), h3 = __float2half_rn(v.w);
    __half l0 = __float2half_rn(v.x - __half2float(h0));
    __half l1 = __float2half_rn(v.y - __half2float(h1));
    __half l2 = __float2half_rn(v.z - __half2float(h2));
    __half l3 = __float2half_rn(v.w - __half2float(h3));
    ((ushort4*)o1)[en.off4 + i] = h4bits(h0, h1, h2, h3);
    ((ushort4*)o2)[en.off4 + i] = h4bits(l0, l1, l2, l3);
}

// ---------------- HMMA fp16 GEMM (A single, B hi/lo, 2 products) ----------------
#define A_ST 40
#define B_ST 136
#define A_BYTES (128 * A_ST * 2)
#define B_BYTES (32 * B_ST * 2)
#define BUF_BYTES (A_BYTES + 2 * B_BYTES)        // 27648
#define GSMEM_BYTES (2 * BUF_BYTES)              // 55296

__device__ __forceinline__ uint32_t smem_u32(const void* p) {
    uint32_t a;
    asm("{ .reg .u64 t; cvta.to.shared.u64 t, %1; cvt.u32.u64 %0, t; }" : "=r"(a) : "l"(p));
    return a;
}

#define LDMX4(r0, r1, r2, r3, addr) \
    asm volatile("ldmatrix.sync.aligned.m8n8.x4.shared.b16 {%0,%1,%2,%3}, [%4];" \
                 : "=r"(r0), "=r"(r1), "=r"(r2), "=r"(r3) : "r"(addr))
#define LDMX2T(r0, r1, addr) \
    asm volatile("ldmatrix.sync.aligned.m8n8.x2.trans.shared.b16 {%0,%1}, [%2];" \
                 : "=r"(r0), "=r"(r1) : "r"(addr))
#define MMAF16(acc, a, b) \
    asm volatile("mma.sync.aligned.m16n8k16.row.col.f32.f16.f16.f32 " \
                 "{%0,%1,%2,%3}, {%4,%5,%6,%7}, {%8,%9}, {%0,%1,%2,%3};" \
                 : "+f"((acc)[0]), "+f"((acc)[1]), "+f"((acc)[2]), "+f"((acc)[3]) \
                 : "r"((a)[0]), "r"((a)[1]), "r"((a)[2]), "r"((a)[3]), \
                   "r"((b)[0]), "r"((b)[1]))

__device__ __forceinline__ void store2(float* p, float x, float y) {
    *(float2*)p = make_float2(x, y);
}
__device__ __forceinline__ void store2(__half* p, float x, float y) {
    *(__half2*)p = __floats2half2_rn(x, y);
}

template <typename OT>
__global__ void __launch_bounds__(256, 1) gemm_mma(
    const __half* __restrict__ A, long lda, long sAz,
    const __half* __restrict__ B1, const __half* __restrict__ B2,
    long ldb, long sBz,
    OT* __restrict__ C, long ldc, long sCz, int Kc,
    const float* __restrict__ AH, float* __restrict__ sp1, float* __restrict__ sp2)
{
    extern __shared__ char sm[];
    int tid = threadIdx.x;
    int wid = tid >> 5, lane = tid & 31;
    int mBase = blockIdx.y * 128;
    int nBase = blockIdx.x * 128;
    int z = blockIdx.z;

    const __half* a = A + (long)z * sAz + (size_t)mBase * lda;
    const __half* b1 = B1 + (long)z * sBz + nBase;
    const __half* b2 = B2 + (long)z * sBz + nBase;
    OT* c = C + (long)z * sCz;

    float acc[4][4][4];
#pragma unroll
    for (int i = 0; i < 4; i++)
#pragma unroll
        for (int j = 0; j < 4; j++)
#pragma unroll
            for (int r = 0; r < 4; r++) acc[i][j][r] = 0.f;

    int mW = (wid >> 2) * 64;
    int nW = (wid & 3) * 32;
    uint32_t sb = smem_u32(sm);
    uint4 ra[2], rb1[2], rb2[2];

#pragma unroll
    for (int i = 0; i < 2; i++) {
        int cch = i * 256 + tid;
        int r = cch >> 2, ch = cch & 3;
        ra[i] = *(const uint4*)((const char*)a + (size_t)r * lda * 2 + ch * 16);
        int rB = cch >> 4, chB = cch & 15;
        rb1[i] = *(const uint4*)((const char*)b1 + (size_t)rB * ldb * 2 + chB * 16);
        rb2[i] = *(const uint4*)((const char*)b2 + (size_t)rB * ldb * 2 + chB * 16);
    }
#pragma unroll
    for (int i = 0; i < 2; i++) {
        int cch = i * 256 + tid;
        int r = cch >> 2, ch = cch & 3;
        *(uint4*)(sm + r * (A_ST * 2) + ch * 16) = ra[i];
        int rB = cch >> 4, chB = cch & 15;
        *(uint4*)(sm + A_BYTES + rB * (B_ST * 2) + chB * 16) = rb1[i];
        *(uint4*)(sm + A_BYTES + B_BYTES + rB * (B_ST * 2) + chB * 16) = rb2[i];
    }
    __syncthreads();

    int nT = Kc >> 5;
    for (int t = 0; t < nT; t++) {
        if (t + 1 < nT) {
#pragma unroll
            for (int i = 0; i < 2; i++) {
                int cch = i * 256 + tid;
                int r = cch >> 2, ch = cch & 3;
                ra[i] = *(const uint4*)((const char*)a + (size_t)r * lda * 2 + (t + 1) * 64 + ch * 16);
                int rB = cch >> 4, chB = cch & 15;
                rb1[i] = *(const uint4*)((const char*)b1 + (size_t)((t + 1) * 32 + rB) * ldb * 2 + chB * 16);
                rb2[i] = *(const uint4*)((const char*)b2 + (size_t)((t + 1) * 32 + rB) * ldb * 2 + chB * 16);
            }
        }
        uint32_t bufb = sb + (uint32_t)(t & 1) * BUF_BYTES;
        uint32_t sA = bufb;
        uint32_t sB1 = bufb + A_BYTES;
        uint32_t sB2 = bufb + A_BYTES + B_BYTES;

#pragma unroll
        for (int kk = 0; kk < 32; kk += 16) {
            uint32_t af[4][4];
            uint32_t bfr[2][4][2];
#pragma unroll
            for (int mt = 0; mt < 4; mt++) {
                uint32_t off = (uint32_t)((mW + mt * 16 + (lane & 15)) * (A_ST * 2)
                                          + (kk + ((lane >> 4) << 3)) * 2);
                LDMX4(af[mt][0], af[mt][1], af[mt][2], af[mt][3], sA + off);
            }
#pragma unroll
            for (int nt = 0; nt < 4; nt++) {
                uint32_t off = (uint32_t)((kk + (lane & 15)) * (B_ST * 2) + (nW + nt * 8) * 2);
                LDMX2T(bfr[0][nt][0], bfr[0][nt][1], sB1 + off);
                LDMX2T(bfr[1][nt][0], bfr[1][nt][1], sB2 + off);
            }
#pragma unroll
            for (int mt = 0; mt < 4; mt++)
#pragma unroll
                for (int nt = 0; nt < 4; nt++) {
                    MMAF16(acc[mt][nt], af[mt], bfr[0][nt]);
                    MMAF16(acc[mt][nt], af[mt], bfr[1][nt]);
                }
        }
        if (t + 1 < nT) {
            char* nb = sm + ((t + 1) & 1) * BUF_BYTES;
#pragma unroll
            for (int i = 0; i < 2; i++) {
                int cch = i * 256 + tid;
                int r = cch >> 2, ch = cch & 3;
                *(uint4*)(nb + r * (A_ST * 2) + ch * 16) = ra[i];
                int rB = cch >> 4, chB = cch & 15;
                *(uint4*)(nb + A_BYTES + rB * (B_ST * 2) + chB * 16) = rb1[i];
                *(uint4*)(nb + A_BYTES + B_BYTES + rB * (B_ST * 2) + chB * 16) = rb2[i];
            }
            __syncthreads();
        }
    }

    // C writes
#pragma unroll
    for (int mt = 0; mt < 4; mt++) {
        int row0 = mBase + mW + mt * 16 + (lane >> 2);
#pragma unroll
        for (int nt = 0; nt < 4; nt++) {
            int col = nBase + nW + nt * 8 + (lane & 3) * 2;
            OT* cr = c + (size_t)row0 * ldc + col;
            store2(cr, acc[mt][nt][0], acc[mt][nt][1]);
            store2(cr + 8 * ldc, acc[mt][nt][2], acc[mt][nt][3]);
        }
    }

    // s1/s2 partial dots from fp32 accumulators (head gemm only)
    if (AH != nullptr) {
        const float* ah1 = AH + (size_t)z * 2 * ldc;
        const float* ah2 = ah1 + ldc;
        float w1v[4][2], w2v[4][2];
#pragma unroll
        for (int nt = 0; nt < 4; nt++) {
            int col = nBase + nW + nt * 8 + (lane & 3) * 2;
            w1v[nt][0] = ah1[col]; w1v[nt][1] = ah1[col + 1];
            w2v[nt][0] = ah2[col]; w2v[nt][1] = ah2[col + 1];
        }
        float p1[4][2], p2[4][2];
#pragma unroll
        for (int mt = 0; mt < 4; mt++) {
            float a1lo = 0.f, a1hi = 0.f, a2lo = 0.f, a2hi = 0.f;
#pragma unroll
            for (int nt = 0; nt < 4; nt++) {
                a1lo += acc[mt][nt][0] * w1v[nt][0] + acc[mt][nt][1] * w1v[nt][1];
                a1hi += acc[mt][nt][2] * w1v[nt][0] + acc[mt][nt][3] * w1v[nt][1];
                a2lo += acc[mt][nt][0] * w2v[nt][0] + acc[mt][nt][1] * w2v[nt][1];
                a2hi += acc[mt][nt][2] * w2v[nt][0] + acc[mt][nt][3] * w2v[nt][1];
            }
            p1[mt][0] = a1lo; p1[mt][1] = a1hi;
            p2[mt][0] = a2lo; p2[mt][1] = a2hi;
        }
#pragma unroll
        for (int o = 1; o <= 2; o <<= 1) {
#pragma unroll
            for (int mt = 0; mt < 4; mt++) {
                p1[mt][0] += __shfl_xor_sync(0xffffffffu, p1[mt][0], o);
                p1[mt][1] += __shfl_xor_sync(0xffffffffu, p1[mt][1], o);
                p2[mt][0] += __shfl_xor_sync(0xffffffffu, p2[mt][0], o);
                p2[mt][1] += __shfl_xor_sync(0xffffffffu, p2[mt][1], o);
            }
        }
        float* sbuf = (float*)sm;
        __syncthreads();
        if ((lane & 3) == 0) {
            int nw = wid & 3;
#pragma unroll
            for (int mt = 0; mt < 4; mt++) {
                int r0 = mW + mt * 16 + (lane >> 2);
                sbuf[(nw * 128 + r0) * 2 + 0] = p1[mt][0];
                sbuf[(nw * 128 + r0) * 2 + 1] = p2[mt][0];
                sbuf[(nw * 128 + r0 + 8) * 2 + 0] = p1[mt][1];
                sbuf[(nw * 128 + r0 + 8) * 2 + 1] = p2[mt][1];
            }
        }
        __syncthreads();
        int row = tid >> 1, which = tid & 1;
        float s = sbuf[(0 * 128 + row) * 2 + which] + sbuf[(1 * 128 + row) * 2 + which]
                + sbuf[(2 * 128 + row) * 2 + which] + sbuf[(3 * 128 + row) * 2 + which];
        float* sp = which ? sp2 : sp1;
        sp[((size_t)z * 4 + blockIdx.x) * NN + mBase + row] = s;
    }
}

// combine per-x-block s partials -> s1/s2
__global__ void combine_s(const float* __restrict__ sp1, const float* __restrict__ sp2,
                          float* __restrict__ s1, float* __restrict__ s2, int nbx) {
    int idx = blockIdx.x * blockDim.x + threadIdx.x;
    if (idx >= NH * NN) return;
    int z = idx / NN, n = idx - z * NN;
    float a = 0.f, b = 0.f;
    for (int bx = 0; bx < nbx; bx++) {
        a += sp1[((size_t)z * 4 + bx) * NN + n];
        b += sp2[((size_t)z * 4 + bx) * NN + n];
    }
    s1[idx] = a;
    s2[idx] = b;
}

// ---------------- CSR build ----------------
__global__ void csr_count(const float* __restrict__ adj, int* __restrict__ deg) {
    int row = blockIdx.x * (blockDim.x >> 5) + (threadIdx.x >> 5);
    if (row >= NN) return;
    int lane = threadIdx.x & 31;
    const float* r = adj + (size_t)row * NN;
    int cnt = 0;
    for (int c0 = 0; c0 < NN; c0 += 32) {
        float v = r[c0 + lane];
        unsigned m = __ballot_sync(0xffffffffu, v > 0.f);
        cnt += __popc(m);
    }
    if (lane == 0) deg[row] = cnt;
}

__global__ void csr_scan(const int* __restrict__ deg, int* __restrict__ rowptr) {
    __shared__ int s[1024];
    int t = threadIdx.x;
    int d0 = deg[2 * t], d1 = deg[2 * t + 1];
    s[t] = d0 + d1;
    __syncthreads();
    for (int off = 1; off < 1024; off <<= 1) {
        int v = s[t];
        int add = (t >= off) ? s[t - off] : 0;
        __syncthreads();
        s[t] = v + add;
        __syncthreads();
    }
    int excl = (t > 0) ? s[t - 1] : 0;
    rowptr[2 * t]     = excl;
    rowptr[2 * t + 1] = excl + d0;
    if (t == 1023) rowptr[NN] = s[1023];
}

__global__ void csr_fill(const float* __restrict__ adj, const int* __restrict__ rowptr,
                         int* __restrict__ colidx) {
    int row = blockIdx.x * (blockDim.x >> 5) + (threadIdx.x >> 5);
    if (row >= NN) return;
    int lane = threadIdx.x & 31;
    const float* r = adj + (size_t)row * NN;
    int pos = rowptr[row];
    for (int c0 = 0; c0 < NN; c0 += 32) {
        float v = r[c0 + lane];
        unsigned m = __ballot_sync(0xffffffffu, v > 0.f);
        if (v > 0.f) {
            int off = __popc(m & ((1u << lane) - 1u));
            colidx[pos + off] = c0 + lane;
        }
        pos += __popc(m);
    }
}

// ---------------- fused split-K reduce + o1/o2 dot (block per node, float4) ----------------
__global__ void reduce_dot(const float* __restrict__ part, const float* __restrict__ ao,
                           __half* __restrict__ hoh, float* __restrict__ o1,
                           float* __restrict__ o2, int fout, int ks) {
    __shared__ float rbuf[8];
    int i = blockIdx.x;
    int tid = threadIdx.x;                  // 128
    int wid = tid >> 5, lane = tid & 31;
    int f4 = fout >> 2;                     // 32..96
    size_t MN4 = (size_t)NN * f4;
    float v1 = 0.f, v2 = 0.f;
    if (tid < f4) {
        size_t idx4 = (size_t)i * f4 + tid;
        float4 s = make_float4(0.f, 0.f, 0.f, 0.f);
        const float4* p4 = (const float4*)part;
        for (int p = 0; p < ks; p++) {
            float4 v = p4[(size_t)p * MN4 + idx4];
            s.x += v.x; s.y += v.y; s.z += v.z; s.w += v.w;
        }
        __half2 h0 = __floats2half2_rn(s.x, s.y);
        __half2 h1 = __floats2half2_rn(s.z, s.w);
        uint2 hv;
        hv.x = *(uint32_t*)&h0; hv.y = *(uint32_t*)&h1;
        *(uint2*)(hoh + (size_t)i * fout + 4 * tid) = hv;
        float4 w1 = *(const float4*)&ao[4 * tid];
        float4 w2 = *(const float4*)&ao[fout + 4 * tid];
        v1 = s.x * w1.x + s.y * w1.y + s.z * w1.z + s.w * w1.w;
        v2 = s.x * w2.x + s.y * w2.y + s.z * w2.z + s.w * w2.w;
    }
#pragma unroll
    for (int o = 16; o; o >>= 1) {
        v1 += __shfl_xor_sync(0xffffffffu, v1, o);
        v2 += __shfl_xor_sync(0xffffffffu, v2, o);
    }
    if (lane == 0) { rbuf[wid] = v1; rbuf[4 + wid] = v2; }
    __syncthreads();
    if (tid == 0) {
        o1[i] = rbuf[0] + rbuf[1] + rbuf[2] + rbuf[3];
        o2[i] = rbuf[4] + rbuf[5] + rbuf[6] + rbuf[7];
    }
}

// ---------------- helpers ----------------
__device__ __forceinline__ float elu1(float x) { return x > 0.f ? x : expm1f(x); }

__device__ __forceinline__ void write_h_quad(__half* o, size_t idx,
                                             float a, float b, float c, float d) {
    __half2 p0 = __floats2half2_rn(a, b);
    __half2 p1 = __floats2half2_rn(c, d);
    uint2 v;
    v.x = *(uint32_t*)&p0; v.y = *(uint32_t*)&p1;
    *(uint2*)(o + idx) = v;
}

// block softmax over neighbor list. 128 threads.
__device__ __forceinline__ int block_softmax(const int* __restrict__ rowptr,
                                             const int* __restrict__ colidx,
                                             float si, const float* __restrict__ s2,
                                             int i, float* ex, int* cj, float& inv) {
    __shared__ float rbuf[8];
    int tid = threadIdx.x;
    int wid = tid >> 5, lane = tid & 31;
    int b = rowptr[i];
    int d = rowptr[i + 1] - b;
    if (d > DEG_CAP) d = DEG_CAP;
    float lm = -1e30f;
    for (int k = tid; k < d; k += 128) {
        int j = colidx[b + k];
        cj[k] = j;
        float v = si + s2[j];
        v = v > 0.f ? v : ALPHA * v;
        ex[k] = v;
        lm = fmaxf(lm, v);
    }
#pragma unroll
    for (int o = 16; o; o >>= 1) lm = fmaxf(lm, __shfl_xor_sync(0xffffffffu, lm, o));
    if (lane == 0) rbuf[wid] = lm;
    __syncthreads();
    float m = fmaxf(fmaxf(rbuf[0], rbuf[1]), fmaxf(rbuf[2], rbuf[3]));
    float ls = 0.f;
    for (int k = tid; k < d; k += 128) {
        float t = expf(ex[k] - m);
        ex[k] = t;
        ls += t;
    }
#pragma unroll
    for (int o = 16; o; o >>= 1) ls += __shfl_xor_sync(0xffffffffu, ls, o);
    if (lane == 0) rbuf[4 + wid] = ls;
    __syncthreads();
    inv = 1.f / (rbuf[4] + rbuf[5] + rbuf[6] + rbuf[7]);
    return d;
}

__device__ __forceinline__ void unpack_h4(uint2 v, float& a, float& b, float& c, float& d) {
    float2 p0 = __half22float2(*(__half2*)&v.x);
    float2 p1 = __half22float2(*(__half2*)&v.y);
    a = p0.x; b = p0.y; c = p1.x; d = p1.y;
}

// ---------------- fused head softmax + SpMM: hcat(fp16) = elu(softmax @ h) ----------------
__global__ void spmm_h_fused(const int* __restrict__ rowptr, const int* __restrict__ colidx,
                             const float* __restrict__ s1, const float* __restrict__ s2,
                             const __half* __restrict__ h,
                             __half* __restrict__ out,
                             int hid, int out_stride) {
    __shared__ float ex[DEG_CAP];
    __shared__ int cj[DEG_CAP];
    int i = blockIdx.x, head = blockIdx.y;
    int tid = threadIdx.x;                    // 128
    float inv;
    int d = block_softmax(rowptr, colidx, s1[(size_t)head * NN + i],
                          s2 + (size_t)head * NN, i, ex, cj, inv);
    int pos = hid >> 2;                       // uint2 chunks per row (32..128)
    if (tid >= pos) return;
    const uint2* hb = (const uint2*)(h + (size_t)head * NN * hid);
    float x0 = 0.f, x1 = 0.f, x2 = 0.f, x3 = 0.f;
#pragma unroll 8
    for (int k = 0; k < d; k++) {
        float a = ex[k];
        float v0, v1, v2, v3;
        unpack_h4(hb[(size_t)cj[k] * pos + tid], v0, v1, v2, v3);
        x0 += a * v0; x1 += a * v1; x2 += a * v2; x3 += a * v3;
    }
    size_t base = (size_t)i * out_stride + (size_t)head * hid + 4 * tid;
    write_h_quad(out, base, elu1(x0 * inv), elu1(x1 * inv), elu1(x2 * inv), elu1(x3 * inv));
}

// ---------------- fused output softmax + SpMM: x'(fp16) = elu(softmax @ ho_fp16) ----------------
__global__ void spmm_out_fused(const int* __restrict__ rowptr, const int* __restrict__ colidx,
                               const float* __restrict__ s1, const float* __restrict__ s2,
                               const __half* __restrict__ hoh,
                               __half* __restrict__ out, float* __restrict__ ofp, int hid) {
    __shared__ float ex[DEG_CAP];
    __shared__ int cj[DEG_CAP];
    int i = blockIdx.x;
    int tid = threadIdx.x;                    // 128
    float inv;
    int d = block_softmax(rowptr, colidx, s1[i], s2, i, ex, cj, inv);
    int pos = hid >> 2;                       // 32..96
    if (tid >= pos) return;
    const uint2* hb = (const uint2*)hoh;
    float x0 = 0.f, x1 = 0.f, x2 = 0.f, x3 = 0.f;
#pragma unroll 8
    for (int k = 0; k < d; k++) {
        float a = ex[k];
        float v0, v1, v2, v3;
        unpack_h4(hb[(size_t)cj[k] * pos + tid], v0, v1, v2, v3);
        x0 += a * v0; x1 += a * v1; x2 += a * v2; x3 += a * v3;
    }
    float e0 = elu1(x0 * inv), e1 = elu1(x1 * inv), e2 = elu1(x2 * inv), e3 = elu1(x3 * inv);
    size_t base = (size_t)i * hid + 4 * tid;
    if (ofp) *(float4*)(ofp + base) = make_float4(e0, e1, e2, e3);
    else     write_h_quad(out, base, e0, e1, e2, e3);
}

// ---------------- host side ----------------
struct LayerDims { int fin, hid, fout; };
static const LayerDims g_dims[6] = {
    {256, 128, 128}, {128, 256, 256}, {256, 512, 384},
    {384, 512, 256}, {256, 256, 128}, {128, 128, 256}
};

extern "C" void kernel_launch(void* const* d_in, const int* in_sizes, int n_in,
                              void* d_out, int out_size) {
    const float* x   = (const float*)d_in[0];
    const float* adj = (const float*)d_in[1];

    float *p_s1, *p_s2, *p_sp1, *p_sp2, *p_o1v, *p_o2v, *p_part;
    int *p_deg, *p_rowptr, *p_colidx;
    __half *p_h, *p_hoh, *p_af, *p_b1, *p_b2;
    cudaGetSymbolAddress((void**)&p_deg, g_deg);
    cudaGetSymbolAddress((void**)&p_rowptr, g_rowptr);
    cudaGetSymbolAddress((void**)&p_colidx, g_colidx);
    cudaGetSymbolAddress((void**)&p_h, g_h);
    cudaGetSymbolAddress((void**)&p_s1, g_s1);
    cudaGetSymbolAddress((void**)&p_s2, g_s2);
    cudaGetSymbolAddress((void**)&p_sp1, g_sp1);
    cudaGetSymbolAddress((void**)&p_sp2, g_sp2);
    cudaGetSymbolAddress((void**)&p_hoh, g_hoh);
    cudaGetSymbolAddress((void**)&p_o1v, g_o1);
    cudaGetSymbolAddress((void**)&p_o2v, g_o2);
    cudaGetSymbolAddress((void**)&p_part, g_part);
    cudaGetSymbolAddress((void**)&p_af, g_af);
    cudaGetSymbolAddress((void**)&p_b1, g_b1);
    cudaGetSymbolAddress((void**)&p_b2, g_b2);

    static int smem_set = 0;
    if (!smem_set) {
        cudaFuncSetAttribute(gemm_mma<float>, cudaFuncAttributeMaxDynamicSharedMemorySize, GSMEM_BYTES);
        cudaFuncSetAttribute(gemm_mma<__half>, cudaFuncAttributeMaxDynamicSharedMemorySize, GSMEM_BYTES);
        smem_set = 1;
    }

    // weight table: offsets into g_b1/g_b2 (elements), hi/lo split once upfront
    long whoff[6], wooff[6];
    WTab tab;
    long cur = 0, maxN4 = 0;
    for (int l = 0; l < 6; l++) {
        int fin = g_dims[l].fin, hid = g_dims[l].hid, fout = g_dims[l].fout;
        long nWh = (long)NH * fin * hid;
        long nWo = (long)NH * hid * fout;
        whoff[l] = cur;
        tab.e[2 * l] = { (const float*)d_in[2 + 4 * l], cur / 4, nWh / 4 };
        cur += nWh;
        wooff[l] = cur;
        tab.e[2 * l + 1] = { (const float*)d_in[4 + 4 * l], cur / 4, nWo / 4 };
        cur += nWo;
        if (nWh / 4 > maxN4) maxN4 = nWh / 4;
        if (nWo / 4 > maxN4) maxN4 = nWo / 4;
    }

    // Build CSR of adjacency
    csr_count<<<NN / 8, 256>>>(adj, p_deg);
    csr_scan<<<1, 1024>>>(p_deg, p_rowptr);
    csr_fill<<<NN / 8, 256>>>(adj, p_rowptr, p_colidx);

    // all weights split to fp16 hi/lo in one launch; layer-0 x -> fp16
    split_hf_batch<<<dim3((unsigned)((maxN4 + 255) / 256), 12), 256>>>(tab, p_b1, p_b2);
    conv_h<<<(NN * 256 / 4 + 255) / 256, 256>>>(x, p_af, NN * 256 / 4);

    for (int l = 0; l < 6; l++) {
        int fin = g_dims[l].fin, hid = g_dims[l].hid, fout = g_dims[l].fout;
        const float* ah = (const float*)d_in[3 + 4 * l];
        const float* ao = (const float*)d_in[5 + 4 * l];

        // ---- head GEMM: h[head] = x @ Wh[head], fp16 out + fused s1/s2 partial dots ----
        gemm_mma<__half><<<dim3(hid / 128, NN / 128, NH), 256, GSMEM_BYTES>>>(
            p_af, fin, 0L,
            p_b1 + whoff[l], p_b2 + whoff[l], hid, (long)fin * hid,
            p_h, hid, (long)NN * hid, fin,
            ah, p_sp1, p_sp2);
        combine_s<<<(NH * NN + 255) / 256, 256>>>(p_sp1, p_sp2, p_s1, p_s2, hid / 128);

        // fused softmax+SpMM (writes hcat fp16 -> Wo A operand)
        spmm_h_fused<<<dim3(NN, NH), 128>>>(p_rowptr, p_colidx, p_s1, p_s2, p_h,
                                            p_af, hid, NH * hid);

        // ---- output GEMM: ho = hcat @ Wo, adaptive split-K, fused reduce+dot ----
        int Ktot = NH * hid;
        int ks = (fout >= 256) ? 4 : 8;
        int Kc = Ktot / ks;
        gemm_mma<float><<<dim3(fout / 128, NN / 128, ks), 256, GSMEM_BYTES>>>(
            p_af, Ktot, (long)Kc,
            p_b1 + wooff[l], p_b2 + wooff[l], fout, (long)Kc * fout,
            p_part, fout, (long)NN * fout, Kc,
            nullptr, nullptr, nullptr);
        reduce_dot<<<NN, 128>>>(p_part, ao, p_hoh, p_o1v, p_o2v, fout, ks);

        // fused output softmax + SpMM; fp32 d_out at layer 5, else fp16 next-x
        float* ofp = (l == 5) ? (float*)d_out : nullptr;
        spmm_out_fused<<<NN, 128>>>(p_rowptr, p_colidx, p_o1v, p_o2v, p_hoh,
                                    p_af, ofp, fout);
    }
    (void)in_sizes; (void)n_in; (void)out_size;
}

// round 16
// speedup vs baseline: 1.2716x; 1.0856x over previous
#include <cuda_runtime.h>
#include <cuda_bf16.h>
#include <cuda_fp16.h>
#include <math.h>
#include <stdint.h>

#define NN 2048          // nodes
#define NH 8             // heads
#define ALPHA 0.2f
#define NNZ_CAP (2048*128)
#define HID_MAX 512
#define DEG_CAP 1024

// ---------------- scratch (static device allocations) ----------------
__device__ int   g_deg[NN];
__device__ int   g_rowptr[NN + 1];
__device__ int   g_colidx[NNZ_CAP];
__device__ __half g_h[NH * NN * HID_MAX];       // per-head projected features (fp16)
__device__ float g_s1[NH * NN];
__device__ float g_s2[NH * NN];
__device__ float g_sp1[NH * 4 * NN];            // per-x-block s partials from gemm epilogue
__device__ float g_sp2[NH * 4 * NN];
__device__ __half g_hoh[NN * HID_MAX];          // output-head features (fp16, gather operand)
__device__ float g_o1[NN];
__device__ float g_o2[NN];
__device__ float g_part[8 * NN * 384];          // split-K partials for Wo gemm
// fp16 operand buffers (A: activations; B: ALL weights, single fp16)
__device__ __half g_af[NN * 4096];
__device__ __half g_b1[1 << 23];

// ---------------- fp16 conversions ----------------
__device__ __forceinline__ ushort4 h4bits(__half a, __half b, __half c, __half d) {
    ushort4 u;
    u.x = *(unsigned short*)&a; u.y = *(unsigned short*)&b;
    u.z = *(unsigned short*)&c; u.w = *(unsigned short*)&d;
    return u;
}

__global__ void conv_h(const float* __restrict__ in, __half* __restrict__ o, long n4) {
    long i = (long)blockIdx.x * blockDim.x + threadIdx.x;
    if (i >= n4) return;
    float4 v = ((const float4*)in)[i];
    ((ushort4*)o)[i] = h4bits(__float2half_rn(v.x), __float2half_rn(v.y),
                              __float2half_rn(v.z), __float2half_rn(v.w));
}

struct WEnt { const float* src; long off4; long n4; };
struct WTab { WEnt e[12]; };

__global__ void conv_h_batch(WTab tab, __half* __restrict__ o1) {
    WEnt en = tab.e[blockIdx.y];
    long i = (long)blockIdx.x * blockDim.x + threadIdx.x;
    if (i >= en.n4) return;
    float4 v = ((const float4*)en.src)[i];
    ((ushort4*)o1)[en.off4 + i] = h4bits(__float2half_rn(v.x), __float2half_rn(v.y),
                                         __float2half_rn(v.z), __float2half_rn(v.w));
}

// ---------------- HMMA fp16 GEMM (single product) ----------------
#define A_ST 40
#define B_ST 136
#define A_BYTES (128 * A_ST * 2)
#define B_BYTES (32 * B_ST * 2)
#define BUF_BYTES (A_BYTES + B_BYTES)            // 18944
#define GSMEM_BYTES (2 * BUF_BYTES)              // 37888

__device__ __forceinline__ uint32_t smem_u32(const void* p) {
    uint32_t a;
    asm("{ .reg .u64 t; cvta.to.shared.u64 t, %1; cvt.u32.u64 %0, t; }" : "=r"(a) : "l"(p));
    return a;
}

#define LDMX4(r0, r1, r2, r3, addr) \
    asm volatile("ldmatrix.sync.aligned.m8n8.x4.shared.b16 {%0,%1,%2,%3}, [%4];" \
                 : "=r"(r0), "=r"(r1), "=r"(r2), "=r"(r3) : "r"(addr))
#define LDMX2T(r0, r1, addr) \
    asm volatile("ldmatrix.sync.aligned.m8n8.x2.trans.shared.b16 {%0,%1}, [%2];" \
                 : "=r"(r0), "=r"(r1) : "r"(addr))
#define MMAF16(acc, a, b) \
    asm volatile("mma.sync.aligned.m16n8k16.row.col.f32.f16.f16.f32 " \
                 "{%0,%1,%2,%3}, {%4,%5,%6,%7}, {%8,%9}, {%0,%1,%2,%3};" \
                 : "+f"((acc)[0]), "+f"((acc)[1]), "+f"((acc)[2]), "+f"((acc)[3]) \
                 : "r"((a)[0]), "r"((a)[1]), "r"((a)[2]), "r"((a)[3]), \
                   "r"((b)[0]), "r"((b)[1]))

__device__ __forceinline__ void store2(float* p, float x, float y) {
    *(float2*)p = make_float2(x, y);
}
__device__ __forceinline__ void store2(__half* p, float x, float y) {
    *(__half2*)p = __floats2half2_rn(x, y);
}

template <typename OT>
__global__ void __launch_bounds__(256, 1) gemm_mma(
    const __half* __restrict__ A, long lda, long sAz,
    const __half* __restrict__ B1, long ldb, long sBz,
    OT* __restrict__ C, long ldc, long sCz, int Kc,
    const float* __restrict__ AH, float* __restrict__ sp1, float* __restrict__ sp2)
{
    extern __shared__ char sm[];
    int tid = threadIdx.x;
    int wid = tid >> 5, lane = tid & 31;
    int mBase = blockIdx.y * 128;
    int nBase = blockIdx.x * 128;
    int z = blockIdx.z;

    const __half* a = A + (long)z * sAz + (size_t)mBase * lda;
    const __half* b1 = B1 + (long)z * sBz + nBase;
    OT* c = C + (long)z * sCz;

    float acc[4][4][4];
#pragma unroll
    for (int i = 0; i < 4; i++)
#pragma unroll
        for (int j = 0; j < 4; j++)
#pragma unroll
            for (int r = 0; r < 4; r++) acc[i][j][r] = 0.f;

    int mW = (wid >> 2) * 64;
    int nW = (wid & 3) * 32;
    uint32_t sb = smem_u32(sm);
    uint4 ra[2], rb1[2];

#pragma unroll
    for (int i = 0; i < 2; i++) {
        int cch = i * 256 + tid;
        int r = cch >> 2, ch = cch & 3;
        ra[i] = *(const uint4*)((const char*)a + (size_t)r * lda * 2 + ch * 16);
        int rB = cch >> 4, chB = cch & 15;
        rb1[i] = *(const uint4*)((const char*)b1 + (size_t)rB * ldb * 2 + chB * 16);
    }
#pragma unroll
    for (int i = 0; i < 2; i++) {
        int cch = i * 256 + tid;
        int r = cch >> 2, ch = cch & 3;
        *(uint4*)(sm + r * (A_ST * 2) + ch * 16) = ra[i];
        int rB = cch >> 4, chB = cch & 15;
        *(uint4*)(sm + A_BYTES + rB * (B_ST * 2) + chB * 16) = rb1[i];
    }
    __syncthreads();

    int nT = Kc >> 5;
    for (int t = 0; t < nT; t++) {
        if (t + 1 < nT) {
#pragma unroll
            for (int i = 0; i < 2; i++) {
                int cch = i * 256 + tid;
                int r = cch >> 2, ch = cch & 3;
                ra[i] = *(const uint4*)((const char*)a + (size_t)r * lda * 2 + (t + 1) * 64 + ch * 16);
                int rB = cch >> 4, chB = cch & 15;
                rb1[i] = *(const uint4*)((const char*)b1 + (size_t)((t + 1) * 32 + rB) * ldb * 2 + chB * 16);
            }
        }
        uint32_t bufb = sb + (uint32_t)(t & 1) * BUF_BYTES;
        uint32_t sA = bufb;
        uint32_t sB1 = bufb + A_BYTES;

#pragma unroll
        for (int kk = 0; kk < 32; kk += 16) {
            uint32_t af[4][4];
            uint32_t bfr[4][2];
#pragma unroll
            for (int mt = 0; mt < 4; mt++) {
                uint32_t off = (uint32_t)((mW + mt * 16 + (lane & 15)) * (A_ST * 2)
                                          + (kk + ((lane >> 4) << 3)) * 2);
                LDMX4(af[mt][0], af[mt][1], af[mt][2], af[mt][3], sA + off);
            }
#pragma unroll
            for (int nt = 0; nt < 4; nt++) {
                uint32_t off = (uint32_t)((kk + (lane & 15)) * (B_ST * 2) + (nW + nt * 8) * 2);
                LDMX2T(bfr[nt][0], bfr[nt][1], sB1 + off);
            }
#pragma unroll
            for (int mt = 0; mt < 4; mt++)
#pragma unroll
                for (int nt = 0; nt < 4; nt++)
                    MMAF16(acc[mt][nt], af[mt], bfr[nt]);
        }
        if (t + 1 < nT) {
            char* nb = sm + ((t + 1) & 1) * BUF_BYTES;
#pragma unroll
            for (int i = 0; i < 2; i++) {
                int cch = i * 256 + tid;
                int r = cch >> 2, ch = cch & 3;
                *(uint4*)(nb + r * (A_ST * 2) + ch * 16) = ra[i];
                int rB = cch >> 4, chB = cch & 15;
                *(uint4*)(nb + A_BYTES + rB * (B_ST * 2) + chB * 16) = rb1[i];
            }
            __syncthreads();
        }
    }

    // C writes
#pragma unroll
    for (int mt = 0; mt < 4; mt++) {
        int row0 = mBase + mW + mt * 16 + (lane >> 2);
#pragma unroll
        for (int nt = 0; nt < 4; nt++) {
            int col = nBase + nW + nt * 8 + (lane & 3) * 2;
            OT* cr = c + (size_t)row0 * ldc + col;
            store2(cr, acc[mt][nt][0], acc[mt][nt][1]);
            store2(cr + 8 * ldc, acc[mt][nt][2], acc[mt][nt][3]);
        }
    }

    // s1/s2 partial dots from fp32 accumulators (head gemm only)
    if (AH != nullptr) {
        const float* ah1 = AH + (size_t)z * 2 * ldc;
        const float* ah2 = ah1 + ldc;
        float w1v[4][2], w2v[4][2];
#pragma unroll
        for (int nt = 0; nt < 4; nt++) {
            int col = nBase + nW + nt * 8 + (lane & 3) * 2;
            w1v[nt][0] = ah1[col]; w1v[nt][1] = ah1[col + 1];
            w2v[nt][0] = ah2[col]; w2v[nt][1] = ah2[col + 1];
        }
        float p1[4][2], p2[4][2];
#pragma unroll
        for (int mt = 0; mt < 4; mt++) {
            float a1lo = 0.f, a1hi = 0.f, a2lo = 0.f, a2hi = 0.f;
#pragma unroll
            for (int nt = 0; nt < 4; nt++) {
                a1lo += acc[mt][nt][0] * w1v[nt][0] + acc[mt][nt][1] * w1v[nt][1];
                a1hi += acc[mt][nt][2] * w1v[nt][0] + acc[mt][nt][3] * w1v[nt][1];
                a2lo += acc[mt][nt][0] * w2v[nt][0] + acc[mt][nt][1] * w2v[nt][1];
                a2hi += acc[mt][nt][2] * w2v[nt][0] + acc[mt][nt][3] * w2v[nt][1];
            }
            p1[mt][0] = a1lo; p1[mt][1] = a1hi;
            p2[mt][0] = a2lo; p2[mt][1] = a2hi;
        }
#pragma unroll
        for (int o = 1; o <= 2; o <<= 1) {
#pragma unroll
            for (int mt = 0; mt < 4; mt++) {
                p1[mt][0] += __shfl_xor_sync(0xffffffffu, p1[mt][0], o);
                p1[mt][1] += __shfl_xor_sync(0xffffffffu, p1[mt][1], o);
                p2[mt][0] += __shfl_xor_sync(0xffffffffu, p2[mt][0], o);
                p2[mt][1] += __shfl_xor_sync(0xffffffffu, p2[mt][1], o);
            }
        }
        float* sbuf = (float*)sm;
        __syncthreads();
        if ((lane & 3) == 0) {
            int nw = wid & 3;
#pragma unroll
            for (int mt = 0; mt < 4; mt++) {
                int r0 = mW + mt * 16 + (lane >> 2);
                sbuf[(nw * 128 + r0) * 2 + 0] = p1[mt][0];
                sbuf[(nw * 128 + r0) * 2 + 1] = p2[mt][0];
                sbuf[(nw * 128 + r0 + 8) * 2 + 0] = p1[mt][1];
                sbuf[(nw * 128 + r0 + 8) * 2 + 1] = p2[mt][1];
            }
        }
        __syncthreads();
        int row = tid >> 1, which = tid & 1;
        float s = sbuf[(0 * 128 + row) * 2 + which] + sbuf[(1 * 128 + row) * 2 + which]
                + sbuf[(2 * 128 + row) * 2 + which] + sbuf[(3 * 128 + row) * 2 + which];
        float* sp = which ? sp2 : sp1;
        sp[((size_t)z * 4 + blockIdx.x) * NN + mBase + row] = s;
    }
}

// combine per-x-block s partials -> s1/s2
__global__ void combine_s(const float* __restrict__ sp1, const float* __restrict__ sp2,
                          float* __restrict__ s1, float* __restrict__ s2, int nbx) {
    int idx = blockIdx.x * blockDim.x + threadIdx.x;
    if (idx >= NH * NN) return;
    int z = idx / NN, n = idx - z * NN;
    float a = 0.f, b = 0.f;
    for (int bx = 0; bx < nbx; bx++) {
        a += sp1[((size_t)z * 4 + bx) * NN + n];
        b += sp2[((size_t)z * 4 + bx) * NN + n];
    }
    s1[idx] = a;
    s2[idx] = b;
}

// ---------------- CSR build ----------------
__global__ void csr_count(const float* __restrict__ adj, int* __restrict__ deg) {
    int row = blockIdx.x * (blockDim.x >> 5) + (threadIdx.x >> 5);
    if (row >= NN) return;
    int lane = threadIdx.x & 31;
    const float* r = adj + (size_t)row * NN;
    int cnt = 0;
    for (int c0 = 0; c0 < NN; c0 += 32) {
        float v = r[c0 + lane];
        unsigned m = __ballot_sync(0xffffffffu, v > 0.f);
        cnt += __popc(m);
    }
    if (lane == 0) deg[row] = cnt;
}

__global__ void csr_scan(const int* __restrict__ deg, int* __restrict__ rowptr) {
    __shared__ int s[1024];
    int t = threadIdx.x;
    int d0 = deg[2 * t], d1 = deg[2 * t + 1];
    s[t] = d0 + d1;
    __syncthreads();
    for (int off = 1; off < 1024; off <<= 1) {
        int v = s[t];
        int add = (t >= off) ? s[t - off] : 0;
        __syncthreads();
        s[t] = v + add;
        __syncthreads();
    }
    int excl = (t > 0) ? s[t - 1] : 0;
    rowptr[2 * t]     = excl;
    rowptr[2 * t + 1] = excl + d0;
    if (t == 1023) rowptr[NN] = s[1023];
}

__global__ void csr_fill(const float* __restrict__ adj, const int* __restrict__ rowptr,
                         int* __restrict__ colidx) {
    int row = blockIdx.x * (blockDim.x >> 5) + (threadIdx.x >> 5);
    if (row >= NN) return;
    int lane = threadIdx.x & 31;
    const float* r = adj + (size_t)row * NN;
    int pos = rowptr[row];
    for (int c0 = 0; c0 < NN; c0 += 32) {
        float v = r[c0 + lane];
        unsigned m = __ballot_sync(0xffffffffu, v > 0.f);
        if (v > 0.f) {
            int off = __popc(m & ((1u << lane) - 1u));
            colidx[pos + off] = c0 + lane;
        }
        pos += __popc(m);
    }
}

// ---------------- fused split-K reduce + o1/o2 dot (block per node, float4) ----------------
__global__ void reduce_dot(const float* __restrict__ part, const float* __restrict__ ao,
                           __half* __restrict__ hoh, float* __restrict__ o1,
                           float* __restrict__ o2, int fout, int ks) {
    __shared__ float rbuf[8];
    int i = blockIdx.x;
    int tid = threadIdx.x;                  // 128
    int wid = tid >> 5, lane = tid & 31;
    int f4 = fout >> 2;                     // 32..96
    size_t MN4 = (size_t)NN * f4;
    float v1 = 0.f, v2 = 0.f;
    if (tid < f4) {
        size_t idx4 = (size_t)i * f4 + tid;
        float4 s = make_float4(0.f, 0.f, 0.f, 0.f);
        const float4* p4 = (const float4*)part;
        for (int p = 0; p < ks; p++) {
            float4 v = p4[(size_t)p * MN4 + idx4];
            s.x += v.x; s.y += v.y; s.z += v.z; s.w += v.w;
        }
        __half2 h0 = __floats2half2_rn(s.x, s.y);
        __half2 h1 = __floats2half2_rn(s.z, s.w);
        uint2 hv;
        hv.x = *(uint32_t*)&h0; hv.y = *(uint32_t*)&h1;
        *(uint2*)(hoh + (size_t)i * fout + 4 * tid) = hv;
        float4 w1 = *(const float4*)&ao[4 * tid];
        float4 w2 = *(const float4*)&ao[fout + 4 * tid];
        v1 = s.x * w1.x + s.y * w1.y + s.z * w1.z + s.w * w1.w;
        v2 = s.x * w2.x + s.y * w2.y + s.z * w2.z + s.w * w2.w;
    }
#pragma unroll
    for (int o = 16; o; o >>= 1) {
        v1 += __shfl_xor_sync(0xffffffffu, v1, o);
        v2 += __shfl_xor_sync(0xffffffffu, v2, o);
    }
    if (lane == 0) { rbuf[wid] = v1; rbuf[4 + wid] = v2; }
    __syncthreads();
    if (tid == 0) {
        o1[i] = rbuf[0] + rbuf[1] + rbuf[2] + rbuf[3];
        o2[i] = rbuf[4] + rbuf[5] + rbuf[6] + rbuf[7];
    }
}

// ---------------- helpers ----------------
__device__ __forceinline__ float elu1(float x) { return x > 0.f ? x : expm1f(x); }

__device__ __forceinline__ void write_h_quad(__half* o, size_t idx,
                                             float a, float b, float c, float d) {
    __half2 p0 = __floats2half2_rn(a, b);
    __half2 p1 = __floats2half2_rn(c, d);
    uint2 v;
    v.x = *(uint32_t*)&p0; v.y = *(uint32_t*)&p1;
    *(uint2*)(o + idx) = v;
}

// block softmax over neighbor list. 128 threads.
__device__ __forceinline__ int block_softmax(const int* __restrict__ rowptr,
                                             const int* __restrict__ colidx,
                                             float si, const float* __restrict__ s2,
                                             int i, float* ex, int* cj, float& inv) {
    __shared__ float rbuf[8];
    int tid = threadIdx.x;
    int wid = tid >> 5, lane = tid & 31;
    int b = rowptr[i];
    int d = rowptr[i + 1] - b;
    if (d > DEG_CAP) d = DEG_CAP;
    float lm = -1e30f;
    for (int k = tid; k < d; k += 128) {
        int j = colidx[b + k];
        cj[k] = j;
        float v = si + s2[j];
        v = v > 0.f ? v : ALPHA * v;
        ex[k] = v;
        lm = fmaxf(lm, v);
    }
#pragma unroll
    for (int o = 16; o; o >>= 1) lm = fmaxf(lm, __shfl_xor_sync(0xffffffffu, lm, o));
    if (lane == 0) rbuf[wid] = lm;
    __syncthreads();
    float m = fmaxf(fmaxf(rbuf[0], rbuf[1]), fmaxf(rbuf[2], rbuf[3]));
    float ls = 0.f;
    for (int k = tid; k < d; k += 128) {
        float t = expf(ex[k] - m);
        ex[k] = t;
        ls += t;
    }
#pragma unroll
    for (int o = 16; o; o >>= 1) ls += __shfl_xor_sync(0xffffffffu, ls, o);
    if (lane == 0) rbuf[4 + wid] = ls;
    __syncthreads();
    inv = 1.f / (rbuf[4] + rbuf[5] + rbuf[6] + rbuf[7]);
    return d;
}

__device__ __forceinline__ void unpack_h4(uint2 v, float& a, float& b, float& c, float& d) {
    float2 p0 = __half22float2(*(__half2*)&v.x);
    float2 p1 = __half22float2(*(__half2*)&v.y);
    a = p0.x; b = p0.y; c = p1.x; d = p1.y;
}

// ---------------- fused head softmax + SpMM: hcat(fp16) = elu(softmax @ h) ----------------
__global__ void spmm_h_fused(const int* __restrict__ rowptr, const int* __restrict__ colidx,
                             const float* __restrict__ s1, const float* __restrict__ s2,
                             const __half* __restrict__ h,
                             __half* __restrict__ out,
                             int hid, int out_stride) {
    __shared__ float ex[DEG_CAP];
    __shared__ int cj[DEG_CAP];
    int i = blockIdx.x, head = blockIdx.y;
    int tid = threadIdx.x;                    // 128
    float inv;
    int d = block_softmax(rowptr, colidx, s1[(size_t)head * NN + i],
                          s2 + (size_t)head * NN, i, ex, cj, inv);
    int pos = hid >> 2;                       // uint2 chunks per row (32..128)
    if (tid >= pos) return;
    const uint2* hb = (const uint2*)(h + (size_t)head * NN * hid);
    float x0 = 0.f, x1 = 0.f, x2 = 0.f, x3 = 0.f;
#pragma unroll 8
    for (int k = 0; k < d; k++) {
        float a = ex[k];
        float v0, v1, v2, v3;
        unpack_h4(hb[(size_t)cj[k] * pos + tid], v0, v1, v2, v3);
        x0 += a * v0; x1 += a * v1; x2 += a * v2; x3 += a * v3;
    }
    size_t base = (size_t)i * out_stride + (size_t)head * hid + 4 * tid;
    write_h_quad(out, base, elu1(x0 * inv), elu1(x1 * inv), elu1(x2 * inv), elu1(x3 * inv));
}

// ---------------- fused output softmax + SpMM: x'(fp16) = elu(softmax @ ho_fp16) ----------------
__global__ void spmm_out_fused(const int* __restrict__ rowptr, const int* __restrict__ colidx,
                               const float* __restrict__ s1, const float* __restrict__ s2,
                               const __half* __restrict__ hoh,
                               __half* __restrict__ out, float* __restrict__ ofp, int hid) {
    __shared__ float ex[DEG_CAP];
    __shared__ int cj[DEG_CAP];
    int i = blockIdx.x;
    int tid = threadIdx.x;                    // 128
    float inv;
    int d = block_softmax(rowptr, colidx, s1[i], s2, i, ex, cj, inv);
    int pos = hid >> 2;                       // 32..96
    if (tid >= pos) return;
    const uint2* hb = (const uint2*)hoh;
    float x0 = 0.f, x1 = 0.f, x2 = 0.f, x3 = 0.f;
#pragma unroll 8
    for (int k = 0; k < d; k++) {
        float a = ex[k];
        float v0, v1, v2, v3;
        unpack_h4(hb[(size_t)cj[k] * pos + tid], v0, v1, v2, v3);
        x0 += a * v0; x1 += a * v1; x2 += a * v2; x3 += a * v3;
    }
    float e0 = elu1(x0 * inv), e1 = elu1(x1 * inv), e2 = elu1(x2 * inv), e3 = elu1(x3 * inv);
    size_t base = (size_t)i * hid + 4 * tid;
    if (ofp) *(float4*)(ofp + base) = make_float4(e0, e1, e2, e3);
    else     write_h_quad(out, base, e0, e1, e2, e3);
}

// ---------------- host side ----------------
struct LayerDims { int fin, hid, fout; };
static const LayerDims g_dims[6] = {
    {256, 128, 128}, {128, 256, 256}, {256, 512, 384},
    {384, 512, 256}, {256, 256, 128}, {128, 128, 256}
};

extern "C" void kernel_launch(void* const* d_in, const int* in_sizes, int n_in,
                              void* d_out, int out_size) {
    const float* x   = (const float*)d_in[0];
    const float* adj = (const float*)d_in[1];

    float *p_s1, *p_s2, *p_sp1, *p_sp2, *p_o1v, *p_o2v, *p_part;
    int *p_deg, *p_rowptr, *p_colidx;
    __half *p_h, *p_hoh, *p_af, *p_b1;
    cudaGetSymbolAddress((void**)&p_deg, g_deg);
    cudaGetSymbolAddress((void**)&p_rowptr, g_rowptr);
    cudaGetSymbolAddress((void**)&p_colidx, g_colidx);
    cudaGetSymbolAddress((void**)&p_h, g_h);
    cudaGetSymbolAddress((void**)&p_s1, g_s1);
    cudaGetSymbolAddress((void**)&p_s2, g_s2);
    cudaGetSymbolAddress((void**)&p_sp1, g_sp1);
    cudaGetSymbolAddress((void**)&p_sp2, g_sp2);
    cudaGetSymbolAddress((void**)&p_hoh, g_hoh);
    cudaGetSymbolAddress((void**)&p_o1v, g_o1);
    cudaGetSymbolAddress((void**)&p_o2v, g_o2);
    cudaGetSymbolAddress((void**)&p_part, g_part);
    cudaGetSymbolAddress((void**)&p_af, g_af);
    cudaGetSymbolAddress((void**)&p_b1, g_b1);

    static int smem_set = 0;
    if (!smem_set) {
        cudaFuncSetAttribute(gemm_mma<float>, cudaFuncAttributeMaxDynamicSharedMemorySize, GSMEM_BYTES);
        cudaFuncSetAttribute(gemm_mma<__half>, cudaFuncAttributeMaxDynamicSharedMemorySize, GSMEM_BYTES);
        smem_set = 1;
    }

    // weight table: offsets into g_b1 (elements), converted once upfront
    long whoff[6], wooff[6];
    WTab tab;
    long cur = 0, maxN4 = 0;
    for (int l = 0; l < 6; l++) {
        int fin = g_dims[l].fin, hid = g_dims[l].hid, fout = g_dims[l].fout;
        long nWh = (long)NH * fin * hid;
        long nWo = (long)NH * hid * fout;
        whoff[l] = cur;
        tab.e[2 * l] = { (const float*)d_in[2 + 4 * l], cur / 4, nWh / 4 };
        cur += nWh;
        wooff[l] = cur;
        tab.e[2 * l + 1] = { (const float*)d_in[4 + 4 * l], cur / 4, nWo / 4 };
        cur += nWo;
        if (nWh / 4 > maxN4) maxN4 = nWh / 4;
        if (nWo / 4 > maxN4) maxN4 = nWo / 4;
    }

    // Build CSR of adjacency
    csr_count<<<NN / 8, 256>>>(adj, p_deg);
    csr_scan<<<1, 1024>>>(p_deg, p_rowptr);
    csr_fill<<<NN / 8, 256>>>(adj, p_rowptr, p_colidx);

    // all weights -> fp16 in one launch; layer-0 x -> fp16
    conv_h_batch<<<dim3((unsigned)((maxN4 + 255) / 256), 12), 256>>>(tab, p_b1);
    conv_h<<<(NN * 256 / 4 + 255) / 256, 256>>>(x, p_af, NN * 256 / 4);

    for (int l = 0; l < 6; l++) {
        int fin = g_dims[l].fin, hid = g_dims[l].hid, fout = g_dims[l].fout;
        const float* ah = (const float*)d_in[3 + 4 * l];
        const float* ao = (const float*)d_in[5 + 4 * l];

        // ---- head GEMM: h[head] = x @ Wh[head], fp16 out + fused s1/s2 partial dots ----
        gemm_mma<__half><<<dim3(hid / 128, NN / 128, NH), 256, GSMEM_BYTES>>>(
            p_af, fin, 0L,
            p_b1 + whoff[l], hid, (long)fin * hid,
            p_h, hid, (long)NN * hid, fin,
            ah, p_sp1, p_sp2);
        combine_s<<<(NH * NN + 255) / 256, 256>>>(p_sp1, p_sp2, p_s1, p_s2, hid / 128);

        // fused softmax+SpMM (writes hcat fp16 -> Wo A operand)
        spmm_h_fused<<<dim3(NN, NH), 128>>>(p_rowptr, p_colidx, p_s1, p_s2, p_h,
                                            p_af, hid, NH * hid);

        // ---- output GEMM: ho = hcat @ Wo, adaptive split-K, fused reduce+dot ----
        int Ktot = NH * hid;
        int ks = (fout >= 256) ? 4 : 8;
        int Kc = Ktot / ks;
        gemm_mma<float><<<dim3(fout / 128, NN / 128, ks), 256, GSMEM_BYTES>>>(
            p_af, Ktot, (long)Kc,
            p_b1 + wooff[l], fout, (long)Kc * fout,
            p_part, fout, (long)NN * fout, Kc,
            nullptr, nullptr, nullptr);
        reduce_dot<<<NN, 128>>>(p_part, ao, p_hoh, p_o1v, p_o2v, fout, ks);

        // fused output softmax + SpMM; fp32 d_out at layer 5, else fp16 next-x
        float* ofp = (l == 5) ? (float*)d_out : nullptr;
        spmm_out_fused<<<NN, 128>>>(p_rowptr, p_colidx, p_o1v, p_o2v, p_hoh,
                                    p_af, ofp, fout);
    }
    (void)in_sizes; (void)n_in; (void)out_size;
}

// round 17
// speedup vs baseline: 1.3411x; 1.0546x over previous
#include <cuda_runtime.h>
#include <cuda_bf16.h>
#include <cuda_fp16.h>
#include <math.h>
#include <stdint.h>

#define NN 2048          // nodes
#define NH 8             // heads
#define ALPHA 0.2f
#define NNZ_CAP (2048*128)
#define HID_MAX 512
#define DEG_CAP 1024

// ---------------- scratch (static device allocations) ----------------
__device__ int   g_deg[NN];
__device__ int   g_rowptr[NN + 1];
__device__ int   g_colidx[NNZ_CAP];
__device__ __half g_h[NH * NN * HID_MAX];       // per-head projected features (fp16)
__device__ float g_s1[NH * NN];
__device__ float g_s2[NH * NN];
__device__ float g_sp1[NH * 4 * NN];            // per-x-block s partials from gemm epilogue
__device__ float g_sp2[NH * 4 * NN];
__device__ __half g_hoh[NN * HID_MAX];          // output-head features (fp16, gather operand)
__device__ float g_o1[NN];
__device__ float g_o2[NN];
__device__ float g_part[16 * NN * 192];         // split-K partials for Wo gemm (<=3072*NN floats)
// fp16 operand buffers (A: activations; B: ALL weights, single fp16)
__device__ __half g_af[NN * 4096];
__device__ __half g_b1[1 << 23];

// ---------------- fp16 conversions ----------------
__device__ __forceinline__ ushort4 h4bits(__half a, __half b, __half c, __half d) {
    ushort4 u;
    u.x = *(unsigned short*)&a; u.y = *(unsigned short*)&b;
    u.z = *(unsigned short*)&c; u.w = *(unsigned short*)&d;
    return u;
}

__global__ void conv_h(const float* __restrict__ in, __half* __restrict__ o, long n4) {
    long i = (long)blockIdx.x * blockDim.x + threadIdx.x;
    if (i >= n4) return;
    float4 v = ((const float4*)in)[i];
    ((ushort4*)o)[i] = h4bits(__float2half_rn(v.x), __float2half_rn(v.y),
                              __float2half_rn(v.z), __float2half_rn(v.w));
}

struct WEnt { const float* src; long off4; long n4; };
struct WTab { WEnt e[12]; };

__global__ void conv_h_batch(WTab tab, __half* __restrict__ o1) {
    WEnt en = tab.e[blockIdx.y];
    long i = (long)blockIdx.x * blockDim.x + threadIdx.x;
    if (i >= en.n4) return;
    float4 v = ((const float4*)en.src)[i];
    ((ushort4*)o1)[en.off4 + i] = h4bits(__float2half_rn(v.x), __float2half_rn(v.y),
                                         __float2half_rn(v.z), __float2half_rn(v.w));
}

// ---------------- HMMA fp16 GEMM (single product, occupancy 2) ----------------
#define A_ST 40
#define B_ST 136
#define A_BYTES (128 * A_ST * 2)
#define B_BYTES (32 * B_ST * 2)
#define BUF_BYTES (A_BYTES + B_BYTES)            // 18944
#define GSMEM_BYTES (2 * BUF_BYTES)              // 37888

__device__ __forceinline__ uint32_t smem_u32(const void* p) {
    uint32_t a;
    asm("{ .reg .u64 t; cvta.to.shared.u64 t, %1; cvt.u32.u64 %0, t; }" : "=r"(a) : "l"(p));
    return a;
}

#define LDMX4(r0, r1, r2, r3, addr) \
    asm volatile("ldmatrix.sync.aligned.m8n8.x4.shared.b16 {%0,%1,%2,%3}, [%4];" \
                 : "=r"(r0), "=r"(r1), "=r"(r2), "=r"(r3) : "r"(addr))
#define LDMX2T(r0, r1, addr) \
    asm volatile("ldmatrix.sync.aligned.m8n8.x2.trans.shared.b16 {%0,%1}, [%2];" \
                 : "=r"(r0), "=r"(r1) : "r"(addr))
#define MMAF16(acc, a, b) \
    asm volatile("mma.sync.aligned.m16n8k16.row.col.f32.f16.f16.f32 " \
                 "{%0,%1,%2,%3}, {%4,%5,%6,%7}, {%8,%9}, {%0,%1,%2,%3};" \
                 : "+f"((acc)[0]), "+f"((acc)[1]), "+f"((acc)[2]), "+f"((acc)[3]) \
                 : "r"((a)[0]), "r"((a)[1]), "r"((a)[2]), "r"((a)[3]), \
                   "r"((b)[0]), "r"((b)[1]))

__device__ __forceinline__ void store2(float* p, float x, float y) {
    *(float2*)p = make_float2(x, y);
}
__device__ __forceinline__ void store2(__half* p, float x, float y) {
    *(__half2*)p = __floats2half2_rn(x, y);
}

template <typename OT>
__global__ void __launch_bounds__(256, 2) gemm_mma(
    const __half* __restrict__ A, long lda, long sAz,
    const __half* __restrict__ B1, long ldb, long sBz,
    OT* __restrict__ C, long ldc, long sCz, int Kc,
    const float* __restrict__ AH, float* __restrict__ sp1, float* __restrict__ sp2)
{
    extern __shared__ char sm[];
    int tid = threadIdx.x;
    int wid = tid >> 5, lane = tid & 31;
    int mBase = blockIdx.y * 128;
    int nBase = blockIdx.x * 128;
    int z = blockIdx.z;

    const __half* a = A + (long)z * sAz + (size_t)mBase * lda;
    const __half* b1 = B1 + (long)z * sBz + nBase;
    OT* c = C + (long)z * sCz;

    float acc[4][4][4];
#pragma unroll
    for (int i = 0; i < 4; i++)
#pragma unroll
        for (int j = 0; j < 4; j++)
#pragma unroll
            for (int r = 0; r < 4; r++) acc[i][j][r] = 0.f;

    int mW = (wid >> 2) * 64;
    int nW = (wid & 3) * 32;
    uint32_t sb = smem_u32(sm);
    uint4 ra[2], rb1[2];

#pragma unroll
    for (int i = 0; i < 2; i++) {
        int cch = i * 256 + tid;
        int r = cch >> 2, ch = cch & 3;
        ra[i] = *(const uint4*)((const char*)a + (size_t)r * lda * 2 + ch * 16);
        int rB = cch >> 4, chB = cch & 15;
        rb1[i] = *(const uint4*)((const char*)b1 + (size_t)rB * ldb * 2 + chB * 16);
    }
#pragma unroll
    for (int i = 0; i < 2; i++) {
        int cch = i * 256 + tid;
        int r = cch >> 2, ch = cch & 3;
        *(uint4*)(sm + r * (A_ST * 2) + ch * 16) = ra[i];
        int rB = cch >> 4, chB = cch & 15;
        *(uint4*)(sm + A_BYTES + rB * (B_ST * 2) + chB * 16) = rb1[i];
    }
    __syncthreads();

    int nT = Kc >> 5;
    for (int t = 0; t < nT; t++) {
        if (t + 1 < nT) {
#pragma unroll
            for (int i = 0; i < 2; i++) {
                int cch = i * 256 + tid;
                int r = cch >> 2, ch = cch & 3;
                ra[i] = *(const uint4*)((const char*)a + (size_t)r * lda * 2 + (t + 1) * 64 + ch * 16);
                int rB = cch >> 4, chB = cch & 15;
                rb1[i] = *(const uint4*)((const char*)b1 + (size_t)((t + 1) * 32 + rB) * ldb * 2 + chB * 16);
            }
        }
        uint32_t bufb = sb + (uint32_t)(t & 1) * BUF_BYTES;
        uint32_t sA = bufb;
        uint32_t sB1 = bufb + A_BYTES;

#pragma unroll
        for (int kk = 0; kk < 32; kk += 16) {
            uint32_t af[4][4];
            uint32_t bfr[4][2];
#pragma unroll
            for (int mt = 0; mt < 4; mt++) {
                uint32_t off = (uint32_t)((mW + mt * 16 + (lane & 15)) * (A_ST * 2)
                                          + (kk + ((lane >> 4) << 3)) * 2);
                LDMX4(af[mt][0], af[mt][1], af[mt][2], af[mt][3], sA + off);
            }
#pragma unroll
            for (int nt = 0; nt < 4; nt++) {
                uint32_t off = (uint32_t)((kk + (lane & 15)) * (B_ST * 2) + (nW + nt * 8) * 2);
                LDMX2T(bfr[nt][0], bfr[nt][1], sB1 + off);
            }
#pragma unroll
            for (int mt = 0; mt < 4; mt++)
#pragma unroll
                for (int nt = 0; nt < 4; nt++)
                    MMAF16(acc[mt][nt], af[mt], bfr[nt]);
        }
        if (t + 1 < nT) {
            char* nb = sm + ((t + 1) & 1) * BUF_BYTES;
#pragma unroll
            for (int i = 0; i < 2; i++) {
                int cch = i * 256 + tid;
                int r = cch >> 2, ch = cch & 3;
                *(uint4*)(nb + r * (A_ST * 2) + ch * 16) = ra[i];
                int rB = cch >> 4, chB = cch & 15;
                *(uint4*)(nb + A_BYTES + rB * (B_ST * 2) + chB * 16) = rb1[i];
            }
            __syncthreads();
        }
    }

    // C writes
#pragma unroll
    for (int mt = 0; mt < 4; mt++) {
        int row0 = mBase + mW + mt * 16 + (lane >> 2);
#pragma unroll
        for (int nt = 0; nt < 4; nt++) {
            int col = nBase + nW + nt * 8 + (lane & 3) * 2;
            OT* cr = c + (size_t)row0 * ldc + col;
            store2(cr, acc[mt][nt][0], acc[mt][nt][1]);
            store2(cr + 8 * ldc, acc[mt][nt][2], acc[mt][nt][3]);
        }
    }

    // s1/s2 partial dots from fp32 accumulators (head gemm only)
    if (AH != nullptr) {
        const float* ah1 = AH + (size_t)z * 2 * ldc;
        const float* ah2 = ah1 + ldc;
        float w1v[4][2], w2v[4][2];
#pragma unroll
        for (int nt = 0; nt < 4; nt++) {
            int col = nBase + nW + nt * 8 + (lane & 3) * 2;
            w1v[nt][0] = ah1[col]; w1v[nt][1] = ah1[col + 1];
            w2v[nt][0] = ah2[col]; w2v[nt][1] = ah2[col + 1];
        }
        float p1[4][2], p2[4][2];
#pragma unroll
        for (int mt = 0; mt < 4; mt++) {
            float a1lo = 0.f, a1hi = 0.f, a2lo = 0.f, a2hi = 0.f;
#pragma unroll
            for (int nt = 0; nt < 4; nt++) {
                a1lo += acc[mt][nt][0] * w1v[nt][0] + acc[mt][nt][1] * w1v[nt][1];
                a1hi += acc[mt][nt][2] * w1v[nt][0] + acc[mt][nt][3] * w1v[nt][1];
                a2lo += acc[mt][nt][0] * w2v[nt][0] + acc[mt][nt][1] * w2v[nt][1];
                a2hi += acc[mt][nt][2] * w2v[nt][0] + acc[mt][nt][3] * w2v[nt][1];
            }
            p1[mt][0] = a1lo; p1[mt][1] = a1hi;
            p2[mt][0] = a2lo; p2[mt][1] = a2hi;
        }
#pragma unroll
        for (int o = 1; o <= 2; o <<= 1) {
#pragma unroll
            for (int mt = 0; mt < 4; mt++) {
                p1[mt][0] += __shfl_xor_sync(0xffffffffu, p1[mt][0], o);
                p1[mt][1] += __shfl_xor_sync(0xffffffffu, p1[mt][1], o);
                p2[mt][0] += __shfl_xor_sync(0xffffffffu, p2[mt][0], o);
                p2[mt][1] += __shfl_xor_sync(0xffffffffu, p2[mt][1], o);
            }
        }
        float* sbuf = (float*)sm;
        __syncthreads();
        if ((lane & 3) == 0) {
            int nw = wid & 3;
#pragma unroll
            for (int mt = 0; mt < 4; mt++) {
                int r0 = mW + mt * 16 + (lane >> 2);
                sbuf[(nw * 128 + r0) * 2 + 0] = p1[mt][0];
                sbuf[(nw * 128 + r0) * 2 + 1] = p2[mt][0];
                sbuf[(nw * 128 + r0 + 8) * 2 + 0] = p1[mt][1];
                sbuf[(nw * 128 + r0 + 8) * 2 + 1] = p2[mt][1];
            }
        }
        __syncthreads();
        int row = tid >> 1, which = tid & 1;
        float s = sbuf[(0 * 128 + row) * 2 + which] + sbuf[(1 * 128 + row) * 2 + which]
                + sbuf[(2 * 128 + row) * 2 + which] + sbuf[(3 * 128 + row) * 2 + which];
        float* sp = which ? sp2 : sp1;
        sp[((size_t)z * 4 + blockIdx.x) * NN + mBase + row] = s;
    }
}

// combine per-x-block s partials -> s1/s2
__global__ void combine_s(const float* __restrict__ sp1, const float* __restrict__ sp2,
                          float* __restrict__ s1, float* __restrict__ s2, int nbx) {
    int idx = blockIdx.x * blockDim.x + threadIdx.x;
    if (idx >= NH * NN) return;
    int z = idx / NN, n = idx - z * NN;
    float a = 0.f, b = 0.f;
    for (int bx = 0; bx < nbx; bx++) {
        a += sp1[((size_t)z * 4 + bx) * NN + n];
        b += sp2[((size_t)z * 4 + bx) * NN + n];
    }
    s1[idx] = a;
    s2[idx] = b;
}

// ---------------- CSR build ----------------
__global__ void csr_count(const float* __restrict__ adj, int* __restrict__ deg) {
    int row = blockIdx.x * (blockDim.x >> 5) + (threadIdx.x >> 5);
    if (row >= NN) return;
    int lane = threadIdx.x & 31;
    const float* r = adj + (size_t)row * NN;
    int cnt = 0;
    for (int c0 = 0; c0 < NN; c0 += 32) {
        float v = r[c0 + lane];
        unsigned m = __ballot_sync(0xffffffffu, v > 0.f);
        cnt += __popc(m);
    }
    if (lane == 0) deg[row] = cnt;
}

__global__ void csr_scan(const int* __restrict__ deg, int* __restrict__ rowptr) {
    __shared__ int s[1024];
    int t = threadIdx.x;
    int d0 = deg[2 * t], d1 = deg[2 * t + 1];
    s[t] = d0 + d1;
    __syncthreads();
    for (int off = 1; off < 1024; off <<= 1) {
        int v = s[t];
        int add = (t >= off) ? s[t - off] : 0;
        __syncthreads();
        s[t] = v + add;
        __syncthreads();
    }
    int excl = (t > 0) ? s[t - 1] : 0;
    rowptr[2 * t]     = excl;
    rowptr[2 * t + 1] = excl + d0;
    if (t == 1023) rowptr[NN] = s[1023];
}

__global__ void csr_fill(const float* __restrict__ adj, const int* __restrict__ rowptr,
                         int* __restrict__ colidx) {
    int row = blockIdx.x * (blockDim.x >> 5) + (threadIdx.x >> 5);
    if (row >= NN) return;
    int lane = threadIdx.x & 31;
    const float* r = adj + (size_t)row * NN;
    int pos = rowptr[row];
    for (int c0 = 0; c0 < NN; c0 += 32) {
        float v = r[c0 + lane];
        unsigned m = __ballot_sync(0xffffffffu, v > 0.f);
        if (v > 0.f) {
            int off = __popc(m & ((1u << lane) - 1u));
            colidx[pos + off] = c0 + lane;
        }
        pos += __popc(m);
    }
}

// ---------------- fused split-K reduce + o1/o2 dot (block per node, float4) ----------------
__global__ void reduce_dot(const float* __restrict__ part, const float* __restrict__ ao,
                           __half* __restrict__ hoh, float* __restrict__ o1,
                           float* __restrict__ o2, int fout, int ks) {
    __shared__ float rbuf[8];
    int i = blockIdx.x;
    int tid = threadIdx.x;                  // 128
    int wid = tid >> 5, lane = tid & 31;
    int f4 = fout >> 2;                     // 32..96
    size_t MN4 = (size_t)NN * f4;
    float v1 = 0.f, v2 = 0.f;
    if (tid < f4) {
        size_t idx4 = (size_t)i * f4 + tid;
        float4 s = make_float4(0.f, 0.f, 0.f, 0.f);
        const float4* p4 = (const float4*)part;
        for (int p = 0; p < ks; p++) {
            float4 v = p4[(size_t)p * MN4 + idx4];
            s.x += v.x; s.y += v.y; s.z += v.z; s.w += v.w;
        }
        __half2 h0 = __floats2half2_rn(s.x, s.y);
        __half2 h1 = __floats2half2_rn(s.z, s.w);
        uint2 hv;
        hv.x = *(uint32_t*)&h0; hv.y = *(uint32_t*)&h1;
        *(uint2*)(hoh + (size_t)i * fout + 4 * tid) = hv;
        float4 w1 = *(const float4*)&ao[4 * tid];
        float4 w2 = *(const float4*)&ao[fout + 4 * tid];
        v1 = s.x * w1.x + s.y * w1.y + s.z * w1.z + s.w * w1.w;
        v2 = s.x * w2.x + s.y * w2.y + s.z * w2.z + s.w * w2.w;
    }
#pragma unroll
    for (int o = 16; o; o >>= 1) {
        v1 += __shfl_xor_sync(0xffffffffu, v1, o);
        v2 += __shfl_xor_sync(0xffffffffu, v2, o);
    }
    if (lane == 0) { rbuf[wid] = v1; rbuf[4 + wid] = v2; }
    __syncthreads();
    if (tid == 0) {
        o1[i] = rbuf[0] + rbuf[1] + rbuf[2] + rbuf[3];
        o2[i] = rbuf[4] + rbuf[5] + rbuf[6] + rbuf[7];
    }
}

// ---------------- helpers ----------------
__device__ __forceinline__ float elu1(float x) { return x > 0.f ? x : expm1f(x); }

__device__ __forceinline__ void write_h_quad(__half* o, size_t idx,
                                             float a, float b, float c, float d) {
    __half2 p0 = __floats2half2_rn(a, b);
    __half2 p1 = __floats2half2_rn(c, d);
    uint2 v;
    v.x = *(uint32_t*)&p0; v.y = *(uint32_t*)&p1;
    *(uint2*)(o + idx) = v;
}

// block softmax over neighbor list. 128 threads.
__device__ __forceinline__ int block_softmax(const int* __restrict__ rowptr,
                                             const int* __restrict__ colidx,
                                             float si, const float* __restrict__ s2,
                                             int i, float* ex, int* cj, float& inv) {
    __shared__ float rbuf[8];
    int tid = threadIdx.x;
    int wid = tid >> 5, lane = tid & 31;
    int b = rowptr[i];
    int d = rowptr[i + 1] - b;
    if (d > DEG_CAP) d = DEG_CAP;
    float lm = -1e30f;
    for (int k = tid; k < d; k += 128) {
        int j = colidx[b + k];
        cj[k] = j;
        float v = si + s2[j];
        v = v > 0.f ? v : ALPHA * v;
        ex[k] = v;
        lm = fmaxf(lm, v);
    }
#pragma unroll
    for (int o = 16; o; o >>= 1) lm = fmaxf(lm, __shfl_xor_sync(0xffffffffu, lm, o));
    if (lane == 0) rbuf[wid] = lm;
    __syncthreads();
    float m = fmaxf(fmaxf(rbuf[0], rbuf[1]), fmaxf(rbuf[2], rbuf[3]));
    float ls = 0.f;
    for (int k = tid; k < d; k += 128) {
        float t = expf(ex[k] - m);
        ex[k] = t;
        ls += t;
    }
#pragma unroll
    for (int o = 16; o; o >>= 1) ls += __shfl_xor_sync(0xffffffffu, ls, o);
    if (lane == 0) rbuf[4 + wid] = ls;
    __syncthreads();
    inv = 1.f / (rbuf[4] + rbuf[5] + rbuf[6] + rbuf[7]);
    return d;
}

__device__ __forceinline__ void unpack_h4(uint2 v, float& a, float& b, float& c, float& d) {
    float2 p0 = __half22float2(*(__half2*)&v.x);
    float2 p1 = __half22float2(*(__half2*)&v.y);
    a = p0.x; b = p0.y; c = p1.x; d = p1.y;
}

// ---------------- fused head softmax + SpMM: hcat(fp16) = elu(softmax @ h) ----------------
__global__ void spmm_h_fused(const int* __restrict__ rowptr, const int* __restrict__ colidx,
                             const float* __restrict__ s1, const float* __restrict__ s2,
                             const __half* __restrict__ h,
                             __half* __restrict__ out,
                             int hid, int out_stride) {
    __shared__ float ex[DEG_CAP];
    __shared__ int cj[DEG_CAP];
    int i = blockIdx.x, head = blockIdx.y;
    int tid = threadIdx.x;                    // 128
    float inv;
    int d = block_softmax(rowptr, colidx, s1[(size_t)head * NN + i],
                          s2 + (size_t)head * NN, i, ex, cj, inv);
    int pos = hid >> 2;                       // uint2 chunks per row (32..128)
    if (tid >= pos) return;
    const uint2* hb = (const uint2*)(h + (size_t)head * NN * hid);
    float x0 = 0.f, x1 = 0.f, x2 = 0.f, x3 = 0.f;
#pragma unroll 8
    for (int k = 0; k < d; k++) {
        float a = ex[k];
        float v0, v1, v2, v3;
        unpack_h4(hb[(size_t)cj[k] * pos + tid], v0, v1, v2, v3);
        x0 += a * v0; x1 += a * v1; x2 += a * v2; x3 += a * v3;
    }
    size_t base = (size_t)i * out_stride + (size_t)head * hid + 4 * tid;
    write_h_quad(out, base, elu1(x0 * inv), elu1(x1 * inv), elu1(x2 * inv), elu1(x3 * inv));
}

// ---------------- fused output softmax + SpMM: x'(fp16) = elu(softmax @ ho_fp16) ----------------
__global__ void spmm_out_fused(const int* __restrict__ rowptr, const int* __restrict__ colidx,
                               const float* __restrict__ s1, const float* __restrict__ s2,
                               const __half* __restrict__ hoh,
                               __half* __restrict__ out, float* __restrict__ ofp, int hid) {
    __shared__ float ex[DEG_CAP];
    __shared__ int cj[DEG_CAP];
    int i = blockIdx.x;
    int tid = threadIdx.x;                    // 128
    float inv;
    int d = block_softmax(rowptr, colidx, s1[i], s2, i, ex, cj, inv);
    int pos = hid >> 2;                       // 32..96
    if (tid >= pos) return;
    const uint2* hb = (const uint2*)hoh;
    float x0 = 0.f, x1 = 0.f, x2 = 0.f, x3 = 0.f;
#pragma unroll 8
    for (int k = 0; k < d; k++) {
        float a = ex[k];
        float v0, v1, v2, v3;
        unpack_h4(hb[(size_t)cj[k] * pos + tid], v0, v1, v2, v3);
        x0 += a * v0; x1 += a * v1; x2 += a * v2; x3 += a * v3;
    }
    float e0 = elu1(x0 * inv), e1 = elu1(x1 * inv), e2 = elu1(x2 * inv), e3 = elu1(x3 * inv);
    size_t base = (size_t)i * hid + 4 * tid;
    if (ofp) *(float4*)(ofp + base) = make_float4(e0, e1, e2, e3);
    else     write_h_quad(out, base, e0, e1, e2, e3);
}

// ---------------- host side ----------------
struct LayerDims { int fin, hid, fout; };
static const LayerDims g_dims[6] = {
    {256, 128, 128}, {128, 256, 256}, {256, 512, 384},
    {384, 512, 256}, {256, 256, 128}, {128, 128, 256}
};

extern "C" void kernel_launch(void* const* d_in, const int* in_sizes, int n_in,
                              void* d_out, int out_size) {
    const float* x   = (const float*)d_in[0];
    const float* adj = (const float*)d_in[1];

    float *p_s1, *p_s2, *p_sp1, *p_sp2, *p_o1v, *p_o2v, *p_part;
    int *p_deg, *p_rowptr, *p_colidx;
    __half *p_h, *p_hoh, *p_af, *p_b1;
    cudaGetSymbolAddress((void**)&p_deg, g_deg);
    cudaGetSymbolAddress((void**)&p_rowptr, g_rowptr);
    cudaGetSymbolAddress((void**)&p_colidx, g_colidx);
    cudaGetSymbolAddress((void**)&p_h, g_h);
    cudaGetSymbolAddress((void**)&p_s1, g_s1);
    cudaGetSymbolAddress((void**)&p_s2, g_s2);
    cudaGetSymbolAddress((void**)&p_sp1, g_sp1);
    cudaGetSymbolAddress((void**)&p_sp2, g_sp2);
    cudaGetSymbolAddress((void**)&p_hoh, g_hoh);
    cudaGetSymbolAddress((void**)&p_o1v, g_o1);
    cudaGetSymbolAddress((void**)&p_o2v, g_o2);
    cudaGetSymbolAddress((void**)&p_part, g_part);
    cudaGetSymbolAddress((void**)&p_af, g_af);
    cudaGetSymbolAddress((void**)&p_b1, g_b1);

    static int smem_set = 0;
    if (!smem_set) {
        cudaFuncSetAttribute(gemm_mma<float>, cudaFuncAttributeMaxDynamicSharedMemorySize, GSMEM_BYTES);
        cudaFuncSetAttribute(gemm_mma<__half>, cudaFuncAttributeMaxDynamicSharedMemorySize, GSMEM_BYTES);
        smem_set = 1;
    }

    // weight table: offsets into g_b1 (elements), converted once upfront
    long whoff[6], wooff[6];
    WTab tab;
    long cur = 0, maxN4 = 0;
    for (int l = 0; l < 6; l++) {
        int fin = g_dims[l].fin, hid = g_dims[l].hid, fout = g_dims[l].fout;
        long nWh = (long)NH * fin * hid;
        long nWo = (long)NH * hid * fout;
        whoff[l] = cur;
        tab.e[2 * l] = { (const float*)d_in[2 + 4 * l], cur / 4, nWh / 4 };
        cur += nWh;
        wooff[l] = cur;
        tab.e[2 * l + 1] = { (const float*)d_in[4 + 4 * l], cur / 4, nWo / 4 };
        cur += nWo;
        if (nWh / 4 > maxN4) maxN4 = nWh / 4;
        if (nWo / 4 > maxN4) maxN4 = nWo / 4;
    }

    // Build CSR of adjacency
    csr_count<<<NN / 8, 256>>>(adj, p_deg);
    csr_scan<<<1, 1024>>>(p_deg, p_rowptr);
    csr_fill<<<NN / 8, 256>>>(adj, p_rowptr, p_colidx);

    // all weights -> fp16 in one launch; layer-0 x -> fp16
    conv_h_batch<<<dim3((unsigned)((maxN4 + 255) / 256), 12), 256>>>(tab, p_b1);
    conv_h<<<(NN * 256 / 4 + 255) / 256, 256>>>(x, p_af, NN * 256 / 4);

    for (int l = 0; l < 6; l++) {
        int fin = g_dims[l].fin, hid = g_dims[l].hid, fout = g_dims[l].fout;
        const float* ah = (const float*)d_in[3 + 4 * l];
        const float* ao = (const float*)d_in[5 + 4 * l];

        // ---- head GEMM: h[head] = x @ Wh[head], fp16 out + fused s1/s2 partial dots ----
        gemm_mma<__half><<<dim3(hid / 128, NN / 128, NH), 256, GSMEM_BYTES>>>(
            p_af, fin, 0L,
            p_b1 + whoff[l], hid, (long)fin * hid,
            p_h, hid, (long)NN * hid, fin,
            ah, p_sp1, p_sp2);
        combine_s<<<(NH * NN + 255) / 256, 256>>>(p_sp1, p_sp2, p_s1, p_s2, hid / 128);

        // fused softmax+SpMM (writes hcat fp16 -> Wo A operand)
        spmm_h_fused<<<dim3(NN, NH), 128>>>(p_rowptr, p_colidx, p_s1, p_s2, p_h,
                                            p_af, hid, NH * hid);

        // ---- output GEMM: ho = hcat @ Wo, tuned split-K, fused reduce+dot ----
        int Ktot = NH * hid;
        int ks = (fout == 128) ? 16 : 8;
        int Kc = Ktot / ks;
        gemm_mma<float><<<dim3(fout / 128, NN / 128, ks), 256, GSMEM_BYTES>>>(
            p_af, Ktot, (long)Kc,
            p_b1 + wooff[l], fout, (long)Kc * fout,
            p_part, fout, (long)NN * fout, Kc,
            nullptr, nullptr, nullptr);
        reduce_dot<<<NN, 128>>>(p_part, ao, p_hoh, p_o1v, p_o2v, fout, ks);

        // fused output softmax + SpMM; fp32 d_out at layer 5, else fp16 next-x
        float* ofp = (l == 5) ? (float*)d_out : nullptr;
        spmm_out_fused<<<NN, 128>>>(p_rowptr, p_colidx, p_o1v, p_o2v, p_hoh,
                                    p_af, ofp, fout);
    }
    (void)in_sizes; (void)n_in; (void)out_size;
}